// round 8
// baseline (speedup 1.0000x reference)
#include <cuda_runtime.h>
#include <math.h>
#include <stdint.h>

#define BB 2
#define SS 2048
#define DD 2048
#define HH 16
#define DHH 128
#define ND3 (3*DD)

// ---------------- scratch (static device globals; no allocation) ----------------
__device__ float g_qkv[(size_t)BB*SS*ND3];      // [B,S,3D]
__device__ float g_q  [(size_t)BB*HH*SS*DHH];   // [B,H,S,DH] (pre-scaled by 1/sqrt(DH))
__device__ float g_k  [(size_t)BB*HH*SS*DHH];
__device__ float g_v  [(size_t)BB*HH*SS*DHH];
__device__ float g_ctx[(size_t)BB*SS*DD];       // [B,S,H*DH]
__device__ float g_cos[SS*64];
__device__ float g_sin[SS*64];

__device__ __forceinline__ uint32_t f32_to_tf32(float x) {
    uint32_t r;
    asm("cvt.rna.tf32.f32 %0, %1;" : "=r"(r) : "f"(x));
    return r;
}

#define MMA_TF32(c0,c1,c2,c3,a0,a1,a2,a3,b0,b1)                          \
    asm volatile(                                                        \
        "mma.sync.aligned.m16n8k8.row.col.f32.tf32.tf32.f32 "            \
        "{%0,%1,%2,%3}, {%4,%5,%6,%7}, {%8,%9}, {%0,%1,%2,%3};"          \
        : "+f"(c0), "+f"(c1), "+f"(c2), "+f"(c3)                         \
        : "r"(a0), "r"(a1), "r"(a2), "r"(a3), "r"(b0), "r"(b1))

// ==================== tf32 mma.sync GEMM v3 (double-buffered) ====================
// CTA tile 256x128, 512 threads = 16 warps (4x4), warp tile 64x32, K-chunk 32.
// Two smem stages, ONE __syncthreads per chunk: STS(k+1) overlaps MMA(k).
#define G2_BM 256
#define G2_BN 128
#define G2_BK 32
#define G2_ASTR 36
#define G2_BSTR 132
#define G2_STAGE (G2_BM*G2_ASTR + G2_BK*G2_BSTR)   // 13440 u32
#define G2_SMEM_BYTES (2 * G2_STAGE * 4)

__global__ void __launch_bounds__(512) mma_gemm_kernel(
    const float* __restrict__ A, const float* __restrict__ Bm,
    const float* __restrict__ bias, float* __restrict__ C,
    int M, int N, int K)
{
    extern __shared__ uint32_t gsm[];

    int tid  = threadIdx.x;
    int lane = tid & 31;
    int w    = tid >> 5;
    int wr   = w >> 2;
    int wc   = w & 3;
    int grp  = lane >> 2;
    int tig  = lane & 3;
    int m0 = blockIdx.y * G2_BM;
    int n0 = blockIdx.x * G2_BN;

    float acc[4][4][4];
#pragma unroll
    for (int mt = 0; mt < 4; mt++)
#pragma unroll
        for (int nt = 0; nt < 4; nt++)
#pragma unroll
            for (int i = 0; i < 4; i++) acc[mt][nt][i] = 0.f;

    float4 pa[4], pb[2];
#pragma unroll
    for (int i = 0; i < 4; i++) {
        int s = tid + i * 512;
        int ar = s >> 3, ac = (s & 7) * 4;
        pa[i] = *(const float4*)(A + (size_t)(m0 + ar) * K + ac);
    }
#pragma unroll
    for (int i = 0; i < 2; i++) {
        int s = tid + i * 512;
        int br = s >> 5, bc = (s & 31) * 4;
        pb[i] = *(const float4*)(Bm + (size_t)br * N + n0 + bc);
    }

    const int nCh = K / G2_BK;
    for (int kc = 0; kc < nCh; kc++) {
        uint32_t* As = gsm + (kc & 1) * G2_STAGE;
        uint32_t* Bs = As + G2_BM * G2_ASTR;
#pragma unroll
        for (int i = 0; i < 4; i++) {
            int s = tid + i * 512;
            int ar = s >> 3, ac = (s & 7) * 4;
            uint4 t;
            t.x = f32_to_tf32(pa[i].x); t.y = f32_to_tf32(pa[i].y);
            t.z = f32_to_tf32(pa[i].z); t.w = f32_to_tf32(pa[i].w);
            *(uint4*)&As[ar * G2_ASTR + ac] = t;
        }
#pragma unroll
        for (int i = 0; i < 2; i++) {
            int s = tid + i * 512;
            int br = s >> 5, bc = (s & 31) * 4;
            uint4 t;
            t.x = f32_to_tf32(pb[i].x); t.y = f32_to_tf32(pb[i].y);
            t.z = f32_to_tf32(pb[i].z); t.w = f32_to_tf32(pb[i].w);
            *(uint4*)&Bs[br * G2_BSTR + bc] = t;
        }
        __syncthreads();

        if (kc + 1 < nCh) {
            int k0 = (kc + 1) * G2_BK;
#pragma unroll
            for (int i = 0; i < 4; i++) {
                int s = tid + i * 512;
                int ar = s >> 3, ac = (s & 7) * 4;
                pa[i] = *(const float4*)(A + (size_t)(m0 + ar) * K + k0 + ac);
            }
#pragma unroll
            for (int i = 0; i < 2; i++) {
                int s = tid + i * 512;
                int br = s >> 5, bc = (s & 31) * 4;
                pb[i] = *(const float4*)(Bm + (size_t)(k0 + br) * N + n0 + bc);
            }
        }

#pragma unroll
        for (int kk = 0; kk < 4; kk++) {
            uint32_t af[4][4], bf[4][2];
#pragma unroll
            for (int mt = 0; mt < 4; mt++) {
                int r = wr * 64 + mt * 16 + grp;
                int kb = kk * 8 + tig;
                af[mt][0] = As[r * G2_ASTR + kb];
                af[mt][1] = As[(r + 8) * G2_ASTR + kb];
                af[mt][2] = As[r * G2_ASTR + kb + 4];
                af[mt][3] = As[(r + 8) * G2_ASTR + kb + 4];
            }
#pragma unroll
            for (int nt = 0; nt < 4; nt++) {
                int cn = wc * 32 + nt * 8 + grp;
                bf[nt][0] = Bs[(kk * 8 + tig) * G2_BSTR + cn];
                bf[nt][1] = Bs[(kk * 8 + tig + 4) * G2_BSTR + cn];
            }
#pragma unroll
            for (int mt = 0; mt < 4; mt++)
#pragma unroll
                for (int nt = 0; nt < 4; nt++)
                    MMA_TF32(acc[mt][nt][0], acc[mt][nt][1], acc[mt][nt][2], acc[mt][nt][3],
                             af[mt][0], af[mt][1], af[mt][2], af[mt][3],
                             bf[nt][0], bf[nt][1]);
        }
        // no trailing sync: next chunk writes the other stage
    }

#pragma unroll
    for (int mt = 0; mt < 4; mt++) {
        int r0 = m0 + wr * 64 + mt * 16 + grp;
#pragma unroll
        for (int nt = 0; nt < 4; nt++) {
            int cn = n0 + wc * 32 + nt * 8 + tig * 2;
            float b0 = bias[cn], b1 = bias[cn + 1];
            float2 v0 = make_float2(acc[mt][nt][0] + b0, acc[mt][nt][1] + b1);
            float2 v1 = make_float2(acc[mt][nt][2] + b0, acc[mt][nt][3] + b1);
            *(float2*)(C + (size_t)r0 * N + cn) = v0;
            *(float2*)(C + (size_t)(r0 + 8) * N + cn) = v1;
        }
    }
}

// ---------------- RoPE tables ----------------
__global__ void rope_table_kernel() {
    int idx = blockIdx.x * blockDim.x + threadIdx.x;
    if (idx >= SS * 64) return;
    int t = idx >> 6;
    int j = idx & 63;
    double theta = (double)t * pow(10000.0, -(double)j / 64.0);
    g_cos[idx] = (float)cos(theta);
    g_sin[idx] = (float)sin(theta);
}

// ---------------- RoPE + split + transpose to [B,H,S,DH] ----------------
__global__ void rope_split_kernel() {
    int idx = blockIdx.x * blockDim.x + threadIdx.x;
    if (idx >= BB * HH * SS * 64) return;
    int j = idx & 63;
    int s = (idx >> 6) & (SS - 1);
    int h = (idx >> 17) & (HH - 1);
    int b = idx >> 21;

    const float* qrow = g_qkv + (size_t)(b * SS + s) * ND3 + h * DHH;
    const float* krow = qrow + DD;
    const float* vrow = qrow + 2 * DD;
    float c  = g_cos[s * 64 + j];
    float sn = g_sin[s * 64 + j];
    size_t o = ((size_t)(b * HH + h) * SS + s) * DHH;

    const float qscale = 0.088388347648318447f;  // 1/sqrt(128)

    float u0 = qrow[j], u1 = qrow[j + 64], ue = qrow[2 * j], uo = qrow[2 * j + 1];
    g_q[o + j]      = (u0 * c + uo * sn) * qscale;
    g_q[o + j + 64] = (u1 * c - ue * sn) * qscale;

    u0 = krow[j]; u1 = krow[j + 64]; ue = krow[2 * j]; uo = krow[2 * j + 1];
    g_k[o + j]      = u0 * c + uo * sn;
    g_k[o + j + 64] = u1 * c - ue * sn;

    g_v[o + j]      = vrow[j];
    g_v[o + j + 64] = vrow[j + 64];
}

// ==================== flash attention v3: BM=64, BN=128, 512 threads ====================
// 16 warps = (g: 4 row-groups of 16 q-rows) x (qq: 4 quarters of keys / out-cols).
// QK: warp = 16 rows x 32 keys. PV: warp = 16 rows x 32 out-cols over all 128 keys.
// Strides (u32): Q 132, K 132, V 136, P 132 -> all fragment accesses conflict-free.
#define A3_QSTR 132
#define A3_KSTR 132
#define A3_VSTR 136
#define A3_PSTR 132
#define A3_RED  (64*A3_QSTR + 128*A3_KSTR + 128*A3_VSTR + 64*A3_PSTR)
#define A3_SMEM_U32 (A3_RED + 512)
#define A3_SMEM_BYTES (A3_SMEM_U32 * 4)

__global__ void __launch_bounds__(512) attn_mma_kernel() {
    extern __shared__ uint32_t sm4[];
    uint32_t* Qs = sm4;                          // [64][132]  tf32
    uint32_t* Ks = Qs + 64 * A3_QSTR;            // [128][132] tf32
    uint32_t* Vs = Ks + 128 * A3_KSTR;           // [128][136] tf32
    uint32_t* Ps = Vs + 128 * A3_VSTR;           // [64][132]  tf32
    float* redmax = (float*)(sm4 + A3_RED);      // [4][64]
    float* redsum = redmax + 256;                // [4][64]

    int tid  = threadIdx.x;
    int lane = tid & 31;
    int w    = tid >> 5;        // 0..15
    int g    = w & 3;           // row group: q rows [g*16, g*16+16)
    int qq   = w >> 2;          // 0..3: key quarter (QK) / out-col quarter (PV)
    int grp  = lane >> 2;       // 0..7
    int tig  = lane & 3;        // 0..3

    int bh = blockIdx.y;
    int b = bh >> 4, h = bh & 15;
    int q0 = blockIdx.x * 64;

    const float* Qg = g_q + (size_t)bh * SS * DHH;
    const float* Kg = g_k + (size_t)bh * SS * DHH;
    const float* Vg = g_v + (size_t)bh * SS * DHH;

    // load Q tile (tf32): 64 rows x 128 d
#pragma unroll
    for (int i = 0; i < 4; i++) {
        int flat = tid + i * 512;
        int r = flat >> 5, c = (flat & 31) * 4;
        float4 q4 = *(const float4*)(Qg + (size_t)(q0 + r) * DHH + c);
        uint4 t;
        t.x = f32_to_tf32(q4.x); t.y = f32_to_tf32(q4.y);
        t.z = f32_to_tf32(q4.z); t.w = f32_to_tf32(q4.w);
        *(uint4*)&Qs[r * A3_QSTR + c] = t;
    }

    float o[4][4];
#pragma unroll
    for (int nt = 0; nt < 4; nt++)
#pragma unroll
        for (int i = 0; i < 4; i++) o[nt][i] = 0.f;
    float m0 = -1e30f, m1 = -1e30f, l0 = 0.f, l1 = 0.f;

    int qr0 = g * 16 + grp;     // thread's rows: qr0, qr0+8

    for (int kt = 0; kt < SS / 128; kt++) {
        __syncthreads();   // prev iter done with Ks/Vs/Ps
        // load K,V tile: 128 keys x 128 d
#pragma unroll
        for (int i = 0; i < 8; i++) {
            int flat = tid + i * 512;
            int r = flat >> 5, c = (flat & 31) * 4;
            float4 k4 = *(const float4*)(Kg + (size_t)(kt * 128 + r) * DHH + c);
            uint4 t;
            t.x = f32_to_tf32(k4.x); t.y = f32_to_tf32(k4.y);
            t.z = f32_to_tf32(k4.z); t.w = f32_to_tf32(k4.w);
            *(uint4*)&Ks[r * A3_KSTR + c] = t;
            float4 v4 = *(const float4*)(Vg + (size_t)(kt * 128 + r) * DHH + c);
            t.x = f32_to_tf32(v4.x); t.y = f32_to_tf32(v4.y);
            t.z = f32_to_tf32(v4.z); t.w = f32_to_tf32(v4.w);
            *(uint4*)&Vs[r * A3_VSTR + c] = t;
        }
        __syncthreads();

        // S = Q K^T : warp computes 16 rows x 32 keys (its quarter)
        float s[4][4];
#pragma unroll
        for (int nt = 0; nt < 4; nt++)
#pragma unroll
            for (int i = 0; i < 4; i++) s[nt][i] = 0.f;

#pragma unroll
        for (int ks = 0; ks < 16; ks++) {
            uint32_t a0 = Qs[qr0 * A3_QSTR + ks * 8 + tig];
            uint32_t a1 = Qs[(qr0 + 8) * A3_QSTR + ks * 8 + tig];
            uint32_t a2 = Qs[qr0 * A3_QSTR + ks * 8 + tig + 4];
            uint32_t a3 = Qs[(qr0 + 8) * A3_QSTR + ks * 8 + tig + 4];
#pragma unroll
            for (int nt = 0; nt < 4; nt++) {
                int kr = qq * 32 + nt * 8 + grp;
                uint32_t b0 = Ks[kr * A3_KSTR + ks * 8 + tig];
                uint32_t b1 = Ks[kr * A3_KSTR + ks * 8 + tig + 4];
                MMA_TF32(s[nt][0], s[nt][1], s[nt][2], s[nt][3], a0, a1, a2, a3, b0, b1);
            }
        }

        // partial max over this warp's 32 keys
        float mx0 = -1e30f, mx1 = -1e30f;
#pragma unroll
        for (int nt = 0; nt < 4; nt++) {
            mx0 = fmaxf(mx0, fmaxf(s[nt][0], s[nt][1]));
            mx1 = fmaxf(mx1, fmaxf(s[nt][2], s[nt][3]));
        }
#pragma unroll
        for (int off = 1; off <= 2; off <<= 1) {
            mx0 = fmaxf(mx0, __shfl_xor_sync(0xffffffffu, mx0, off));
            mx1 = fmaxf(mx1, __shfl_xor_sync(0xffffffffu, mx1, off));
        }
        if (tig == 0) {
            redmax[qq * 64 + qr0]     = mx0;
            redmax[qq * 64 + qr0 + 8] = mx1;
        }
        __syncthreads();
        float nm0 = fmaxf(fmaxf(redmax[qr0], redmax[64 + qr0]),
                          fmaxf(redmax[128 + qr0], redmax[192 + qr0]));
        float nm1 = fmaxf(fmaxf(redmax[qr0 + 8], redmax[64 + qr0 + 8]),
                          fmaxf(redmax[128 + qr0 + 8], redmax[192 + qr0 + 8]));
        nm0 = fmaxf(m0, nm0);
        nm1 = fmaxf(m1, nm1);
        float sc0 = __expf(m0 - nm0), sc1 = __expf(m1 - nm1);

        float ps0 = 0.f, ps1 = 0.f;
#pragma unroll
        for (int nt = 0; nt < 4; nt++) {
            float p0 = __expf(s[nt][0] - nm0);
            float p1 = __expf(s[nt][1] - nm0);
            float p2 = __expf(s[nt][2] - nm1);
            float p3 = __expf(s[nt][3] - nm1);
            ps0 += p0 + p1;
            ps1 += p2 + p3;
            int pc = qq * 32 + nt * 8 + 2 * tig;
            Ps[qr0 * A3_PSTR + pc]           = f32_to_tf32(p0);
            Ps[qr0 * A3_PSTR + pc + 1]       = f32_to_tf32(p1);
            Ps[(qr0 + 8) * A3_PSTR + pc]     = f32_to_tf32(p2);
            Ps[(qr0 + 8) * A3_PSTR + pc + 1] = f32_to_tf32(p3);
        }
#pragma unroll
        for (int off = 1; off <= 2; off <<= 1) {
            ps0 += __shfl_xor_sync(0xffffffffu, ps0, off);
            ps1 += __shfl_xor_sync(0xffffffffu, ps1, off);
        }
        if (tig == 0) {
            redsum[qq * 64 + qr0]     = ps0;
            redsum[qq * 64 + qr0 + 8] = ps1;
        }
        __syncthreads();   // P complete (all quarters), sums ready
        float pt0 = (redsum[qr0] + redsum[64 + qr0])
                  + (redsum[128 + qr0] + redsum[192 + qr0]);
        float pt1 = (redsum[qr0 + 8] + redsum[64 + qr0 + 8])
                  + (redsum[128 + qr0 + 8] + redsum[192 + qr0 + 8]);
        l0 = l0 * sc0 + pt0;  m0 = nm0;
        l1 = l1 * sc1 + pt1;  m1 = nm1;
#pragma unroll
        for (int nt = 0; nt < 4; nt++) {
            o[nt][0] *= sc0; o[nt][1] *= sc0;
            o[nt][2] *= sc1; o[nt][3] *= sc1;
        }

        // O += P V : warp = 16 rows x 32 out cols (its quarter), K = 128 keys
#pragma unroll
        for (int ks = 0; ks < 16; ks++) {
            uint32_t a0 = Ps[qr0 * A3_PSTR + ks * 8 + tig];
            uint32_t a1 = Ps[(qr0 + 8) * A3_PSTR + ks * 8 + tig];
            uint32_t a2 = Ps[qr0 * A3_PSTR + ks * 8 + tig + 4];
            uint32_t a3 = Ps[(qr0 + 8) * A3_PSTR + ks * 8 + tig + 4];
#pragma unroll
            for (int nt = 0; nt < 4; nt++) {
                int vc = qq * 32 + nt * 8 + grp;
                uint32_t b0 = Vs[(ks * 8 + tig) * A3_VSTR + vc];
                uint32_t b1 = Vs[(ks * 8 + tig + 4) * A3_VSTR + vc];
                MMA_TF32(o[nt][0], o[nt][1], o[nt][2], o[nt][3], a0, a1, a2, a3, b0, b1);
            }
        }
    }

    // epilogue
    float inv0 = 1.f / l0, inv1 = 1.f / l1;
    int r0 = q0 + qr0;
    float* dst0 = g_ctx + (size_t)(b * SS + r0) * DD + h * DHH;
    float* dst1 = g_ctx + (size_t)(b * SS + r0 + 8) * DD + h * DHH;
#pragma unroll
    for (int nt = 0; nt < 4; nt++) {
        int cn = qq * 32 + nt * 8 + 2 * tig;
        *(float2*)(dst0 + cn) = make_float2(o[nt][0] * inv0, o[nt][1] * inv0);
        *(float2*)(dst1 + cn) = make_float2(o[nt][2] * inv1, o[nt][3] * inv1);
    }
}

// ---------------- launch ----------------
extern "C" void kernel_launch(void* const* d_in, const int* in_sizes, int n_in,
                              void* d_out, int out_size) {
    const float* x    = (const float*)d_in[0];
    const float* Wqkv = (const float*)d_in[1];
    const float* bqkv = (const float*)d_in[2];
    const float* Wo   = (const float*)d_in[3];
    const float* bo   = (const float*)d_in[4];
    float* out = (float*)d_out;

    void *qkvPtr, *ctxPtr;
    cudaGetSymbolAddress(&qkvPtr, g_qkv);
    cudaGetSymbolAddress(&ctxPtr, g_ctx);

    cudaFuncSetAttribute(attn_mma_kernel,
                         cudaFuncAttributeMaxDynamicSharedMemorySize,
                         A3_SMEM_BYTES);
    cudaFuncSetAttribute(mma_gemm_kernel,
                         cudaFuncAttributeMaxDynamicSharedMemorySize,
                         G2_SMEM_BYTES);

    // 1) RoPE tables
    rope_table_kernel<<<(SS * 64 + 255) / 256, 256>>>();

    // 2) QKV GEMM (tf32 mma.sync, double-buffered)
    mma_gemm_kernel<<<dim3(ND3 / G2_BN, (BB * SS) / G2_BM), 512, G2_SMEM_BYTES>>>(
        x, Wqkv, bqkv, (float*)qkvPtr, BB * SS, ND3, DD);

    // 3) RoPE + split/transpose (+ fold 1/sqrt(DH) into Q)
    rope_split_kernel<<<(BB * HH * SS * 64) / 256, 256>>>();

    // 4) flash attention v3 (tf32 mma, BM=64/BN=128) -> g_ctx
    attn_mma_kernel<<<dim3(SS / 64, BB * HH), 512, A3_SMEM_BYTES>>>();

    // 5) output projection (tf32 mma.sync, double-buffered)
    mma_gemm_kernel<<<dim3(DD / G2_BN, (BB * SS) / G2_BM), 512, G2_SMEM_BYTES>>>(
        (const float*)ctxPtr, Wo, bo, out, BB * SS, DD, DD);
}

// round 9
// speedup vs baseline: 1.1652x; 1.1652x over previous
#include <cuda_runtime.h>
#include <math.h>
#include <stdint.h>

#define BB 2
#define SS 2048
#define DD 2048
#define HH 16
#define DHH 128
#define ND3 (3*DD)

// ---------------- scratch (static device globals; no allocation) ----------------
__device__ float g_qkv[(size_t)BB*SS*ND3];      // [B,S,3D]
__device__ float g_q  [(size_t)BB*HH*SS*DHH];   // [B,H,S,DH] (pre-scaled by 1/sqrt(DH))
__device__ float g_k  [(size_t)BB*HH*SS*DHH];
__device__ float g_v  [(size_t)BB*HH*SS*DHH];
__device__ float g_ctx[(size_t)BB*SS*DD];       // [B,S,H*DH]
__device__ float g_cos[SS*64];
__device__ float g_sin[SS*64];

__device__ __forceinline__ uint32_t f32_to_tf32(float x) {
    uint32_t r;
    asm("cvt.rna.tf32.f32 %0, %1;" : "=r"(r) : "f"(x));
    return r;
}

#define MMA_TF32(c0,c1,c2,c3,a0,a1,a2,a3,b0,b1)                          \
    asm volatile(                                                        \
        "mma.sync.aligned.m16n8k8.row.col.f32.tf32.tf32.f32 "            \
        "{%0,%1,%2,%3}, {%4,%5,%6,%7}, {%8,%9}, {%0,%1,%2,%3};"          \
        : "+f"(c0), "+f"(c1), "+f"(c2), "+f"(c3)                         \
        : "r"(a0), "r"(a1), "r"(a2), "r"(a3), "r"(b0), "r"(b1))

// ==================== tf32 mma.sync GEMM (R6 version, known-good) ====================
#define G2_BM 256
#define G2_BN 128
#define G2_BK 32
#define G2_ASTR 36
#define G2_BSTR 132
#define G2_SMEM_BYTES ((G2_BM*G2_ASTR + G2_BK*G2_BSTR) * 4)

__global__ void __launch_bounds__(512) mma_gemm_kernel(
    const float* __restrict__ A, const float* __restrict__ Bm,
    const float* __restrict__ bias, float* __restrict__ C,
    int M, int N, int K)
{
    extern __shared__ uint32_t gsm[];
    uint32_t* As = gsm;                    // [256][36]
    uint32_t* Bs = gsm + G2_BM * G2_ASTR;  // [32][132]

    int tid  = threadIdx.x;
    int lane = tid & 31;
    int w    = tid >> 5;
    int wr   = w >> 2;
    int wc   = w & 3;
    int grp  = lane >> 2;
    int tig  = lane & 3;
    int m0 = blockIdx.y * G2_BM;
    int n0 = blockIdx.x * G2_BN;

    float acc[4][4][4];
#pragma unroll
    for (int mt = 0; mt < 4; mt++)
#pragma unroll
        for (int nt = 0; nt < 4; nt++)
#pragma unroll
            for (int i = 0; i < 4; i++) acc[mt][nt][i] = 0.f;

    float4 pa[4], pb[2];
#pragma unroll
    for (int i = 0; i < 4; i++) {
        int s = tid + i * 512;
        int ar = s >> 3, ac = (s & 7) * 4;
        pa[i] = *(const float4*)(A + (size_t)(m0 + ar) * K + ac);
    }
#pragma unroll
    for (int i = 0; i < 2; i++) {
        int s = tid + i * 512;
        int br = s >> 5, bc = (s & 31) * 4;
        pb[i] = *(const float4*)(Bm + (size_t)br * N + n0 + bc);
    }

    const int nCh = K / G2_BK;
    for (int kc = 0; kc < nCh; kc++) {
#pragma unroll
        for (int i = 0; i < 4; i++) {
            int s = tid + i * 512;
            int ar = s >> 3, ac = (s & 7) * 4;
            uint4 t;
            t.x = f32_to_tf32(pa[i].x); t.y = f32_to_tf32(pa[i].y);
            t.z = f32_to_tf32(pa[i].z); t.w = f32_to_tf32(pa[i].w);
            *(uint4*)&As[ar * G2_ASTR + ac] = t;
        }
#pragma unroll
        for (int i = 0; i < 2; i++) {
            int s = tid + i * 512;
            int br = s >> 5, bc = (s & 31) * 4;
            uint4 t;
            t.x = f32_to_tf32(pb[i].x); t.y = f32_to_tf32(pb[i].y);
            t.z = f32_to_tf32(pb[i].z); t.w = f32_to_tf32(pb[i].w);
            *(uint4*)&Bs[br * G2_BSTR + bc] = t;
        }
        __syncthreads();

        if (kc + 1 < nCh) {
            int k0 = (kc + 1) * G2_BK;
#pragma unroll
            for (int i = 0; i < 4; i++) {
                int s = tid + i * 512;
                int ar = s >> 3, ac = (s & 7) * 4;
                pa[i] = *(const float4*)(A + (size_t)(m0 + ar) * K + k0 + ac);
            }
#pragma unroll
            for (int i = 0; i < 2; i++) {
                int s = tid + i * 512;
                int br = s >> 5, bc = (s & 31) * 4;
                pb[i] = *(const float4*)(Bm + (size_t)(k0 + br) * N + n0 + bc);
            }
        }

#pragma unroll
        for (int kk = 0; kk < 4; kk++) {
            uint32_t af[4][4], bf[4][2];
#pragma unroll
            for (int mt = 0; mt < 4; mt++) {
                int r = wr * 64 + mt * 16 + grp;
                int kb = kk * 8 + tig;
                af[mt][0] = As[r * G2_ASTR + kb];
                af[mt][1] = As[(r + 8) * G2_ASTR + kb];
                af[mt][2] = As[r * G2_ASTR + kb + 4];
                af[mt][3] = As[(r + 8) * G2_ASTR + kb + 4];
            }
#pragma unroll
            for (int nt = 0; nt < 4; nt++) {
                int cn = wc * 32 + nt * 8 + grp;
                bf[nt][0] = Bs[(kk * 8 + tig) * G2_BSTR + cn];
                bf[nt][1] = Bs[(kk * 8 + tig + 4) * G2_BSTR + cn];
            }
#pragma unroll
            for (int mt = 0; mt < 4; mt++)
#pragma unroll
                for (int nt = 0; nt < 4; nt++)
                    MMA_TF32(acc[mt][nt][0], acc[mt][nt][1], acc[mt][nt][2], acc[mt][nt][3],
                             af[mt][0], af[mt][1], af[mt][2], af[mt][3],
                             bf[nt][0], bf[nt][1]);
        }
        __syncthreads();
    }

#pragma unroll
    for (int mt = 0; mt < 4; mt++) {
        int r0 = m0 + wr * 64 + mt * 16 + grp;
#pragma unroll
        for (int nt = 0; nt < 4; nt++) {
            int cn = n0 + wc * 32 + nt * 8 + tig * 2;
            float b0 = bias[cn], b1 = bias[cn + 1];
            float2 v0 = make_float2(acc[mt][nt][0] + b0, acc[mt][nt][1] + b1);
            float2 v1 = make_float2(acc[mt][nt][2] + b0, acc[mt][nt][3] + b1);
            *(float2*)(C + (size_t)r0 * N + cn) = v0;
            *(float2*)(C + (size_t)(r0 + 8) * N + cn) = v1;
        }
    }
}

// ---------------- RoPE tables ----------------
__global__ void rope_table_kernel() {
    int idx = blockIdx.x * blockDim.x + threadIdx.x;
    if (idx >= SS * 64) return;
    int t = idx >> 6;
    int j = idx & 63;
    double theta = (double)t * pow(10000.0, -(double)j / 64.0);
    g_cos[idx] = (float)cos(theta);
    g_sin[idx] = (float)sin(theta);
}

// ---------------- RoPE + split + transpose to [B,H,S,DH] ----------------
__global__ void rope_split_kernel() {
    int idx = blockIdx.x * blockDim.x + threadIdx.x;
    if (idx >= BB * HH * SS * 64) return;
    int j = idx & 63;
    int s = (idx >> 6) & (SS - 1);
    int h = (idx >> 17) & (HH - 1);
    int b = idx >> 21;

    const float* qrow = g_qkv + (size_t)(b * SS + s) * ND3 + h * DHH;
    const float* krow = qrow + DD;
    const float* vrow = qrow + 2 * DD;
    float c  = g_cos[s * 64 + j];
    float sn = g_sin[s * 64 + j];
    size_t o = ((size_t)(b * HH + h) * SS + s) * DHH;

    const float qscale = 0.088388347648318447f;  // 1/sqrt(128)

    float u0 = qrow[j], u1 = qrow[j + 64], ue = qrow[2 * j], uo = qrow[2 * j + 1];
    g_q[o + j]      = (u0 * c + uo * sn) * qscale;
    g_q[o + j + 64] = (u1 * c - ue * sn) * qscale;

    u0 = krow[j]; u1 = krow[j + 64]; ue = krow[2 * j]; uo = krow[2 * j + 1];
    g_k[o + j]      = u0 * c + uo * sn;
    g_k[o + j + 64] = u1 * c - ue * sn;

    g_v[o + j]      = vrow[j];
    g_v[o + j + 64] = vrow[j + 64];
}

// ==================== flash attention v4: big warp tiles ====================
// BM=128 q-rows, BN=64 keys/step, 256 threads = 8 warps.
// Warp (g, hf): g = row group (32 rows), hf = key half (QK: 32 keys) / col half (PV: 64 cols).
// QK warp tile 32x32, PV warp tile 32x64 -> minimal LDS per MMA.
// Strides (u32): Q 132, K 132, V 136, P 72 -> all accesses conflict-free.
#define A4_QSTR 132
#define A4_KSTR 132
#define A4_VSTR 136
#define A4_PSTR 72
#define A4_RED  (128*A4_QSTR + 64*A4_KSTR + 64*A4_VSTR + 128*A4_PSTR)
#define A4_SMEM_U32 (A4_RED + 512)
#define A4_SMEM_BYTES (A4_SMEM_U32 * 4)

__global__ void __launch_bounds__(256) attn_mma_kernel() {
    extern __shared__ uint32_t sm4[];
    uint32_t* Qs = sm4;                          // [128][132] tf32
    uint32_t* Ks = Qs + 128 * A4_QSTR;           // [64][132]  tf32
    uint32_t* Vs = Ks + 64 * A4_KSTR;            // [64][136]  tf32
    uint32_t* Ps = Vs + 64 * A4_VSTR;            // [128][72]  tf32
    float* redmax = (float*)(sm4 + A4_RED);      // [2][128]
    float* redsum = redmax + 256;                // [2][128]

    int tid  = threadIdx.x;
    int lane = tid & 31;
    int w    = tid >> 5;        // 0..7
    int g    = w & 3;           // row group: q rows [g*32, g*32+32)
    int hf   = w >> 2;          // 0/1: key half (QK) / out-col half (PV)
    int grp  = lane >> 2;       // 0..7
    int tig  = lane & 3;        // 0..3

    int bh = blockIdx.y;
    int b = bh >> 4, h = bh & 15;
    int q0 = blockIdx.x * 128;

    const float* Qg = g_q + (size_t)bh * SS * DHH;
    const float* Kg = g_k + (size_t)bh * SS * DHH;
    const float* Vg = g_v + (size_t)bh * SS * DHH;

    // load Q tile (tf32): 128 rows x 128 d
#pragma unroll
    for (int i = 0; i < 16; i++) {
        int flat = tid + i * 256;
        int r = flat >> 5, c = (flat & 31) * 4;
        float4 q4 = *(const float4*)(Qg + (size_t)(q0 + r) * DHH + c);
        uint4 t;
        t.x = f32_to_tf32(q4.x); t.y = f32_to_tf32(q4.y);
        t.z = f32_to_tf32(q4.z); t.w = f32_to_tf32(q4.w);
        *(uint4*)&Qs[r * A4_QSTR + c] = t;
    }

    // thread owns 4 row-slots: r0, r0+8, r0+16, r0+24  (slots 0..3)
    int r0 = g * 32 + grp;
    float o[2][8][4];           // [mt][nt][c] : rows r0+16mt(+8), cols hf*64+nt*8+2tig(+1)
#pragma unroll
    for (int mt = 0; mt < 2; mt++)
#pragma unroll
        for (int nt = 0; nt < 8; nt++)
#pragma unroll
            for (int i = 0; i < 4; i++) o[mt][nt][i] = 0.f;
    float m[4] = {-1e30f, -1e30f, -1e30f, -1e30f};
    float l[4] = {0.f, 0.f, 0.f, 0.f};

    for (int kt = 0; kt < SS / 64; kt++) {
        __syncthreads();   // prev iter done with Ks/Vs/Ps
        // load K,V tile: 64 keys x 128 d
#pragma unroll
        for (int i = 0; i < 8; i++) {
            int flat = tid + i * 256;
            int r = flat >> 5, c = (flat & 31) * 4;
            float4 k4 = *(const float4*)(Kg + (size_t)(kt * 64 + r) * DHH + c);
            uint4 t;
            t.x = f32_to_tf32(k4.x); t.y = f32_to_tf32(k4.y);
            t.z = f32_to_tf32(k4.z); t.w = f32_to_tf32(k4.w);
            *(uint4*)&Ks[r * A4_KSTR + c] = t;
            float4 v4 = *(const float4*)(Vg + (size_t)(kt * 64 + r) * DHH + c);
            t.x = f32_to_tf32(v4.x); t.y = f32_to_tf32(v4.y);
            t.z = f32_to_tf32(v4.z); t.w = f32_to_tf32(v4.w);
            *(uint4*)&Vs[r * A4_VSTR + c] = t;
        }
        __syncthreads();

        // S = Q K^T : warp tile 32 rows x 32 keys (its half)
        float s[2][4][4];
#pragma unroll
        for (int mt = 0; mt < 2; mt++)
#pragma unroll
            for (int nt = 0; nt < 4; nt++)
#pragma unroll
                for (int i = 0; i < 4; i++) s[mt][nt][i] = 0.f;

#pragma unroll
        for (int ks = 0; ks < 16; ks++) {
            uint32_t af[2][4];
#pragma unroll
            for (int mt = 0; mt < 2; mt++) {
                int rr = r0 + mt * 16;
                af[mt][0] = Qs[rr * A4_QSTR + ks * 8 + tig];
                af[mt][1] = Qs[(rr + 8) * A4_QSTR + ks * 8 + tig];
                af[mt][2] = Qs[rr * A4_QSTR + ks * 8 + tig + 4];
                af[mt][3] = Qs[(rr + 8) * A4_QSTR + ks * 8 + tig + 4];
            }
#pragma unroll
            for (int nt = 0; nt < 4; nt++) {
                int kr = hf * 32 + nt * 8 + grp;
                uint32_t b0 = Ks[kr * A4_KSTR + ks * 8 + tig];
                uint32_t b1 = Ks[kr * A4_KSTR + ks * 8 + tig + 4];
#pragma unroll
                for (int mt = 0; mt < 2; mt++)
                    MMA_TF32(s[mt][nt][0], s[mt][nt][1], s[mt][nt][2], s[mt][nt][3],
                             af[mt][0], af[mt][1], af[mt][2], af[mt][3], b0, b1);
            }
        }

        // partial max over this warp's 32 keys (per row-slot)
        float mx[4] = {-1e30f, -1e30f, -1e30f, -1e30f};
#pragma unroll
        for (int mt = 0; mt < 2; mt++)
#pragma unroll
            for (int nt = 0; nt < 4; nt++) {
                mx[2*mt]   = fmaxf(mx[2*mt],   fmaxf(s[mt][nt][0], s[mt][nt][1]));
                mx[2*mt+1] = fmaxf(mx[2*mt+1], fmaxf(s[mt][nt][2], s[mt][nt][3]));
            }
#pragma unroll
        for (int off = 1; off <= 2; off <<= 1)
#pragma unroll
            for (int sl = 0; sl < 4; sl++)
                mx[sl] = fmaxf(mx[sl], __shfl_xor_sync(0xffffffffu, mx[sl], off));
        if (tig == 0) {
#pragma unroll
            for (int sl = 0; sl < 4; sl++)
                redmax[hf * 128 + r0 + sl * 8] = mx[sl];
        }
        __syncthreads();
        float nm[4], sc[4];
#pragma unroll
        for (int sl = 0; sl < 4; sl++) {
            int rr = r0 + sl * 8;
            nm[sl] = fmaxf(m[sl], fmaxf(redmax[rr], redmax[128 + rr]));
            sc[sl] = __expf(m[sl] - nm[sl]);
        }

        // exp + P store (float2), partial sums
        float ps[4] = {0.f, 0.f, 0.f, 0.f};
#pragma unroll
        for (int mt = 0; mt < 2; mt++)
#pragma unroll
            for (int nt = 0; nt < 4; nt++) {
                float p0 = __expf(s[mt][nt][0] - nm[2*mt]);
                float p1 = __expf(s[mt][nt][1] - nm[2*mt]);
                float p2 = __expf(s[mt][nt][2] - nm[2*mt+1]);
                float p3 = __expf(s[mt][nt][3] - nm[2*mt+1]);
                ps[2*mt]   += p0 + p1;
                ps[2*mt+1] += p2 + p3;
                int pc = hf * 32 + nt * 8 + 2 * tig;
                int rr = r0 + mt * 16;
                uint2 t0 = make_uint2(f32_to_tf32(p0), f32_to_tf32(p1));
                uint2 t1 = make_uint2(f32_to_tf32(p2), f32_to_tf32(p3));
                *(uint2*)&Ps[rr * A4_PSTR + pc] = t0;
                *(uint2*)&Ps[(rr + 8) * A4_PSTR + pc] = t1;
            }
#pragma unroll
        for (int off = 1; off <= 2; off <<= 1)
#pragma unroll
            for (int sl = 0; sl < 4; sl++)
                ps[sl] += __shfl_xor_sync(0xffffffffu, ps[sl], off);
        if (tig == 0) {
#pragma unroll
            for (int sl = 0; sl < 4; sl++)
                redsum[hf * 128 + r0 + sl * 8] = ps[sl];
        }
        __syncthreads();   // P complete (both halves), sums ready
#pragma unroll
        for (int sl = 0; sl < 4; sl++) {
            int rr = r0 + sl * 8;
            l[sl] = l[sl] * sc[sl] + redsum[rr] + redsum[128 + rr];
            m[sl] = nm[sl];
        }
#pragma unroll
        for (int mt = 0; mt < 2; mt++)
#pragma unroll
            for (int nt = 0; nt < 8; nt++) {
                o[mt][nt][0] *= sc[2*mt]; o[mt][nt][1] *= sc[2*mt];
                o[mt][nt][2] *= sc[2*mt+1]; o[mt][nt][3] *= sc[2*mt+1];
            }

        // O += P V : warp tile 32 rows x 64 out cols (its half), K = 64 keys
#pragma unroll
        for (int ks = 0; ks < 8; ks++) {
            uint32_t af[2][4];
#pragma unroll
            for (int mt = 0; mt < 2; mt++) {
                int rr = r0 + mt * 16;
                af[mt][0] = Ps[rr * A4_PSTR + ks * 8 + tig];
                af[mt][1] = Ps[(rr + 8) * A4_PSTR + ks * 8 + tig];
                af[mt][2] = Ps[rr * A4_PSTR + ks * 8 + tig + 4];
                af[mt][3] = Ps[(rr + 8) * A4_PSTR + ks * 8 + tig + 4];
            }
#pragma unroll
            for (int nt = 0; nt < 8; nt++) {
                int vc = hf * 64 + nt * 8 + grp;
                uint32_t b0 = Vs[(ks * 8 + tig) * A4_VSTR + vc];
                uint32_t b1 = Vs[(ks * 8 + tig + 4) * A4_VSTR + vc];
#pragma unroll
                for (int mt = 0; mt < 2; mt++)
                    MMA_TF32(o[mt][nt][0], o[mt][nt][1], o[mt][nt][2], o[mt][nt][3],
                             af[mt][0], af[mt][1], af[mt][2], af[mt][3], b0, b1);
            }
        }
    }

    // epilogue: divide by l, write [B,S,H*DH]
    float inv[4];
#pragma unroll
    for (int sl = 0; sl < 4; sl++) inv[sl] = 1.f / l[sl];
#pragma unroll
    for (int mt = 0; mt < 2; mt++) {
        int rrg0 = q0 + r0 + mt * 16;
        float* dst0 = g_ctx + (size_t)(b * SS + rrg0) * DD + h * DHH;
        float* dst1 = g_ctx + (size_t)(b * SS + rrg0 + 8) * DD + h * DHH;
#pragma unroll
        for (int nt = 0; nt < 8; nt++) {
            int cn = hf * 64 + nt * 8 + 2 * tig;
            *(float2*)(dst0 + cn) = make_float2(o[mt][nt][0] * inv[2*mt],
                                                o[mt][nt][1] * inv[2*mt]);
            *(float2*)(dst1 + cn) = make_float2(o[mt][nt][2] * inv[2*mt+1],
                                                o[mt][nt][3] * inv[2*mt+1]);
        }
    }
}

// ---------------- launch ----------------
extern "C" void kernel_launch(void* const* d_in, const int* in_sizes, int n_in,
                              void* d_out, int out_size) {
    const float* x    = (const float*)d_in[0];
    const float* Wqkv = (const float*)d_in[1];
    const float* bqkv = (const float*)d_in[2];
    const float* Wo   = (const float*)d_in[3];
    const float* bo   = (const float*)d_in[4];
    float* out = (float*)d_out;

    void *qkvPtr, *ctxPtr;
    cudaGetSymbolAddress(&qkvPtr, g_qkv);
    cudaGetSymbolAddress(&ctxPtr, g_ctx);

    cudaFuncSetAttribute(attn_mma_kernel,
                         cudaFuncAttributeMaxDynamicSharedMemorySize,
                         A4_SMEM_BYTES);
    cudaFuncSetAttribute(mma_gemm_kernel,
                         cudaFuncAttributeMaxDynamicSharedMemorySize,
                         G2_SMEM_BYTES);

    // 1) RoPE tables
    rope_table_kernel<<<(SS * 64 + 255) / 256, 256>>>();

    // 2) QKV GEMM (tf32 mma.sync)
    mma_gemm_kernel<<<dim3(ND3 / G2_BN, (BB * SS) / G2_BM), 512, G2_SMEM_BYTES>>>(
        x, Wqkv, bqkv, (float*)qkvPtr, BB * SS, ND3, DD);

    // 3) RoPE + split/transpose (+ fold 1/sqrt(DH) into Q)
    rope_split_kernel<<<(BB * HH * SS * 64) / 256, 256>>>();

    // 4) flash attention v4 (32x32 / 32x64 warp tiles) -> g_ctx
    attn_mma_kernel<<<dim3(SS / 128, BB * HH), 256, A4_SMEM_BYTES>>>();

    // 5) output projection (tf32 mma.sync)
    mma_gemm_kernel<<<dim3(DD / G2_BN, (BB * SS) / G2_BM), 512, G2_SMEM_BYTES>>>(
        (const float*)ctxPtr, Wo, bo, out, BB * SS, DD, DD);
}

// round 10
// speedup vs baseline: 1.1989x; 1.0289x over previous
#include <cuda_runtime.h>
#include <math.h>
#include <stdint.h>

#define BB 2
#define SS 2048
#define DD 2048
#define HH 16
#define DHH 128
#define ND3 (3*DD)

// ---------------- scratch (static device globals; no allocation) ----------------
__device__ float g_qkv[(size_t)BB*SS*ND3];      // [B,S,3D]
__device__ float g_q  [(size_t)BB*HH*SS*DHH];   // [B,H,S,DH] (pre-scaled by 1/sqrt(DH))
__device__ float g_k  [(size_t)BB*HH*SS*DHH];
__device__ float g_v  [(size_t)BB*HH*SS*DHH];
__device__ float g_ctx[(size_t)BB*SS*DD];       // [B,S,H*DH]
__device__ float g_cos[SS*64];
__device__ float g_sin[SS*64];

__device__ __forceinline__ uint32_t f32_to_tf32(float x) {
    uint32_t r;
    asm("cvt.rna.tf32.f32 %0, %1;" : "=r"(r) : "f"(x));
    return r;
}

#define MMA_TF32(c0,c1,c2,c3,a0,a1,a2,a3,b0,b1)                          \
    asm volatile(                                                        \
        "mma.sync.aligned.m16n8k8.row.col.f32.tf32.tf32.f32 "            \
        "{%0,%1,%2,%3}, {%4,%5,%6,%7}, {%8,%9}, {%0,%1,%2,%3};"          \
        : "+f"(c0), "+f"(c1), "+f"(c2), "+f"(c3)                         \
        : "r"(a0), "r"(a1), "r"(a2), "r"(a3), "r"(b0), "r"(b1))

// ==================== tf32 mma.sync GEMM v4: 64x64 warp tiles ====================
// CTA tile 256x128, 256 threads = 8 warps (4 row x 2 col), warp tile 64x64, K-chunk 32.
// LDS:MMA ratio 1.0 (A 16 + B 16 LDS per 32 MMAs per kk).
#define G4_BM 256
#define G4_BN 128
#define G4_BK 32
#define G4_ASTR 36
#define G4_BSTR 132
#define G4_SMEM_BYTES ((G4_BM*G4_ASTR + G4_BK*G4_BSTR) * 4)

__global__ void __launch_bounds__(256) mma_gemm_kernel(
    const float* __restrict__ A, const float* __restrict__ Bm,
    const float* __restrict__ bias, float* __restrict__ C,
    int M, int N, int K)
{
    extern __shared__ uint32_t gsm[];
    uint32_t* As = gsm;                    // [256][36]
    uint32_t* Bs = gsm + G4_BM * G4_ASTR;  // [32][132]

    int tid  = threadIdx.x;
    int lane = tid & 31;
    int w    = tid >> 5;     // 0..7
    int wr   = w >> 1;       // 0..3 (64-row block)
    int wc   = w & 1;        // 0..1 (64-col block)
    int grp  = lane >> 2;
    int tig  = lane & 3;
    int m0 = blockIdx.y * G4_BM;
    int n0 = blockIdx.x * G4_BN;

    float acc[4][8][4];
#pragma unroll
    for (int mt = 0; mt < 4; mt++)
#pragma unroll
        for (int nt = 0; nt < 8; nt++)
#pragma unroll
            for (int i = 0; i < 4; i++) acc[mt][nt][i] = 0.f;

    // per-chunk loads: A 256x32 -> 8 float4/thread, B 32x128 -> 4 float4/thread
    float4 pa[8], pb[4];
#pragma unroll
    for (int i = 0; i < 8; i++) {
        int s = tid + i * 256;
        int ar = s >> 3, ac = (s & 7) * 4;
        pa[i] = *(const float4*)(A + (size_t)(m0 + ar) * K + ac);
    }
#pragma unroll
    for (int i = 0; i < 4; i++) {
        int s = tid + i * 256;
        int br = s >> 5, bc = (s & 31) * 4;
        pb[i] = *(const float4*)(Bm + (size_t)br * N + n0 + bc);
    }

    const int nCh = K / G4_BK;
    for (int kc = 0; kc < nCh; kc++) {
#pragma unroll
        for (int i = 0; i < 8; i++) {
            int s = tid + i * 256;
            int ar = s >> 3, ac = (s & 7) * 4;
            uint4 t;
            t.x = f32_to_tf32(pa[i].x); t.y = f32_to_tf32(pa[i].y);
            t.z = f32_to_tf32(pa[i].z); t.w = f32_to_tf32(pa[i].w);
            *(uint4*)&As[ar * G4_ASTR + ac] = t;
        }
#pragma unroll
        for (int i = 0; i < 4; i++) {
            int s = tid + i * 256;
            int br = s >> 5, bc = (s & 31) * 4;
            uint4 t;
            t.x = f32_to_tf32(pb[i].x); t.y = f32_to_tf32(pb[i].y);
            t.z = f32_to_tf32(pb[i].z); t.w = f32_to_tf32(pb[i].w);
            *(uint4*)&Bs[br * G4_BSTR + bc] = t;
        }
        __syncthreads();

        if (kc + 1 < nCh) {
            int k0 = (kc + 1) * G4_BK;
#pragma unroll
            for (int i = 0; i < 8; i++) {
                int s = tid + i * 256;
                int ar = s >> 3, ac = (s & 7) * 4;
                pa[i] = *(const float4*)(A + (size_t)(m0 + ar) * K + k0 + ac);
            }
#pragma unroll
            for (int i = 0; i < 4; i++) {
                int s = tid + i * 256;
                int br = s >> 5, bc = (s & 31) * 4;
                pb[i] = *(const float4*)(Bm + (size_t)(k0 + br) * N + n0 + bc);
            }
        }

#pragma unroll
        for (int kk = 0; kk < 4; kk++) {
            uint32_t af[4][4], bf[8][2];
#pragma unroll
            for (int mt = 0; mt < 4; mt++) {
                int r = wr * 64 + mt * 16 + grp;
                int kb = kk * 8 + tig;
                af[mt][0] = As[r * G4_ASTR + kb];
                af[mt][1] = As[(r + 8) * G4_ASTR + kb];
                af[mt][2] = As[r * G4_ASTR + kb + 4];
                af[mt][3] = As[(r + 8) * G4_ASTR + kb + 4];
            }
#pragma unroll
            for (int nt = 0; nt < 8; nt++) {
                int cn = wc * 64 + nt * 8 + grp;
                bf[nt][0] = Bs[(kk * 8 + tig) * G4_BSTR + cn];
                bf[nt][1] = Bs[(kk * 8 + tig + 4) * G4_BSTR + cn];
            }
#pragma unroll
            for (int mt = 0; mt < 4; mt++)
#pragma unroll
                for (int nt = 0; nt < 8; nt++)
                    MMA_TF32(acc[mt][nt][0], acc[mt][nt][1], acc[mt][nt][2], acc[mt][nt][3],
                             af[mt][0], af[mt][1], af[mt][2], af[mt][3],
                             bf[nt][0], bf[nt][1]);
        }
        __syncthreads();
    }

#pragma unroll
    for (int mt = 0; mt < 4; mt++) {
        int r0 = m0 + wr * 64 + mt * 16 + grp;
#pragma unroll
        for (int nt = 0; nt < 8; nt++) {
            int cn = n0 + wc * 64 + nt * 8 + tig * 2;
            float b0 = bias[cn], b1 = bias[cn + 1];
            float2 v0 = make_float2(acc[mt][nt][0] + b0, acc[mt][nt][1] + b1);
            float2 v1 = make_float2(acc[mt][nt][2] + b0, acc[mt][nt][3] + b1);
            *(float2*)(C + (size_t)r0 * N + cn) = v0;
            *(float2*)(C + (size_t)(r0 + 8) * N + cn) = v1;
        }
    }
}

// ---------------- RoPE tables ----------------
__global__ void rope_table_kernel() {
    int idx = blockIdx.x * blockDim.x + threadIdx.x;
    if (idx >= SS * 64) return;
    int t = idx >> 6;
    int j = idx & 63;
    double theta = (double)t * pow(10000.0, -(double)j / 64.0);
    g_cos[idx] = (float)cos(theta);
    g_sin[idx] = (float)sin(theta);
}

// ---------------- RoPE + split + transpose to [B,H,S,DH] ----------------
__global__ void rope_split_kernel() {
    int idx = blockIdx.x * blockDim.x + threadIdx.x;
    if (idx >= BB * HH * SS * 64) return;
    int j = idx & 63;
    int s = (idx >> 6) & (SS - 1);
    int h = (idx >> 17) & (HH - 1);
    int b = idx >> 21;

    const float* qrow = g_qkv + (size_t)(b * SS + s) * ND3 + h * DHH;
    const float* krow = qrow + DD;
    const float* vrow = qrow + 2 * DD;
    float c  = g_cos[s * 64 + j];
    float sn = g_sin[s * 64 + j];
    size_t o = ((size_t)(b * HH + h) * SS + s) * DHH;

    const float qscale = 0.088388347648318447f;  // 1/sqrt(128)

    float u0 = qrow[j], u1 = qrow[j + 64], ue = qrow[2 * j], uo = qrow[2 * j + 1];
    g_q[o + j]      = (u0 * c + uo * sn) * qscale;
    g_q[o + j + 64] = (u1 * c - ue * sn) * qscale;

    u0 = krow[j]; u1 = krow[j + 64]; ue = krow[2 * j]; uo = krow[2 * j + 1];
    g_k[o + j]      = u0 * c + uo * sn;
    g_k[o + j + 64] = u1 * c - ue * sn;

    g_v[o + j]      = vrow[j];
    g_v[o + j + 64] = vrow[j + 64];
}

// ==================== flash attention v4 (R8, known-good 627us) ====================
#define A4_QSTR 132
#define A4_KSTR 132
#define A4_VSTR 136
#define A4_PSTR 72
#define A4_RED  (128*A4_QSTR + 64*A4_KSTR + 64*A4_VSTR + 128*A4_PSTR)
#define A4_SMEM_U32 (A4_RED + 512)
#define A4_SMEM_BYTES (A4_SMEM_U32 * 4)

__global__ void __launch_bounds__(256) attn_mma_kernel() {
    extern __shared__ uint32_t sm4[];
    uint32_t* Qs = sm4;                          // [128][132] tf32
    uint32_t* Ks = Qs + 128 * A4_QSTR;           // [64][132]  tf32
    uint32_t* Vs = Ks + 64 * A4_KSTR;            // [64][136]  tf32
    uint32_t* Ps = Vs + 64 * A4_VSTR;            // [128][72]  tf32
    float* redmax = (float*)(sm4 + A4_RED);      // [2][128]
    float* redsum = redmax + 256;                // [2][128]

    int tid  = threadIdx.x;
    int lane = tid & 31;
    int w    = tid >> 5;        // 0..7
    int g    = w & 3;           // row group: q rows [g*32, g*32+32)
    int hf   = w >> 2;          // 0/1: key half (QK) / out-col half (PV)
    int grp  = lane >> 2;       // 0..7
    int tig  = lane & 3;        // 0..3

    int bh = blockIdx.y;
    int b = bh >> 4, h = bh & 15;
    int q0 = blockIdx.x * 128;

    const float* Qg = g_q + (size_t)bh * SS * DHH;
    const float* Kg = g_k + (size_t)bh * SS * DHH;
    const float* Vg = g_v + (size_t)bh * SS * DHH;

#pragma unroll
    for (int i = 0; i < 16; i++) {
        int flat = tid + i * 256;
        int r = flat >> 5, c = (flat & 31) * 4;
        float4 q4 = *(const float4*)(Qg + (size_t)(q0 + r) * DHH + c);
        uint4 t;
        t.x = f32_to_tf32(q4.x); t.y = f32_to_tf32(q4.y);
        t.z = f32_to_tf32(q4.z); t.w = f32_to_tf32(q4.w);
        *(uint4*)&Qs[r * A4_QSTR + c] = t;
    }

    int r0 = g * 32 + grp;
    float o[2][8][4];
#pragma unroll
    for (int mt = 0; mt < 2; mt++)
#pragma unroll
        for (int nt = 0; nt < 8; nt++)
#pragma unroll
            for (int i = 0; i < 4; i++) o[mt][nt][i] = 0.f;
    float m[4] = {-1e30f, -1e30f, -1e30f, -1e30f};
    float l[4] = {0.f, 0.f, 0.f, 0.f};

    for (int kt = 0; kt < SS / 64; kt++) {
        __syncthreads();
#pragma unroll
        for (int i = 0; i < 8; i++) {
            int flat = tid + i * 256;
            int r = flat >> 5, c = (flat & 31) * 4;
            float4 k4 = *(const float4*)(Kg + (size_t)(kt * 64 + r) * DHH + c);
            uint4 t;
            t.x = f32_to_tf32(k4.x); t.y = f32_to_tf32(k4.y);
            t.z = f32_to_tf32(k4.z); t.w = f32_to_tf32(k4.w);
            *(uint4*)&Ks[r * A4_KSTR + c] = t;
            float4 v4 = *(const float4*)(Vg + (size_t)(kt * 64 + r) * DHH + c);
            t.x = f32_to_tf32(v4.x); t.y = f32_to_tf32(v4.y);
            t.z = f32_to_tf32(v4.z); t.w = f32_to_tf32(v4.w);
            *(uint4*)&Vs[r * A4_VSTR + c] = t;
        }
        __syncthreads();

        float s[2][4][4];
#pragma unroll
        for (int mt = 0; mt < 2; mt++)
#pragma unroll
            for (int nt = 0; nt < 4; nt++)
#pragma unroll
                for (int i = 0; i < 4; i++) s[mt][nt][i] = 0.f;

#pragma unroll
        for (int ks = 0; ks < 16; ks++) {
            uint32_t af[2][4];
#pragma unroll
            for (int mt = 0; mt < 2; mt++) {
                int rr = r0 + mt * 16;
                af[mt][0] = Qs[rr * A4_QSTR + ks * 8 + tig];
                af[mt][1] = Qs[(rr + 8) * A4_QSTR + ks * 8 + tig];
                af[mt][2] = Qs[rr * A4_QSTR + ks * 8 + tig + 4];
                af[mt][3] = Qs[(rr + 8) * A4_QSTR + ks * 8 + tig + 4];
            }
#pragma unroll
            for (int nt = 0; nt < 4; nt++) {
                int kr = hf * 32 + nt * 8 + grp;
                uint32_t b0 = Ks[kr * A4_KSTR + ks * 8 + tig];
                uint32_t b1 = Ks[kr * A4_KSTR + ks * 8 + tig + 4];
#pragma unroll
                for (int mt = 0; mt < 2; mt++)
                    MMA_TF32(s[mt][nt][0], s[mt][nt][1], s[mt][nt][2], s[mt][nt][3],
                             af[mt][0], af[mt][1], af[mt][2], af[mt][3], b0, b1);
            }
        }

        float mx[4] = {-1e30f, -1e30f, -1e30f, -1e30f};
#pragma unroll
        for (int mt = 0; mt < 2; mt++)
#pragma unroll
            for (int nt = 0; nt < 4; nt++) {
                mx[2*mt]   = fmaxf(mx[2*mt],   fmaxf(s[mt][nt][0], s[mt][nt][1]));
                mx[2*mt+1] = fmaxf(mx[2*mt+1], fmaxf(s[mt][nt][2], s[mt][nt][3]));
            }
#pragma unroll
        for (int off = 1; off <= 2; off <<= 1)
#pragma unroll
            for (int sl = 0; sl < 4; sl++)
                mx[sl] = fmaxf(mx[sl], __shfl_xor_sync(0xffffffffu, mx[sl], off));
        if (tig == 0) {
#pragma unroll
            for (int sl = 0; sl < 4; sl++)
                redmax[hf * 128 + r0 + sl * 8] = mx[sl];
        }
        __syncthreads();
        float nm[4], sc[4];
#pragma unroll
        for (int sl = 0; sl < 4; sl++) {
            int rr = r0 + sl * 8;
            nm[sl] = fmaxf(m[sl], fmaxf(redmax[rr], redmax[128 + rr]));
            sc[sl] = __expf(m[sl] - nm[sl]);
        }

        float ps[4] = {0.f, 0.f, 0.f, 0.f};
#pragma unroll
        for (int mt = 0; mt < 2; mt++)
#pragma unroll
            for (int nt = 0; nt < 4; nt++) {
                float p0 = __expf(s[mt][nt][0] - nm[2*mt]);
                float p1 = __expf(s[mt][nt][1] - nm[2*mt]);
                float p2 = __expf(s[mt][nt][2] - nm[2*mt+1]);
                float p3 = __expf(s[mt][nt][3] - nm[2*mt+1]);
                ps[2*mt]   += p0 + p1;
                ps[2*mt+1] += p2 + p3;
                int pc = hf * 32 + nt * 8 + 2 * tig;
                int rr = r0 + mt * 16;
                uint2 t0 = make_uint2(f32_to_tf32(p0), f32_to_tf32(p1));
                uint2 t1 = make_uint2(f32_to_tf32(p2), f32_to_tf32(p3));
                *(uint2*)&Ps[rr * A4_PSTR + pc] = t0;
                *(uint2*)&Ps[(rr + 8) * A4_PSTR + pc] = t1;
            }
#pragma unroll
        for (int off = 1; off <= 2; off <<= 1)
#pragma unroll
            for (int sl = 0; sl < 4; sl++)
                ps[sl] += __shfl_xor_sync(0xffffffffu, ps[sl], off);
        if (tig == 0) {
#pragma unroll
            for (int sl = 0; sl < 4; sl++)
                redsum[hf * 128 + r0 + sl * 8] = ps[sl];
        }
        __syncthreads();
#pragma unroll
        for (int sl = 0; sl < 4; sl++) {
            int rr = r0 + sl * 8;
            l[sl] = l[sl] * sc[sl] + redsum[rr] + redsum[128 + rr];
            m[sl] = nm[sl];
        }
#pragma unroll
        for (int mt = 0; mt < 2; mt++)
#pragma unroll
            for (int nt = 0; nt < 8; nt++) {
                o[mt][nt][0] *= sc[2*mt]; o[mt][nt][1] *= sc[2*mt];
                o[mt][nt][2] *= sc[2*mt+1]; o[mt][nt][3] *= sc[2*mt+1];
            }

#pragma unroll
        for (int ks = 0; ks < 8; ks++) {
            uint32_t af[2][4];
#pragma unroll
            for (int mt = 0; mt < 2; mt++) {
                int rr = r0 + mt * 16;
                af[mt][0] = Ps[rr * A4_PSTR + ks * 8 + tig];
                af[mt][1] = Ps[(rr + 8) * A4_PSTR + ks * 8 + tig];
                af[mt][2] = Ps[rr * A4_PSTR + ks * 8 + tig + 4];
                af[mt][3] = Ps[(rr + 8) * A4_PSTR + ks * 8 + tig + 4];
            }
#pragma unroll
            for (int nt = 0; nt < 8; nt++) {
                int vc = hf * 64 + nt * 8 + grp;
                uint32_t b0 = Vs[(ks * 8 + tig) * A4_VSTR + vc];
                uint32_t b1 = Vs[(ks * 8 + tig + 4) * A4_VSTR + vc];
#pragma unroll
                for (int mt = 0; mt < 2; mt++)
                    MMA_TF32(o[mt][nt][0], o[mt][nt][1], o[mt][nt][2], o[mt][nt][3],
                             af[mt][0], af[mt][1], af[mt][2], af[mt][3], b0, b1);
            }
        }
    }

    float inv[4];
#pragma unroll
    for (int sl = 0; sl < 4; sl++) inv[sl] = 1.f / l[sl];
#pragma unroll
    for (int mt = 0; mt < 2; mt++) {
        int rrg0 = q0 + r0 + mt * 16;
        float* dst0 = g_ctx + (size_t)(b * SS + rrg0) * DD + h * DHH;
        float* dst1 = g_ctx + (size_t)(b * SS + rrg0 + 8) * DD + h * DHH;
#pragma unroll
        for (int nt = 0; nt < 8; nt++) {
            int cn = hf * 64 + nt * 8 + 2 * tig;
            *(float2*)(dst0 + cn) = make_float2(o[mt][nt][0] * inv[2*mt],
                                                o[mt][nt][1] * inv[2*mt]);
            *(float2*)(dst1 + cn) = make_float2(o[mt][nt][2] * inv[2*mt+1],
                                                o[mt][nt][3] * inv[2*mt+1]);
        }
    }
}

// ---------------- launch ----------------
extern "C" void kernel_launch(void* const* d_in, const int* in_sizes, int n_in,
                              void* d_out, int out_size) {
    const float* x    = (const float*)d_in[0];
    const float* Wqkv = (const float*)d_in[1];
    const float* bqkv = (const float*)d_in[2];
    const float* Wo   = (const float*)d_in[3];
    const float* bo   = (const float*)d_in[4];
    float* out = (float*)d_out;

    void *qkvPtr, *ctxPtr;
    cudaGetSymbolAddress(&qkvPtr, g_qkv);
    cudaGetSymbolAddress(&ctxPtr, g_ctx);

    cudaFuncSetAttribute(attn_mma_kernel,
                         cudaFuncAttributeMaxDynamicSharedMemorySize,
                         A4_SMEM_BYTES);
    cudaFuncSetAttribute(mma_gemm_kernel,
                         cudaFuncAttributeMaxDynamicSharedMemorySize,
                         G4_SMEM_BYTES);

    // 1) RoPE tables
    rope_table_kernel<<<(SS * 64 + 255) / 256, 256>>>();

    // 2) QKV GEMM (tf32 mma.sync, 64x64 warp tiles)
    mma_gemm_kernel<<<dim3(ND3 / G4_BN, (BB * SS) / G4_BM), 256, G4_SMEM_BYTES>>>(
        x, Wqkv, bqkv, (float*)qkvPtr, BB * SS, ND3, DD);

    // 3) RoPE + split/transpose (+ fold 1/sqrt(DH) into Q)
    rope_split_kernel<<<(BB * HH * SS * 64) / 256, 256>>>();

    // 4) flash attention v4 (R8) -> g_ctx
    attn_mma_kernel<<<dim3(SS / 128, BB * HH), 256, A4_SMEM_BYTES>>>();

    // 5) output projection (tf32 mma.sync, 64x64 warp tiles)
    mma_gemm_kernel<<<dim3(DD / G4_BN, (BB * SS) / G4_BM), 256, G4_SMEM_BYTES>>>(
        (const float*)ctxPtr, Wo, bo, out, BB * SS, DD, DD);
}

// round 11
// speedup vs baseline: 1.2527x; 1.0449x over previous
#include <cuda_runtime.h>
#include <math.h>
#include <stdint.h>

#define BB 2
#define SS 2048
#define DD 2048
#define HH 16
#define DHH 128
#define ND3 (3*DD)

// ---------------- scratch (static device globals; no allocation) ----------------
__device__ float g_qkv[(size_t)BB*SS*ND3];      // [B,S,3D]
__device__ float g_q  [(size_t)BB*HH*SS*DHH];   // [B,H,S,DH] (pre-scaled by 1/sqrt(128))
__device__ float g_k  [(size_t)BB*HH*SS*DHH];
__device__ float g_v  [(size_t)BB*HH*SS*DHH];
__device__ float g_ctx[(size_t)BB*SS*DD];       // [B,S,H*DH]
__device__ float g_cos[SS*64];
__device__ float g_sin[SS*64];

__device__ __forceinline__ uint32_t f32_to_tf32(float x) {
    uint32_t r;
    asm("cvt.rna.tf32.f32 %0, %1;" : "=r"(r) : "f"(x));
    return r;
}

#define MMA_TF32(c0,c1,c2,c3,a0,a1,a2,a3,b0,b1)                          \
    asm volatile(                                                        \
        "mma.sync.aligned.m16n8k8.row.col.f32.tf32.tf32.f32 "            \
        "{%0,%1,%2,%3}, {%4,%5,%6,%7}, {%8,%9}, {%0,%1,%2,%3};"          \
        : "+f"(c0), "+f"(c1), "+f"(c2), "+f"(c3)                         \
        : "r"(a0), "r"(a1), "r"(a2), "r"(a3), "r"(b0), "r"(b1))

// ==================== tf32 mma.sync GEMM v4: 64x64 warp tiles (R9, known-good) ====================
#define G4_BM 256
#define G4_BN 128
#define G4_BK 32
#define G4_ASTR 36
#define G4_BSTR 132
#define G4_SMEM_BYTES ((G4_BM*G4_ASTR + G4_BK*G4_BSTR) * 4)

__global__ void __launch_bounds__(256) mma_gemm_kernel(
    const float* __restrict__ A, const float* __restrict__ Bm,
    const float* __restrict__ bias, float* __restrict__ C,
    int M, int N, int K)
{
    extern __shared__ uint32_t gsm[];
    uint32_t* As = gsm;                    // [256][36]
    uint32_t* Bs = gsm + G4_BM * G4_ASTR;  // [32][132]

    int tid  = threadIdx.x;
    int lane = tid & 31;
    int w    = tid >> 5;
    int wr   = w >> 1;
    int wc   = w & 1;
    int grp  = lane >> 2;
    int tig  = lane & 3;
    int m0 = blockIdx.y * G4_BM;
    int n0 = blockIdx.x * G4_BN;

    float acc[4][8][4];
#pragma unroll
    for (int mt = 0; mt < 4; mt++)
#pragma unroll
        for (int nt = 0; nt < 8; nt++)
#pragma unroll
            for (int i = 0; i < 4; i++) acc[mt][nt][i] = 0.f;

    float4 pa[8], pb[4];
#pragma unroll
    for (int i = 0; i < 8; i++) {
        int s = tid + i * 256;
        int ar = s >> 3, ac = (s & 7) * 4;
        pa[i] = *(const float4*)(A + (size_t)(m0 + ar) * K + ac);
    }
#pragma unroll
    for (int i = 0; i < 4; i++) {
        int s = tid + i * 256;
        int br = s >> 5, bc = (s & 31) * 4;
        pb[i] = *(const float4*)(Bm + (size_t)br * N + n0 + bc);
    }

    const int nCh = K / G4_BK;
    for (int kc = 0; kc < nCh; kc++) {
#pragma unroll
        for (int i = 0; i < 8; i++) {
            int s = tid + i * 256;
            int ar = s >> 3, ac = (s & 7) * 4;
            uint4 t;
            t.x = f32_to_tf32(pa[i].x); t.y = f32_to_tf32(pa[i].y);
            t.z = f32_to_tf32(pa[i].z); t.w = f32_to_tf32(pa[i].w);
            *(uint4*)&As[ar * G4_ASTR + ac] = t;
        }
#pragma unroll
        for (int i = 0; i < 4; i++) {
            int s = tid + i * 256;
            int br = s >> 5, bc = (s & 31) * 4;
            uint4 t;
            t.x = f32_to_tf32(pb[i].x); t.y = f32_to_tf32(pb[i].y);
            t.z = f32_to_tf32(pb[i].z); t.w = f32_to_tf32(pb[i].w);
            *(uint4*)&Bs[br * G4_BSTR + bc] = t;
        }
        __syncthreads();

        if (kc + 1 < nCh) {
            int k0 = (kc + 1) * G4_BK;
#pragma unroll
            for (int i = 0; i < 8; i++) {
                int s = tid + i * 256;
                int ar = s >> 3, ac = (s & 7) * 4;
                pa[i] = *(const float4*)(A + (size_t)(m0 + ar) * K + k0 + ac);
            }
#pragma unroll
            for (int i = 0; i < 4; i++) {
                int s = tid + i * 256;
                int br = s >> 5, bc = (s & 31) * 4;
                pb[i] = *(const float4*)(Bm + (size_t)(k0 + br) * N + n0 + bc);
            }
        }

#pragma unroll
        for (int kk = 0; kk < 4; kk++) {
            uint32_t af[4][4], bf[8][2];
#pragma unroll
            for (int mt = 0; mt < 4; mt++) {
                int r = wr * 64 + mt * 16 + grp;
                int kb = kk * 8 + tig;
                af[mt][0] = As[r * G4_ASTR + kb];
                af[mt][1] = As[(r + 8) * G4_ASTR + kb];
                af[mt][2] = As[r * G4_ASTR + kb + 4];
                af[mt][3] = As[(r + 8) * G4_ASTR + kb + 4];
            }
#pragma unroll
            for (int nt = 0; nt < 8; nt++) {
                int cn = wc * 64 + nt * 8 + grp;
                bf[nt][0] = Bs[(kk * 8 + tig) * G4_BSTR + cn];
                bf[nt][1] = Bs[(kk * 8 + tig + 4) * G4_BSTR + cn];
            }
#pragma unroll
            for (int mt = 0; mt < 4; mt++)
#pragma unroll
                for (int nt = 0; nt < 8; nt++)
                    MMA_TF32(acc[mt][nt][0], acc[mt][nt][1], acc[mt][nt][2], acc[mt][nt][3],
                             af[mt][0], af[mt][1], af[mt][2], af[mt][3],
                             bf[nt][0], bf[nt][1]);
        }
        __syncthreads();
    }

#pragma unroll
    for (int mt = 0; mt < 4; mt++) {
        int r0 = m0 + wr * 64 + mt * 16 + grp;
#pragma unroll
        for (int nt = 0; nt < 8; nt++) {
            int cn = n0 + wc * 64 + nt * 8 + tig * 2;
            float b0 = bias[cn], b1 = bias[cn + 1];
            float2 v0 = make_float2(acc[mt][nt][0] + b0, acc[mt][nt][1] + b1);
            float2 v1 = make_float2(acc[mt][nt][2] + b0, acc[mt][nt][3] + b1);
            *(float2*)(C + (size_t)r0 * N + cn) = v0;
            *(float2*)(C + (size_t)(r0 + 8) * N + cn) = v1;
        }
    }
}

// ---------------- RoPE tables ----------------
__global__ void rope_table_kernel() {
    int idx = blockIdx.x * blockDim.x + threadIdx.x;
    if (idx >= SS * 64) return;
    int t = idx >> 6;
    int j = idx & 63;
    double theta = (double)t * pow(10000.0, -(double)j / 64.0);
    g_cos[idx] = (float)cos(theta);
    g_sin[idx] = (float)sin(theta);
}

// ---------------- RoPE + split + transpose to [B,H,S,DH] ----------------
__global__ void rope_split_kernel() {
    int idx = blockIdx.x * blockDim.x + threadIdx.x;
    if (idx >= BB * HH * SS * 64) return;
    int j = idx & 63;
    int s = (idx >> 6) & (SS - 1);
    int h = (idx >> 17) & (HH - 1);
    int b = idx >> 21;

    const float* qrow = g_qkv + (size_t)(b * SS + s) * ND3 + h * DHH;
    const float* krow = qrow + DD;
    const float* vrow = qrow + 2 * DD;
    float c  = g_cos[s * 64 + j];
    float sn = g_sin[s * 64 + j];
    size_t o = ((size_t)(b * HH + h) * SS + s) * DHH;

    const float qscale = 0.088388347648318447f;  // 1/sqrt(128)

    float u0 = qrow[j], u1 = qrow[j + 64], ue = qrow[2 * j], uo = qrow[2 * j + 1];
    g_q[o + j]      = (u0 * c + uo * sn) * qscale;
    g_q[o + j + 64] = (u1 * c - ue * sn) * qscale;

    u0 = krow[j]; u1 = krow[j + 64]; ue = krow[2 * j]; uo = krow[2 * j + 1];
    g_k[o + j]      = u0 * c + uo * sn;
    g_k[o + j + 64] = u1 * c - ue * sn;

    g_v[o + j]      = vrow[j];
    g_v[o + j + 64] = vrow[j + 64];
}

// ==================== flash attention v5: R8 tiling + K/V register prefetch ====================
#define A4_QSTR 132
#define A4_KSTR 132
#define A4_VSTR 136
#define A4_PSTR 72
#define A4_RED  (128*A4_QSTR + 64*A4_KSTR + 64*A4_VSTR + 128*A4_PSTR)
#define A4_SMEM_U32 (A4_RED + 512)
#define A4_SMEM_BYTES (A4_SMEM_U32 * 4)

__global__ void __launch_bounds__(256, 1) attn_mma_kernel() {
    extern __shared__ uint32_t sm4[];
    uint32_t* Qs = sm4;                          // [128][132] tf32
    uint32_t* Ks = Qs + 128 * A4_QSTR;           // [64][132]  tf32
    uint32_t* Vs = Ks + 64 * A4_KSTR;            // [64][136]  tf32
    uint32_t* Ps = Vs + 64 * A4_VSTR;            // [128][72]  tf32
    float* redmax = (float*)(sm4 + A4_RED);      // [2][128]
    float* redsum = redmax + 256;                // [2][128]

    int tid  = threadIdx.x;
    int lane = tid & 31;
    int w    = tid >> 5;        // 0..7
    int g    = w & 3;           // row group: q rows [g*32, g*32+32)
    int hf   = w >> 2;          // 0/1: key half (QK) / out-col half (PV)
    int grp  = lane >> 2;       // 0..7
    int tig  = lane & 3;        // 0..3

    int bh = blockIdx.y;
    int b = bh >> 4, h = bh & 15;
    int q0 = blockIdx.x * 128;

    const float* Qg = g_q + (size_t)bh * SS * DHH;
    const float* Kg = g_k + (size_t)bh * SS * DHH;
    const float* Vg = g_v + (size_t)bh * SS * DHH;

    // this thread's fixed gmem slot for K/V tile loads
    int ldr[8], ldc[8];
#pragma unroll
    for (int i = 0; i < 8; i++) {
        int flat = tid + i * 256;
        ldr[i] = flat >> 5;
        ldc[i] = (flat & 31) * 4;
    }

    // load Q tile (tf32): 128 rows x 128 d
#pragma unroll
    for (int i = 0; i < 16; i++) {
        int flat = tid + i * 256;
        int r = flat >> 5, c = (flat & 31) * 4;
        float4 q4 = *(const float4*)(Qg + (size_t)(q0 + r) * DHH + c);
        uint4 t;
        t.x = f32_to_tf32(q4.x); t.y = f32_to_tf32(q4.y);
        t.z = f32_to_tf32(q4.z); t.w = f32_to_tf32(q4.w);
        *(uint4*)&Qs[r * A4_QSTR + c] = t;
    }

    // prefetch K/V tile 0 into registers
    float4 kpf[8], vpf[8];
#pragma unroll
    for (int i = 0; i < 8; i++) {
        kpf[i] = *(const float4*)(Kg + (size_t)ldr[i] * DHH + ldc[i]);
        vpf[i] = *(const float4*)(Vg + (size_t)ldr[i] * DHH + ldc[i]);
    }

    int r0 = g * 32 + grp;
    float o[2][8][4];
#pragma unroll
    for (int mt = 0; mt < 2; mt++)
#pragma unroll
        for (int nt = 0; nt < 8; nt++)
#pragma unroll
            for (int i = 0; i < 4; i++) o[mt][nt][i] = 0.f;
    float m[4] = {-1e30f, -1e30f, -1e30f, -1e30f};
    float l[4] = {0.f, 0.f, 0.f, 0.f};

    const int NKT = SS / 64;
    for (int kt = 0; kt < NKT; kt++) {
        __syncthreads();   // prev iter done reading Ks/Vs/Ps
        // store prefetched K/V tile (cvt to tf32)
#pragma unroll
        for (int i = 0; i < 8; i++) {
            uint4 t;
            t.x = f32_to_tf32(kpf[i].x); t.y = f32_to_tf32(kpf[i].y);
            t.z = f32_to_tf32(kpf[i].z); t.w = f32_to_tf32(kpf[i].w);
            *(uint4*)&Ks[ldr[i] * A4_KSTR + ldc[i]] = t;
            t.x = f32_to_tf32(vpf[i].x); t.y = f32_to_tf32(vpf[i].y);
            t.z = f32_to_tf32(vpf[i].z); t.w = f32_to_tf32(vpf[i].w);
            *(uint4*)&Vs[ldr[i] * A4_VSTR + ldc[i]] = t;
        }
        __syncthreads();

        // issue gmem loads for next tile (overlap with all compute below)
        {
            int ktn = (kt + 1 < NKT) ? kt + 1 : kt;
            const float* Kn = Kg + (size_t)(ktn * 64) * DHH;
            const float* Vn = Vg + (size_t)(ktn * 64) * DHH;
#pragma unroll
            for (int i = 0; i < 8; i++) {
                kpf[i] = *(const float4*)(Kn + (size_t)ldr[i] * DHH + ldc[i]);
                vpf[i] = *(const float4*)(Vn + (size_t)ldr[i] * DHH + ldc[i]);
            }
        }

        // S = Q K^T : warp tile 32 rows x 32 keys (its half)
        float s[2][4][4];
#pragma unroll
        for (int mt = 0; mt < 2; mt++)
#pragma unroll
            for (int nt = 0; nt < 4; nt++)
#pragma unroll
                for (int i = 0; i < 4; i++) s[mt][nt][i] = 0.f;

#pragma unroll
        for (int ks = 0; ks < 16; ks++) {
            uint32_t af[2][4];
#pragma unroll
            for (int mt = 0; mt < 2; mt++) {
                int rr = r0 + mt * 16;
                af[mt][0] = Qs[rr * A4_QSTR + ks * 8 + tig];
                af[mt][1] = Qs[(rr + 8) * A4_QSTR + ks * 8 + tig];
                af[mt][2] = Qs[rr * A4_QSTR + ks * 8 + tig + 4];
                af[mt][3] = Qs[(rr + 8) * A4_QSTR + ks * 8 + tig + 4];
            }
#pragma unroll
            for (int nt = 0; nt < 4; nt++) {
                int kr = hf * 32 + nt * 8 + grp;
                uint32_t b0 = Ks[kr * A4_KSTR + ks * 8 + tig];
                uint32_t b1 = Ks[kr * A4_KSTR + ks * 8 + tig + 4];
#pragma unroll
                for (int mt = 0; mt < 2; mt++)
                    MMA_TF32(s[mt][nt][0], s[mt][nt][1], s[mt][nt][2], s[mt][nt][3],
                             af[mt][0], af[mt][1], af[mt][2], af[mt][3], b0, b1);
            }
        }

        float mx[4] = {-1e30f, -1e30f, -1e30f, -1e30f};
#pragma unroll
        for (int mt = 0; mt < 2; mt++)
#pragma unroll
            for (int nt = 0; nt < 4; nt++) {
                mx[2*mt]   = fmaxf(mx[2*mt],   fmaxf(s[mt][nt][0], s[mt][nt][1]));
                mx[2*mt+1] = fmaxf(mx[2*mt+1], fmaxf(s[mt][nt][2], s[mt][nt][3]));
            }
#pragma unroll
        for (int off = 1; off <= 2; off <<= 1)
#pragma unroll
            for (int sl = 0; sl < 4; sl++)
                mx[sl] = fmaxf(mx[sl], __shfl_xor_sync(0xffffffffu, mx[sl], off));
        if (tig == 0) {
#pragma unroll
            for (int sl = 0; sl < 4; sl++)
                redmax[hf * 128 + r0 + sl * 8] = mx[sl];
        }
        __syncthreads();
        float nm[4], sc[4];
#pragma unroll
        for (int sl = 0; sl < 4; sl++) {
            int rr = r0 + sl * 8;
            nm[sl] = fmaxf(m[sl], fmaxf(redmax[rr], redmax[128 + rr]));
            sc[sl] = __expf(m[sl] - nm[sl]);
        }

        float ps[4] = {0.f, 0.f, 0.f, 0.f};
#pragma unroll
        for (int mt = 0; mt < 2; mt++)
#pragma unroll
            for (int nt = 0; nt < 4; nt++) {
                float p0 = __expf(s[mt][nt][0] - nm[2*mt]);
                float p1 = __expf(s[mt][nt][1] - nm[2*mt]);
                float p2 = __expf(s[mt][nt][2] - nm[2*mt+1]);
                float p3 = __expf(s[mt][nt][3] - nm[2*mt+1]);
                ps[2*mt]   += p0 + p1;
                ps[2*mt+1] += p2 + p3;
                int pc = hf * 32 + nt * 8 + 2 * tig;
                int rr = r0 + mt * 16;
                uint2 t0 = make_uint2(f32_to_tf32(p0), f32_to_tf32(p1));
                uint2 t1 = make_uint2(f32_to_tf32(p2), f32_to_tf32(p3));
                *(uint2*)&Ps[rr * A4_PSTR + pc] = t0;
                *(uint2*)&Ps[(rr + 8) * A4_PSTR + pc] = t1;
            }
#pragma unroll
        for (int off = 1; off <= 2; off <<= 1)
#pragma unroll
            for (int sl = 0; sl < 4; sl++)
                ps[sl] += __shfl_xor_sync(0xffffffffu, ps[sl], off);
        if (tig == 0) {
#pragma unroll
            for (int sl = 0; sl < 4; sl++)
                redsum[hf * 128 + r0 + sl * 8] = ps[sl];
        }
        __syncthreads();   // P complete (both halves), sums ready
#pragma unroll
        for (int sl = 0; sl < 4; sl++) {
            int rr = r0 + sl * 8;
            l[sl] = l[sl] * sc[sl] + redsum[rr] + redsum[128 + rr];
            m[sl] = nm[sl];
        }
#pragma unroll
        for (int mt = 0; mt < 2; mt++)
#pragma unroll
            for (int nt = 0; nt < 8; nt++) {
                o[mt][nt][0] *= sc[2*mt]; o[mt][nt][1] *= sc[2*mt];
                o[mt][nt][2] *= sc[2*mt+1]; o[mt][nt][3] *= sc[2*mt+1];
            }

        // O += P V : warp tile 32 rows x 64 out cols (its half), K = 64 keys
#pragma unroll
        for (int ks = 0; ks < 8; ks++) {
            uint32_t af[2][4];
#pragma unroll
            for (int mt = 0; mt < 2; mt++) {
                int rr = r0 + mt * 16;
                af[mt][0] = Ps[rr * A4_PSTR + ks * 8 + tig];
                af[mt][1] = Ps[(rr + 8) * A4_PSTR + ks * 8 + tig];
                af[mt][2] = Ps[rr * A4_PSTR + ks * 8 + tig + 4];
                af[mt][3] = Ps[(rr + 8) * A4_PSTR + ks * 8 + tig + 4];
            }
#pragma unroll
            for (int nt = 0; nt < 8; nt++) {
                int vc = hf * 64 + nt * 8 + grp;
                uint32_t b0 = Vs[(ks * 8 + tig) * A4_VSTR + vc];
                uint32_t b1 = Vs[(ks * 8 + tig + 4) * A4_VSTR + vc];
#pragma unroll
                for (int mt = 0; mt < 2; mt++)
                    MMA_TF32(o[mt][nt][0], o[mt][nt][1], o[mt][nt][2], o[mt][nt][3],
                             af[mt][0], af[mt][1], af[mt][2], af[mt][3], b0, b1);
            }
        }
    }

    float inv[4];
#pragma unroll
    for (int sl = 0; sl < 4; sl++) inv[sl] = 1.f / l[sl];
#pragma unroll
    for (int mt = 0; mt < 2; mt++) {
        int rrg0 = q0 + r0 + mt * 16;
        float* dst0 = g_ctx + (size_t)(b * SS + rrg0) * DD + h * DHH;
        float* dst1 = g_ctx + (size_t)(b * SS + rrg0 + 8) * DD + h * DHH;
#pragma unroll
        for (int nt = 0; nt < 8; nt++) {
            int cn = hf * 64 + nt * 8 + 2 * tig;
            *(float2*)(dst0 + cn) = make_float2(o[mt][nt][0] * inv[2*mt],
                                                o[mt][nt][1] * inv[2*mt]);
            *(float2*)(dst1 + cn) = make_float2(o[mt][nt][2] * inv[2*mt+1],
                                                o[mt][nt][3] * inv[2*mt+1]);
        }
    }
}

// ---------------- launch ----------------
extern "C" void kernel_launch(void* const* d_in, const int* in_sizes, int n_in,
                              void* d_out, int out_size) {
    const float* x    = (const float*)d_in[0];
    const float* Wqkv = (const float*)d_in[1];
    const float* bqkv = (const float*)d_in[2];
    const float* Wo   = (const float*)d_in[3];
    const float* bo   = (const float*)d_in[4];
    float* out = (float*)d_out;

    void *qkvPtr, *ctxPtr;
    cudaGetSymbolAddress(&qkvPtr, g_qkv);
    cudaGetSymbolAddress(&ctxPtr, g_ctx);

    cudaFuncSetAttribute(attn_mma_kernel,
                         cudaFuncAttributeMaxDynamicSharedMemorySize,
                         A4_SMEM_BYTES);
    cudaFuncSetAttribute(mma_gemm_kernel,
                         cudaFuncAttributeMaxDynamicSharedMemorySize,
                         G4_SMEM_BYTES);

    // 1) RoPE tables
    rope_table_kernel<<<(SS * 64 + 255) / 256, 256>>>();

    // 2) QKV GEMM (tf32 mma.sync, 64x64 warp tiles)
    mma_gemm_kernel<<<dim3(ND3 / G4_BN, (BB * SS) / G4_BM), 256, G4_SMEM_BYTES>>>(
        x, Wqkv, bqkv, (float*)qkvPtr, BB * SS, ND3, DD);

    // 3) RoPE + split/transpose (+ fold 1/sqrt(DH) into Q)
    rope_split_kernel<<<(BB * HH * SS * 64) / 256, 256>>>();

    // 4) flash attention v5 (K/V register prefetch) -> g_ctx
    attn_mma_kernel<<<dim3(SS / 128, BB * HH), 256, A4_SMEM_BYTES>>>();

    // 5) output projection (tf32 mma.sync, 64x64 warp tiles)
    mma_gemm_kernel<<<dim3(DD / G4_BN, (BB * SS) / G4_BM), 256, G4_SMEM_BYTES>>>(
        (const float*)ctxPtr, Wo, bo, out, BB * SS, DD, DD);
}

// round 12
// speedup vs baseline: 1.2928x; 1.0320x over previous
#include <cuda_runtime.h>
#include <math.h>
#include <stdint.h>

#define BB 2
#define SS 2048
#define DD 2048
#define HH 16
#define DHH 128
#define ND3 (3*DD)

// ---------------- scratch (static device globals; no allocation) ----------------
__device__ float g_qkv[(size_t)BB*SS*ND3];      // [B,S,3D]
__device__ float g_q  [(size_t)BB*HH*SS*DHH];   // [B,H,S,DH], tf32-rounded, scaled 1/sqrt(128)
__device__ float g_k  [(size_t)BB*HH*SS*DHH];   // tf32-rounded
__device__ float g_v  [(size_t)BB*HH*SS*DHH];   // tf32-rounded
__device__ float g_ctx[(size_t)BB*SS*DD];       // [B,S,H*DH], tf32-rounded
__device__ float g_cos[SS*64];
__device__ float g_sin[SS*64];
__device__ float g_xr   [(size_t)BB*SS*DD];     // tf32-rounded x
__device__ float g_wqkvr[(size_t)DD*ND3];       // tf32-rounded Wqkv
__device__ float g_wor  [(size_t)DD*DD];        // tf32-rounded Wo

__device__ __forceinline__ uint32_t f32_to_tf32(float x) {
    uint32_t r;
    asm("cvt.rna.tf32.f32 %0, %1;" : "=r"(r) : "f"(x));
    return r;
}

__device__ __forceinline__ uint32_t smem_u32(const void* p) {
    uint32_t a;
    asm("{ .reg .u64 t; cvta.to.shared.u64 t, %1; cvt.u32.u64 %0, t; }" : "=r"(a) : "l"(p));
    return a;
}

__device__ __forceinline__ void cp16(uint32_t dst, const void* src) {
    asm volatile("cp.async.cg.shared.global [%0], [%1], 16;" :: "r"(dst), "l"(src));
}

#define CP_COMMIT() asm volatile("cp.async.commit_group;" ::: "memory")
#define CP_WAIT2()  asm volatile("cp.async.wait_group 2;" ::: "memory")

#define MMA_TF32(c0,c1,c2,c3,a0,a1,a2,a3,b0,b1)                          \
    asm volatile(                                                        \
        "mma.sync.aligned.m16n8k8.row.col.f32.tf32.tf32.f32 "            \
        "{%0,%1,%2,%3}, {%4,%5,%6,%7}, {%8,%9}, {%0,%1,%2,%3};"          \
        : "+f"(c0), "+f"(c1), "+f"(c2), "+f"(c3)                         \
        : "r"(a0), "r"(a1), "r"(a2), "r"(a3), "r"(b0), "r"(b1))

// ---------------- tf32 pre-round pass (memory-bound) ----------------
__global__ void round_tf32_kernel(const float* __restrict__ in,
                                  float* __restrict__ out, int n4) {
    int i = blockIdx.x * blockDim.x + threadIdx.x;
    if (i >= n4) return;
    float4 v = ((const float4*)in)[i];
    uint4 t;
    t.x = f32_to_tf32(v.x); t.y = f32_to_tf32(v.y);
    t.z = f32_to_tf32(v.z); t.w = f32_to_tf32(v.w);
    ((uint4*)out)[i] = t;
}

// ==================== tf32 mma.sync GEMM v5: cp.async 3-stage ====================
// CTA 256x128, 256 threads = 8 warps (4x2), warp tile 64x64, K-chunk 32.
// Inputs MUST be pre-rounded tf32 bit patterns.
#define G5_ASTR 36
#define G5_BSTR 132
#define G5_STG (256*G5_ASTR + 32*G5_BSTR)    // 13440 u32 per stage
#define G5_SMEM_BYTES (3 * G5_STG * 4)

__global__ void __launch_bounds__(256) mma_gemm_kernel(
    const float* __restrict__ A, const float* __restrict__ Bm,
    const float* __restrict__ bias, float* __restrict__ C,
    int M, int N, int K)
{
    extern __shared__ uint32_t gsm[];
    uint32_t sbase = smem_u32(gsm);

    int tid  = threadIdx.x;
    int lane = tid & 31;
    int w    = tid >> 5;
    int wr   = w >> 1;       // 0..3
    int wc   = w & 1;        // 0..1
    int grp  = lane >> 2;
    int tig  = lane & 3;
    int m0 = blockIdx.y * 256;
    int n0 = blockIdx.x * 128;

    // fixed per-thread load slots
    const int arb = tid >> 3;          // A row base (0..31), +i*32
    const int acc_ = (tid & 7) * 4;    // A col (elements)
    const int brb = tid >> 5;          // B row base (0..7), +i*8
    const int bcc = (tid & 31) * 4;    // B col (elements)
    const float* Abase = A + (size_t)(m0 + arb) * K + acc_;
    const float* Bbase = Bm + (size_t)brb * N + n0 + bcc;

    float acc[4][8][4];
#pragma unroll
    for (int mt = 0; mt < 4; mt++)
#pragma unroll
        for (int nt = 0; nt < 8; nt++)
#pragma unroll
            for (int i = 0; i < 4; i++) acc[mt][nt][i] = 0.f;

    const int nCh = K / 32;

    // prologue: issue chunks 0,1,2 into stages 0,1,2
#pragma unroll
    for (int st = 0; st < 3; st++) {
        uint32_t sA = sbase + st * G5_STG * 4;
        uint32_t sB = sA + 256 * G5_ASTR * 4;
#pragma unroll
        for (int i = 0; i < 8; i++)
            cp16(sA + (((arb + i * 32) * G5_ASTR + acc_) << 2),
                 Abase + (size_t)i * 32 * K + st * 32);
#pragma unroll
        for (int i = 0; i < 4; i++)
            cp16(sB + (((brb + i * 8) * G5_BSTR + bcc) << 2),
                 Bbase + (size_t)(st * 32 + i * 8) * N);
        CP_COMMIT();
    }

    int stage = 0;
    for (int kc = 0; kc < nCh; kc++) {
        CP_WAIT2();          // oldest group (chunk kc) complete
        __syncthreads();
        uint32_t* As = gsm + stage * G5_STG;
        uint32_t* Bs = As + 256 * G5_ASTR;

#pragma unroll
        for (int kk = 0; kk < 4; kk++) {
            uint32_t af[4][4], bf[8][2];
#pragma unroll
            for (int mt = 0; mt < 4; mt++) {
                int r = wr * 64 + mt * 16 + grp;
                int kb = kk * 8 + tig;
                af[mt][0] = As[r * G5_ASTR + kb];
                af[mt][1] = As[(r + 8) * G5_ASTR + kb];
                af[mt][2] = As[r * G5_ASTR + kb + 4];
                af[mt][3] = As[(r + 8) * G5_ASTR + kb + 4];
            }
#pragma unroll
            for (int nt = 0; nt < 8; nt++) {
                int cn = wc * 64 + nt * 8 + grp;
                bf[nt][0] = Bs[(kk * 8 + tig) * G5_BSTR + cn];
                bf[nt][1] = Bs[(kk * 8 + tig + 4) * G5_BSTR + cn];
            }
#pragma unroll
            for (int mt = 0; mt < 4; mt++)
#pragma unroll
                for (int nt = 0; nt < 8; nt++)
                    MMA_TF32(acc[mt][nt][0], acc[mt][nt][1], acc[mt][nt][2], acc[mt][nt][3],
                             af[mt][0], af[mt][1], af[mt][2], af[mt][3],
                             bf[nt][0], bf[nt][1]);
        }
        __syncthreads();     // all warps done reading this stage

        int kn = kc + 3;
        if (kn < nCh) {
            uint32_t sA = sbase + stage * G5_STG * 4;
            uint32_t sB = sA + 256 * G5_ASTR * 4;
#pragma unroll
            for (int i = 0; i < 8; i++)
                cp16(sA + (((arb + i * 32) * G5_ASTR + acc_) << 2),
                     Abase + (size_t)i * 32 * K + kn * 32);
#pragma unroll
            for (int i = 0; i < 4; i++)
                cp16(sB + (((brb + i * 8) * G5_BSTR + bcc) << 2),
                     Bbase + (size_t)(kn * 32 + i * 8) * N);
        }
        CP_COMMIT();         // empty group near the tail is fine
        stage = (stage == 2) ? 0 : stage + 1;
    }

#pragma unroll
    for (int mt = 0; mt < 4; mt++) {
        int r0 = m0 + wr * 64 + mt * 16 + grp;
#pragma unroll
        for (int nt = 0; nt < 8; nt++) {
            int cn = n0 + wc * 64 + nt * 8 + tig * 2;
            float b0 = bias[cn], b1 = bias[cn + 1];
            float2 v0 = make_float2(acc[mt][nt][0] + b0, acc[mt][nt][1] + b1);
            float2 v1 = make_float2(acc[mt][nt][2] + b0, acc[mt][nt][3] + b1);
            *(float2*)(C + (size_t)r0 * N + cn) = v0;
            *(float2*)(C + (size_t)(r0 + 8) * N + cn) = v1;
        }
    }
}

// ---------------- RoPE tables ----------------
__global__ void rope_table_kernel() {
    int idx = blockIdx.x * blockDim.x + threadIdx.x;
    if (idx >= SS * 64) return;
    int t = idx >> 6;
    int j = idx & 63;
    double theta = (double)t * pow(10000.0, -(double)j / 64.0);
    g_cos[idx] = (float)cos(theta);
    g_sin[idx] = (float)sin(theta);
}

// ---------------- RoPE + split + transpose, emit tf32-rounded ----------------
__global__ void rope_split_kernel() {
    int idx = blockIdx.x * blockDim.x + threadIdx.x;
    if (idx >= BB * HH * SS * 64) return;
    int j = idx & 63;
    int s = (idx >> 6) & (SS - 1);
    int h = (idx >> 17) & (HH - 1);
    int b = idx >> 21;

    const float* qrow = g_qkv + (size_t)(b * SS + s) * ND3 + h * DHH;
    const float* krow = qrow + DD;
    const float* vrow = qrow + 2 * DD;
    float c  = g_cos[s * 64 + j];
    float sn = g_sin[s * 64 + j];
    size_t o = ((size_t)(b * HH + h) * SS + s) * DHH;

    const float qscale = 0.088388347648318447f;  // 1/sqrt(128)

    float u0 = qrow[j], u1 = qrow[j + 64], ue = qrow[2 * j], uo = qrow[2 * j + 1];
    ((uint32_t*)g_q)[o + j]      = f32_to_tf32((u0 * c + uo * sn) * qscale);
    ((uint32_t*)g_q)[o + j + 64] = f32_to_tf32((u1 * c - ue * sn) * qscale);

    u0 = krow[j]; u1 = krow[j + 64]; ue = krow[2 * j]; uo = krow[2 * j + 1];
    ((uint32_t*)g_k)[o + j]      = f32_to_tf32(u0 * c + uo * sn);
    ((uint32_t*)g_k)[o + j + 64] = f32_to_tf32(u1 * c - ue * sn);

    ((uint32_t*)g_v)[o + j]      = f32_to_tf32(vrow[j]);
    ((uint32_t*)g_v)[o + j + 64] = f32_to_tf32(vrow[j + 64]);
}

// ==================== flash attention v6: R10 + pre-rounded inputs ====================
#define A4_QSTR 132
#define A4_KSTR 132
#define A4_VSTR 136
#define A4_PSTR 72
#define A4_RED  (128*A4_QSTR + 64*A4_KSTR + 64*A4_VSTR + 128*A4_PSTR)
#define A4_SMEM_U32 (A4_RED + 512)
#define A4_SMEM_BYTES (A4_SMEM_U32 * 4)

__global__ void __launch_bounds__(256, 1) attn_mma_kernel() {
    extern __shared__ uint32_t sm4[];
    uint32_t* Qs = sm4;                          // [128][132] tf32
    uint32_t* Ks = Qs + 128 * A4_QSTR;           // [64][132]  tf32
    uint32_t* Vs = Ks + 64 * A4_KSTR;            // [64][136]  tf32
    uint32_t* Ps = Vs + 64 * A4_VSTR;            // [128][72]  tf32
    float* redmax = (float*)(sm4 + A4_RED);      // [2][128]
    float* redsum = redmax + 256;                // [2][128]

    int tid  = threadIdx.x;
    int lane = tid & 31;
    int w    = tid >> 5;
    int g    = w & 3;
    int hf   = w >> 2;
    int grp  = lane >> 2;
    int tig  = lane & 3;

    int bh = blockIdx.y;
    int b = bh >> 4, h = bh & 15;
    int q0 = blockIdx.x * 128;

    const uint32_t* Qg = (const uint32_t*)g_q + (size_t)bh * SS * DHH;
    const uint32_t* Kg = (const uint32_t*)g_k + (size_t)bh * SS * DHH;
    const uint32_t* Vg = (const uint32_t*)g_v + (size_t)bh * SS * DHH;

    int ldr[8], ldc[8];
#pragma unroll
    for (int i = 0; i < 8; i++) {
        int flat = tid + i * 256;
        ldr[i] = flat >> 5;
        ldc[i] = (flat & 31) * 4;
    }

    // load Q tile (already tf32-rounded)
#pragma unroll
    for (int i = 0; i < 16; i++) {
        int flat = tid + i * 256;
        int r = flat >> 5, c = (flat & 31) * 4;
        uint4 q4 = *(const uint4*)(Qg + (size_t)(q0 + r) * DHH + c);
        *(uint4*)&Qs[r * A4_QSTR + c] = q4;
    }

    // prefetch K/V tile 0
    uint4 kpf[8], vpf[8];
#pragma unroll
    for (int i = 0; i < 8; i++) {
        kpf[i] = *(const uint4*)(Kg + (size_t)ldr[i] * DHH + ldc[i]);
        vpf[i] = *(const uint4*)(Vg + (size_t)ldr[i] * DHH + ldc[i]);
    }

    int r0 = g * 32 + grp;
    float o[2][8][4];
#pragma unroll
    for (int mt = 0; mt < 2; mt++)
#pragma unroll
        for (int nt = 0; nt < 8; nt++)
#pragma unroll
            for (int i = 0; i < 4; i++) o[mt][nt][i] = 0.f;
    float m[4] = {-1e30f, -1e30f, -1e30f, -1e30f};
    float l[4] = {0.f, 0.f, 0.f, 0.f};

    const int NKT = SS / 64;
    for (int kt = 0; kt < NKT; kt++) {
        __syncthreads();
#pragma unroll
        for (int i = 0; i < 8; i++) {
            *(uint4*)&Ks[ldr[i] * A4_KSTR + ldc[i]] = kpf[i];
            *(uint4*)&Vs[ldr[i] * A4_VSTR + ldc[i]] = vpf[i];
        }
        __syncthreads();

        {
            int ktn = (kt + 1 < NKT) ? kt + 1 : kt;
            const uint32_t* Kn = Kg + (size_t)(ktn * 64) * DHH;
            const uint32_t* Vn = Vg + (size_t)(ktn * 64) * DHH;
#pragma unroll
            for (int i = 0; i < 8; i++) {
                kpf[i] = *(const uint4*)(Kn + (size_t)ldr[i] * DHH + ldc[i]);
                vpf[i] = *(const uint4*)(Vn + (size_t)ldr[i] * DHH + ldc[i]);
            }
        }

        float s[2][4][4];
#pragma unroll
        for (int mt = 0; mt < 2; mt++)
#pragma unroll
            for (int nt = 0; nt < 4; nt++)
#pragma unroll
                for (int i = 0; i < 4; i++) s[mt][nt][i] = 0.f;

#pragma unroll
        for (int ks = 0; ks < 16; ks++) {
            uint32_t af[2][4];
#pragma unroll
            for (int mt = 0; mt < 2; mt++) {
                int rr = r0 + mt * 16;
                af[mt][0] = Qs[rr * A4_QSTR + ks * 8 + tig];
                af[mt][1] = Qs[(rr + 8) * A4_QSTR + ks * 8 + tig];
                af[mt][2] = Qs[rr * A4_QSTR + ks * 8 + tig + 4];
                af[mt][3] = Qs[(rr + 8) * A4_QSTR + ks * 8 + tig + 4];
            }
#pragma unroll
            for (int nt = 0; nt < 4; nt++) {
                int kr = hf * 32 + nt * 8 + grp;
                uint32_t b0 = Ks[kr * A4_KSTR + ks * 8 + tig];
                uint32_t b1 = Ks[kr * A4_KSTR + ks * 8 + tig + 4];
#pragma unroll
                for (int mt = 0; mt < 2; mt++)
                    MMA_TF32(s[mt][nt][0], s[mt][nt][1], s[mt][nt][2], s[mt][nt][3],
                             af[mt][0], af[mt][1], af[mt][2], af[mt][3], b0, b1);
            }
        }

        float mx[4] = {-1e30f, -1e30f, -1e30f, -1e30f};
#pragma unroll
        for (int mt = 0; mt < 2; mt++)
#pragma unroll
            for (int nt = 0; nt < 4; nt++) {
                mx[2*mt]   = fmaxf(mx[2*mt],   fmaxf(s[mt][nt][0], s[mt][nt][1]));
                mx[2*mt+1] = fmaxf(mx[2*mt+1], fmaxf(s[mt][nt][2], s[mt][nt][3]));
            }
#pragma unroll
        for (int off = 1; off <= 2; off <<= 1)
#pragma unroll
            for (int sl = 0; sl < 4; sl++)
                mx[sl] = fmaxf(mx[sl], __shfl_xor_sync(0xffffffffu, mx[sl], off));
        if (tig == 0) {
#pragma unroll
            for (int sl = 0; sl < 4; sl++)
                redmax[hf * 128 + r0 + sl * 8] = mx[sl];
        }
        __syncthreads();
        float nm[4], sc[4];
#pragma unroll
        for (int sl = 0; sl < 4; sl++) {
            int rr = r0 + sl * 8;
            nm[sl] = fmaxf(m[sl], fmaxf(redmax[rr], redmax[128 + rr]));
            sc[sl] = __expf(m[sl] - nm[sl]);
        }

        float ps[4] = {0.f, 0.f, 0.f, 0.f};
#pragma unroll
        for (int mt = 0; mt < 2; mt++)
#pragma unroll
            for (int nt = 0; nt < 4; nt++) {
                float p0 = __expf(s[mt][nt][0] - nm[2*mt]);
                float p1 = __expf(s[mt][nt][1] - nm[2*mt]);
                float p2 = __expf(s[mt][nt][2] - nm[2*mt+1]);
                float p3 = __expf(s[mt][nt][3] - nm[2*mt+1]);
                ps[2*mt]   += p0 + p1;
                ps[2*mt+1] += p2 + p3;
                int pc = hf * 32 + nt * 8 + 2 * tig;
                int rr = r0 + mt * 16;
                uint2 t0 = make_uint2(f32_to_tf32(p0), f32_to_tf32(p1));
                uint2 t1 = make_uint2(f32_to_tf32(p2), f32_to_tf32(p3));
                *(uint2*)&Ps[rr * A4_PSTR + pc] = t0;
                *(uint2*)&Ps[(rr + 8) * A4_PSTR + pc] = t1;
            }
#pragma unroll
        for (int off = 1; off <= 2; off <<= 1)
#pragma unroll
            for (int sl = 0; sl < 4; sl++)
                ps[sl] += __shfl_xor_sync(0xffffffffu, ps[sl], off);
        if (tig == 0) {
#pragma unroll
            for (int sl = 0; sl < 4; sl++)
                redsum[hf * 128 + r0 + sl * 8] = ps[sl];
        }
        __syncthreads();
#pragma unroll
        for (int sl = 0; sl < 4; sl++) {
            int rr = r0 + sl * 8;
            l[sl] = l[sl] * sc[sl] + redsum[rr] + redsum[128 + rr];
            m[sl] = nm[sl];
        }
#pragma unroll
        for (int mt = 0; mt < 2; mt++)
#pragma unroll
            for (int nt = 0; nt < 8; nt++) {
                o[mt][nt][0] *= sc[2*mt]; o[mt][nt][1] *= sc[2*mt];
                o[mt][nt][2] *= sc[2*mt+1]; o[mt][nt][3] *= sc[2*mt+1];
            }

#pragma unroll
        for (int ks = 0; ks < 8; ks++) {
            uint32_t af[2][4];
#pragma unroll
            for (int mt = 0; mt < 2; mt++) {
                int rr = r0 + mt * 16;
                af[mt][0] = Ps[rr * A4_PSTR + ks * 8 + tig];
                af[mt][1] = Ps[(rr + 8) * A4_PSTR + ks * 8 + tig];
                af[mt][2] = Ps[rr * A4_PSTR + ks * 8 + tig + 4];
                af[mt][3] = Ps[(rr + 8) * A4_PSTR + ks * 8 + tig + 4];
            }
#pragma unroll
            for (int nt = 0; nt < 8; nt++) {
                int vc = hf * 64 + nt * 8 + grp;
                uint32_t b0 = Vs[(ks * 8 + tig) * A4_VSTR + vc];
                uint32_t b1 = Vs[(ks * 8 + tig + 4) * A4_VSTR + vc];
#pragma unroll
                for (int mt = 0; mt < 2; mt++)
                    MMA_TF32(o[mt][nt][0], o[mt][nt][1], o[mt][nt][2], o[mt][nt][3],
                             af[mt][0], af[mt][1], af[mt][2], af[mt][3], b0, b1);
            }
        }
    }

    // epilogue: divide by l, write tf32-rounded ctx (out-proj consumes it as A)
    float inv[4];
#pragma unroll
    for (int sl = 0; sl < 4; sl++) inv[sl] = 1.f / l[sl];
#pragma unroll
    for (int mt = 0; mt < 2; mt++) {
        int rrg0 = q0 + r0 + mt * 16;
        uint32_t* dst0 = (uint32_t*)g_ctx + (size_t)(b * SS + rrg0) * DD + h * DHH;
        uint32_t* dst1 = (uint32_t*)g_ctx + (size_t)(b * SS + rrg0 + 8) * DD + h * DHH;
#pragma unroll
        for (int nt = 0; nt < 8; nt++) {
            int cn = hf * 64 + nt * 8 + 2 * tig;
            uint2 t0 = make_uint2(f32_to_tf32(o[mt][nt][0] * inv[2*mt]),
                                  f32_to_tf32(o[mt][nt][1] * inv[2*mt]));
            uint2 t1 = make_uint2(f32_to_tf32(o[mt][nt][2] * inv[2*mt+1]),
                                  f32_to_tf32(o[mt][nt][3] * inv[2*mt+1]));
            *(uint2*)(dst0 + cn) = t0;
            *(uint2*)(dst1 + cn) = t1;
        }
    }
}

// ---------------- launch ----------------
extern "C" void kernel_launch(void* const* d_in, const int* in_sizes, int n_in,
                              void* d_out, int out_size) {
    const float* x    = (const float*)d_in[0];
    const float* Wqkv = (const float*)d_in[1];
    const float* bqkv = (const float*)d_in[2];
    const float* Wo   = (const float*)d_in[3];
    const float* bo   = (const float*)d_in[4];
    float* out = (float*)d_out;

    void *qkvPtr, *ctxPtr, *xrPtr, *wqkvrPtr, *worPtr;
    cudaGetSymbolAddress(&qkvPtr, g_qkv);
    cudaGetSymbolAddress(&ctxPtr, g_ctx);
    cudaGetSymbolAddress(&xrPtr, g_xr);
    cudaGetSymbolAddress(&wqkvrPtr, g_wqkvr);
    cudaGetSymbolAddress(&worPtr, g_wor);

    cudaFuncSetAttribute(attn_mma_kernel,
                         cudaFuncAttributeMaxDynamicSharedMemorySize,
                         A4_SMEM_BYTES);
    cudaFuncSetAttribute(mma_gemm_kernel,
                         cudaFuncAttributeMaxDynamicSharedMemorySize,
                         G5_SMEM_BYTES);

    // 0) pre-round inputs to tf32 (memory-bound)
    {
        int n4x = (BB * SS * DD) / 4;
        round_tf32_kernel<<<(n4x + 255) / 256, 256>>>(x, (float*)xrPtr, n4x);
        int n4w = (DD * ND3) / 4;
        round_tf32_kernel<<<(n4w + 255) / 256, 256>>>(Wqkv, (float*)wqkvrPtr, n4w);
        int n4o = (DD * DD) / 4;
        round_tf32_kernel<<<(n4o + 255) / 256, 256>>>(Wo, (float*)worPtr, n4o);
    }

    // 1) RoPE tables
    rope_table_kernel<<<(SS * 64 + 255) / 256, 256>>>();

    // 2) QKV GEMM (cp.async 3-stage tf32 mma)
    mma_gemm_kernel<<<dim3(ND3 / 128, (BB * SS) / 256), 256, G5_SMEM_BYTES>>>(
        (const float*)xrPtr, (const float*)wqkvrPtr, bqkv, (float*)qkvPtr,
        BB * SS, ND3, DD);

    // 3) RoPE + split/transpose, emit tf32-rounded q/k/v
    rope_split_kernel<<<(BB * HH * SS * 64) / 256, 256>>>();

    // 4) flash attention v6 -> g_ctx (tf32-rounded)
    attn_mma_kernel<<<dim3(SS / 128, BB * HH), 256, A4_SMEM_BYTES>>>();

    // 5) output projection (cp.async 3-stage tf32 mma)
    mma_gemm_kernel<<<dim3(DD / 128, (BB * SS) / 256), 256, G5_SMEM_BYTES>>>(
        (const float*)ctxPtr, (const float*)worPtr, bo, out, BB * SS, DD, DD);
}

// round 13
// speedup vs baseline: 2.1077x; 1.6304x over previous
#include <cuda_runtime.h>
#include <cuda_fp16.h>
#include <math.h>
#include <stdint.h>

#define BB 2
#define SS 2048
#define DD 2048
#define HH 16
#define DHH 128
#define ND3 (3*DD)

// ---------------- scratch (static device globals; no allocation) ----------------
__device__ float    g_qkv[(size_t)BB*SS*ND3];          // [B,S,3D] fp32
__device__ uint32_t g_qh [(size_t)BB*HH*SS*DHH/2];     // [B,H,S,DH] fp16 pairs, scaled
__device__ uint32_t g_kh [(size_t)BB*HH*SS*DHH/2];     // fp16 pairs
__device__ uint32_t g_vT [(size_t)BB*HH*DHH*SS/2];     // [B,H,DH,S] fp16 pairs (transposed)
__device__ uint32_t g_ctxh[(size_t)BB*SS*DD/2];        // [B,S,H*DH] fp16 pairs
__device__ uint32_t g_xh [(size_t)BB*SS*DD/2];         // x fp16 pairs [M][K/2]
__device__ uint32_t g_wqkvh[(size_t)ND3*DD/2];         // Wqkv^T fp16 [6144][2048/2]
__device__ uint32_t g_woh  [(size_t)DD*DD/2];          // Wo^T fp16 [2048][1024]
__device__ float g_cos[SS*64];
__device__ float g_sin[SS*64];

__device__ __forceinline__ uint32_t pack_h2(float lo, float hi) {
    __half2 h = __floats2half2_rn(lo, hi);
    return *(uint32_t*)&h;
}

__device__ __forceinline__ uint32_t smem_u32(const void* p) {
    uint32_t a;
    asm("{ .reg .u64 t; cvta.to.shared.u64 t, %1; cvt.u32.u64 %0, t; }" : "=r"(a) : "l"(p));
    return a;
}

__device__ __forceinline__ void cp16(uint32_t dst, const void* src) {
    asm volatile("cp.async.cg.shared.global [%0], [%1], 16;" :: "r"(dst), "l"(src));
}
#define CP_COMMIT() asm volatile("cp.async.commit_group;" ::: "memory")
#define CP_WAIT2()  asm volatile("cp.async.wait_group 2;" ::: "memory")

// fp16 mma: D(fp32) += A(fp16) B(fp16), 16x8x16
#define MMA_F16(c0,c1,c2,c3,a0,a1,a2,a3,b0,b1)                           \
    asm volatile(                                                        \
        "mma.sync.aligned.m16n8k16.row.col.f32.f16.f16.f32 "             \
        "{%0,%1,%2,%3}, {%4,%5,%6,%7}, {%8,%9}, {%0,%1,%2,%3};"          \
        : "+f"(c0), "+f"(c1), "+f"(c2), "+f"(c3)                         \
        : "r"(a0), "r"(a1), "r"(a2), "r"(a3), "r"(b0), "r"(b1))

// ---------------- pre-pass: fp32 -> fp16 (x) ----------------
__global__ void x2h_kernel(const float* __restrict__ in,
                           uint32_t* __restrict__ out, int n4) {
    int i = blockIdx.x * blockDim.x + threadIdx.x;
    if (i >= n4) return;
    float4 v = ((const float4*)in)[i];
    uint2 t;
    t.x = pack_h2(v.x, v.y);
    t.y = pack_h2(v.z, v.w);
    ((uint2*)out)[i] = t;
}

// ---------------- pre-pass: transpose + convert W [K,N] -> [N,K] fp16 ----------------
__global__ void wT2h_kernel(const float* __restrict__ in,
                            __half* __restrict__ out, int K, int N) {
    __shared__ float t[32][33];
    int n0 = blockIdx.x * 32, k0 = blockIdx.y * 32;
    int tx = threadIdx.x, ty = threadIdx.y;
#pragma unroll
    for (int i = 0; i < 32; i += 8)
        t[ty + i][tx] = in[(size_t)(k0 + ty + i) * N + n0 + tx];
    __syncthreads();
#pragma unroll
    for (int i = 0; i < 32; i += 8)
        out[(size_t)(n0 + ty + i) * K + k0 + tx] = __float2half_rn(t[tx][ty + i]);
}

// ---------------- pre-pass: V slice of qkv -> g_vT [B,H,DH,S] fp16 ----------------
__global__ void vT_kernel() {
    __shared__ float t[32][33];
    int bh = blockIdx.z;
    int b = bh >> 4, h = bh & 15;
    int d0 = blockIdx.y * 32;
    int s0 = blockIdx.x * 32;
    int tx = threadIdx.x, ty = threadIdx.y;
    const float* src = g_qkv + (size_t)b * SS * ND3 + 2 * DD + h * DHH;
#pragma unroll
    for (int i = 0; i < 32; i += 8)
        t[ty + i][tx] = src[(size_t)(s0 + ty + i) * ND3 + d0 + tx];
    __syncthreads();
    __half* dst = (__half*)g_vT + (size_t)bh * DHH * SS;
#pragma unroll
    for (int i = 0; i < 32; i += 8)
        dst[(size_t)(d0 + ty + i) * SS + s0 + tx] = __float2half_rn(t[tx][ty + i]);
}

// ==================== fp16 mma GEMM: C = A@B + bias ====================
// A [M][K/2] fp16 pairs, Bt [N][K/2] fp16 pairs (B pre-transposed).
// CTA 256x128, 8 warps (4x2), warp tile 64x64, K-chunk 32 (16 u32), 3-stage cp.async.
#define GH_ASTR 20
#define GH_BSTR 20
#define GH_STG  (256*GH_ASTR + 128*GH_BSTR)   // 7680 u32
#define GH_SMEM_BYTES (3 * GH_STG * 4)        // 92160

__global__ void __launch_bounds__(256) gemm_h_kernel(
    const uint32_t* __restrict__ A, const uint32_t* __restrict__ Bt,
    const float* __restrict__ bias, float* __restrict__ C,
    int M, int N, int K)
{
    extern __shared__ uint32_t gsm[];
    uint32_t sbase = smem_u32(gsm);

    int tid  = threadIdx.x;
    int lane = tid & 31;
    int w    = tid >> 5;
    int wr   = w >> 1;       // 0..3
    int wc   = w & 1;        // 0..1
    int grp  = lane >> 2;
    int tig  = lane & 3;
    int m0 = blockIdx.y * 256;
    int n0 = blockIdx.x * 128;
    const int K2 = K >> 1;

    const int lrow = tid >> 2;          // 0..63
    const int lc4  = (tid & 3) * 4;     // 0,4,8,12
    const uint32_t* Abase = A + (size_t)(m0 + lrow) * K2 + lc4;
    const uint32_t* Bbase = Bt + (size_t)(n0 + lrow) * K2 + lc4;

    float acc[4][8][4];
#pragma unroll
    for (int mt = 0; mt < 4; mt++)
#pragma unroll
        for (int nt = 0; nt < 8; nt++)
#pragma unroll
            for (int i = 0; i < 4; i++) acc[mt][nt][i] = 0.f;

    const int nCh = K / 32;

    // prologue: chunks 0,1,2 -> stages 0,1,2
#pragma unroll
    for (int st = 0; st < 3; st++) {
        uint32_t sA = sbase + st * GH_STG * 4;
        uint32_t sB = sA + 256 * GH_ASTR * 4;
#pragma unroll
        for (int i = 0; i < 4; i++)
            cp16(sA + (((lrow + i * 64) * GH_ASTR + lc4) << 2),
                 Abase + (size_t)i * 64 * K2 + st * 16);
#pragma unroll
        for (int i = 0; i < 2; i++)
            cp16(sB + (((lrow + i * 64) * GH_BSTR + lc4) << 2),
                 Bbase + (size_t)i * 64 * K2 + st * 16);
        CP_COMMIT();
    }

    int stage = 0;
    for (int kc = 0; kc < nCh; kc++) {
        CP_WAIT2();
        __syncthreads();
        uint32_t* As = gsm + stage * GH_STG;
        uint32_t* Bs = As + 256 * GH_ASTR;

#pragma unroll
        for (int kk = 0; kk < 2; kk++) {
            int kb = kk * 8 + tig;
            uint32_t af[4][4], bf[8][2];
#pragma unroll
            for (int mt = 0; mt < 4; mt++) {
                int r = wr * 64 + mt * 16 + grp;
                af[mt][0] = As[r * GH_ASTR + kb];
                af[mt][1] = As[(r + 8) * GH_ASTR + kb];
                af[mt][2] = As[r * GH_ASTR + kb + 4];
                af[mt][3] = As[(r + 8) * GH_ASTR + kb + 4];
            }
#pragma unroll
            for (int nt = 0; nt < 8; nt++) {
                int cn = wc * 64 + nt * 8 + grp;
                bf[nt][0] = Bs[cn * GH_BSTR + kb];
                bf[nt][1] = Bs[cn * GH_BSTR + kb + 4];
            }
#pragma unroll
            for (int mt = 0; mt < 4; mt++)
#pragma unroll
                for (int nt = 0; nt < 8; nt++)
                    MMA_F16(acc[mt][nt][0], acc[mt][nt][1], acc[mt][nt][2], acc[mt][nt][3],
                            af[mt][0], af[mt][1], af[mt][2], af[mt][3],
                            bf[nt][0], bf[nt][1]);
        }
        __syncthreads();

        int kn = kc + 3;
        if (kn < nCh) {
            uint32_t sA = sbase + stage * GH_STG * 4;
            uint32_t sB = sA + 256 * GH_ASTR * 4;
#pragma unroll
            for (int i = 0; i < 4; i++)
                cp16(sA + (((lrow + i * 64) * GH_ASTR + lc4) << 2),
                     Abase + (size_t)i * 64 * K2 + kn * 16);
#pragma unroll
            for (int i = 0; i < 2; i++)
                cp16(sB + (((lrow + i * 64) * GH_BSTR + lc4) << 2),
                     Bbase + (size_t)i * 64 * K2 + kn * 16);
        }
        CP_COMMIT();
        stage = (stage == 2) ? 0 : stage + 1;
    }

#pragma unroll
    for (int mt = 0; mt < 4; mt++) {
        int r0 = m0 + wr * 64 + mt * 16 + grp;
#pragma unroll
        for (int nt = 0; nt < 8; nt++) {
            int cn = n0 + wc * 64 + nt * 8 + tig * 2;
            float b0 = bias[cn], b1 = bias[cn + 1];
            float2 v0 = make_float2(acc[mt][nt][0] + b0, acc[mt][nt][1] + b1);
            float2 v1 = make_float2(acc[mt][nt][2] + b0, acc[mt][nt][3] + b1);
            *(float2*)(C + (size_t)r0 * N + cn) = v0;
            *(float2*)(C + (size_t)(r0 + 8) * N + cn) = v1;
        }
    }
}

// ---------------- RoPE tables ----------------
__global__ void rope_table_kernel() {
    int idx = blockIdx.x * blockDim.x + threadIdx.x;
    if (idx >= SS * 64) return;
    int t = idx >> 6;
    int j = idx & 63;
    double theta = (double)t * pow(10000.0, -(double)j / 64.0);
    g_cos[idx] = (float)cos(theta);
    g_sin[idx] = (float)sin(theta);
}

// ---------------- RoPE + split, emit fp16 pairs; thread j owns d pair (2j, 2j+1) ----------------
__global__ void rope_split_kernel() {
    int idx = blockIdx.x * blockDim.x + threadIdx.x;
    if (idx >= BB * HH * SS * 64) return;
    int j = idx & 63;                 // pair index, d = 2j, 2j+1
    int s = (idx >> 6) & (SS - 1);
    int h = (idx >> 17) & (HH - 1);
    int b = idx >> 21;

    const float* qrow = g_qkv + (size_t)(b * SS + s) * ND3 + h * DHH;
    const float* krow = qrow + DD;
    size_t o = ((size_t)(b * HH + h) * SS + s) * 64;   // u32 units

    const float qscale = 0.088388347648318447f;  // 1/sqrt(128)
    const float* ctab = g_cos + s * 64;
    const float* stab = g_sin + s * 64;

    float q0, q1, k0, k1;
    if (j < 32) {
        int d0 = 2 * j, d1 = 2 * j + 1;
        float c0 = ctab[d0], s0 = stab[d0], c1 = ctab[d1], s1 = stab[d1];
        q0 = qrow[d0] * c0 + qrow[2 * d0 + 1] * s0;
        q1 = qrow[d1] * c1 + qrow[2 * d1 + 1] * s1;
        k0 = krow[d0] * c0 + krow[2 * d0 + 1] * s0;
        k1 = krow[d1] * c1 + krow[2 * d1 + 1] * s1;
    } else {
        int d0 = 2 * j, d1 = 2 * j + 1;
        int e0 = d0 - 64, e1 = d1 - 64;
        float c0 = ctab[e0], s0 = stab[e0], c1 = ctab[e1], s1 = stab[e1];
        q0 = qrow[d0] * c0 - qrow[2 * e0] * s0;
        q1 = qrow[d1] * c1 - qrow[2 * e1] * s1;
        k0 = krow[d0] * c0 - krow[2 * e0] * s0;
        k1 = krow[d1] * c1 - krow[2 * e1] * s1;
    }
    g_qh[o + j] = pack_h2(q0 * qscale, q1 * qscale);
    g_kh[o + j] = pack_h2(k0, k1);
}

// ==================== flash attention fp16 m16n8k16 ====================
// BM=128 q-rows, BN=64 keys/step, 256 threads = 8 warps (4 row-groups x 2 halves).
// Strides (u32): Q 68, K 68, VT 36, P 36 -> all ≡4 mod 32, conflict-free fragments.
#define AH_QSTR 68
#define AH_KSTR 68
#define AH_VSTR 36
#define AH_PSTR 36
#define AH_RED  (128*AH_QSTR + 64*AH_KSTR + 128*AH_VSTR + 128*AH_PSTR)
#define AH_SMEM_U32 (AH_RED + 512)
#define AH_SMEM_BYTES (AH_SMEM_U32 * 4)

__global__ void __launch_bounds__(256, 1) attn_mma_kernel() {
    extern __shared__ uint32_t sm4[];
    uint32_t* Qs  = sm4;                       // [128][68]  fp16 pairs (d)
    uint32_t* Ks  = Qs + 128 * AH_QSTR;        // [64][68]   fp16 pairs (d)
    uint32_t* VsT = Ks + 64 * AH_KSTR;         // [128 d][36] fp16 pairs (keys)
    uint32_t* Ps  = VsT + 128 * AH_VSTR;       // [128][36]  fp16 pairs (keys)
    float* redmax = (float*)(sm4 + AH_RED);    // [2][128]
    float* redsum = redmax + 256;              // [2][128]

    int tid  = threadIdx.x;
    int lane = tid & 31;
    int w    = tid >> 5;
    int g    = w & 3;
    int hf   = w >> 2;
    int grp  = lane >> 2;
    int tig  = lane & 3;

    int bh = blockIdx.y;
    int b = bh >> 4, h = bh & 15;
    int q0 = blockIdx.x * 128;

    const uint32_t* Qg = g_qh + (size_t)bh * SS * 64;
    const uint32_t* Kg = g_kh + (size_t)bh * SS * 64;
    const uint32_t* Vg = g_vT + (size_t)bh * DHH * (SS / 2);

    // load Q tile: 128 rows x 64 u32
#pragma unroll
    for (int i = 0; i < 8; i++) {
        int flat = tid + i * 256;
        int r = flat >> 4, c = (flat & 15) * 4;
        uint4 q4 = *(const uint4*)(Qg + (size_t)(q0 + r) * 64 + c);
        *(uint4*)&Qs[r * AH_QSTR + c] = q4;
    }

    // prefetch slots
    int krr[4], krc[4], vrr[4], vrc[4];
#pragma unroll
    for (int i = 0; i < 4; i++) {
        int flat = tid + i * 256;
        krr[i] = flat >> 4;  krc[i] = (flat & 15) * 4;   // K: [64][64]
        vrr[i] = flat >> 3;  vrc[i] = (flat & 7) * 4;    // VT: [128][32]
    }
    uint4 kpf[4], vpf[4];
#pragma unroll
    for (int i = 0; i < 4; i++) {
        kpf[i] = *(const uint4*)(Kg + (size_t)krr[i] * 64 + krc[i]);
        vpf[i] = *(const uint4*)(Vg + (size_t)vrr[i] * (SS / 2) + vrc[i]);
    }

    int r0 = g * 32 + grp;
    float o[2][8][4];
#pragma unroll
    for (int mt = 0; mt < 2; mt++)
#pragma unroll
        for (int nt = 0; nt < 8; nt++)
#pragma unroll
            for (int i = 0; i < 4; i++) o[mt][nt][i] = 0.f;
    float m[4] = {-1e30f, -1e30f, -1e30f, -1e30f};
    float l[4] = {0.f, 0.f, 0.f, 0.f};

    const int NKT = SS / 64;
    for (int kt = 0; kt < NKT; kt++) {
        __syncthreads();
#pragma unroll
        for (int i = 0; i < 4; i++) {
            *(uint4*)&Ks[krr[i] * AH_KSTR + krc[i]] = kpf[i];
            *(uint4*)&VsT[vrr[i] * AH_VSTR + vrc[i]] = vpf[i];
        }
        __syncthreads();

        {
            int ktn = (kt + 1 < NKT) ? kt + 1 : kt;
            const uint32_t* Kn = Kg + (size_t)(ktn * 64) * 64;
            const uint32_t* Vn = Vg + ktn * 32;
#pragma unroll
            for (int i = 0; i < 4; i++) {
                kpf[i] = *(const uint4*)(Kn + (size_t)krr[i] * 64 + krc[i]);
                vpf[i] = *(const uint4*)(Vn + (size_t)vrr[i] * (SS / 2) + vrc[i]);
            }
        }

        // S = Q K^T : warp tile 32 rows x 32 keys, K=128 -> 8 k16 steps
        float s[2][4][4];
#pragma unroll
        for (int mt = 0; mt < 2; mt++)
#pragma unroll
            for (int nt = 0; nt < 4; nt++)
#pragma unroll
                for (int i = 0; i < 4; i++) s[mt][nt][i] = 0.f;

#pragma unroll
        for (int ks = 0; ks < 8; ks++) {
            int kb = ks * 8 + tig;
            uint32_t af[2][4];
#pragma unroll
            for (int mt = 0; mt < 2; mt++) {
                int rr = r0 + mt * 16;
                af[mt][0] = Qs[rr * AH_QSTR + kb];
                af[mt][1] = Qs[(rr + 8) * AH_QSTR + kb];
                af[mt][2] = Qs[rr * AH_QSTR + kb + 4];
                af[mt][3] = Qs[(rr + 8) * AH_QSTR + kb + 4];
            }
#pragma unroll
            for (int nt = 0; nt < 4; nt++) {
                int kr = hf * 32 + nt * 8 + grp;
                uint32_t b0 = Ks[kr * AH_KSTR + kb];
                uint32_t b1 = Ks[kr * AH_KSTR + kb + 4];
#pragma unroll
                for (int mt = 0; mt < 2; mt++)
                    MMA_F16(s[mt][nt][0], s[mt][nt][1], s[mt][nt][2], s[mt][nt][3],
                            af[mt][0], af[mt][1], af[mt][2], af[mt][3], b0, b1);
            }
        }

        float mx[4] = {-1e30f, -1e30f, -1e30f, -1e30f};
#pragma unroll
        for (int mt = 0; mt < 2; mt++)
#pragma unroll
            for (int nt = 0; nt < 4; nt++) {
                mx[2*mt]   = fmaxf(mx[2*mt],   fmaxf(s[mt][nt][0], s[mt][nt][1]));
                mx[2*mt+1] = fmaxf(mx[2*mt+1], fmaxf(s[mt][nt][2], s[mt][nt][3]));
            }
#pragma unroll
        for (int off = 1; off <= 2; off <<= 1)
#pragma unroll
            for (int sl = 0; sl < 4; sl++)
                mx[sl] = fmaxf(mx[sl], __shfl_xor_sync(0xffffffffu, mx[sl], off));
        if (tig == 0) {
#pragma unroll
            for (int sl = 0; sl < 4; sl++)
                redmax[hf * 128 + r0 + sl * 8] = mx[sl];
        }
        __syncthreads();
        float nm[4], sc[4];
#pragma unroll
        for (int sl = 0; sl < 4; sl++) {
            int rr = r0 + sl * 8;
            nm[sl] = fmaxf(m[sl], fmaxf(redmax[rr], redmax[128 + rr]));
            sc[sl] = __expf(m[sl] - nm[sl]);
        }

        float ps[4] = {0.f, 0.f, 0.f, 0.f};
#pragma unroll
        for (int mt = 0; mt < 2; mt++)
#pragma unroll
            for (int nt = 0; nt < 4; nt++) {
                float p0 = __expf(s[mt][nt][0] - nm[2*mt]);
                float p1 = __expf(s[mt][nt][1] - nm[2*mt]);
                float p2 = __expf(s[mt][nt][2] - nm[2*mt+1]);
                float p3 = __expf(s[mt][nt][3] - nm[2*mt+1]);
                ps[2*mt]   += p0 + p1;
                ps[2*mt+1] += p2 + p3;
                int pc = hf * 16 + nt * 4 + tig;     // key pair index
                int rr = r0 + mt * 16;
                Ps[rr * AH_PSTR + pc]       = pack_h2(p0, p1);
                Ps[(rr + 8) * AH_PSTR + pc] = pack_h2(p2, p3);
            }
#pragma unroll
        for (int off = 1; off <= 2; off <<= 1)
#pragma unroll
            for (int sl = 0; sl < 4; sl++)
                ps[sl] += __shfl_xor_sync(0xffffffffu, ps[sl], off);
        if (tig == 0) {
#pragma unroll
            for (int sl = 0; sl < 4; sl++)
                redsum[hf * 128 + r0 + sl * 8] = ps[sl];
        }
        __syncthreads();
#pragma unroll
        for (int sl = 0; sl < 4; sl++) {
            int rr = r0 + sl * 8;
            l[sl] = l[sl] * sc[sl] + redsum[rr] + redsum[128 + rr];
            m[sl] = nm[sl];
        }
#pragma unroll
        for (int mt = 0; mt < 2; mt++)
#pragma unroll
            for (int nt = 0; nt < 8; nt++) {
                o[mt][nt][0] *= sc[2*mt]; o[mt][nt][1] *= sc[2*mt];
                o[mt][nt][2] *= sc[2*mt+1]; o[mt][nt][3] *= sc[2*mt+1];
            }

        // O += P V : warp tile 32 rows x 64 out cols, 64 keys -> 4 k16 steps
#pragma unroll
        for (int ksv = 0; ksv < 4; ksv++) {
            int kb = ksv * 8 + tig;
            uint32_t af[2][4];
#pragma unroll
            for (int mt = 0; mt < 2; mt++) {
                int rr = r0 + mt * 16;
                af[mt][0] = Ps[rr * AH_PSTR + kb];
                af[mt][1] = Ps[(rr + 8) * AH_PSTR + kb];
                af[mt][2] = Ps[rr * AH_PSTR + kb + 4];
                af[mt][3] = Ps[(rr + 8) * AH_PSTR + kb + 4];
            }
#pragma unroll
            for (int nt = 0; nt < 8; nt++) {
                int vc = hf * 64 + nt * 8 + grp;     // out d col
                uint32_t b0 = VsT[vc * AH_VSTR + kb];
                uint32_t b1 = VsT[vc * AH_VSTR + kb + 4];
#pragma unroll
                for (int mt = 0; mt < 2; mt++)
                    MMA_F16(o[mt][nt][0], o[mt][nt][1], o[mt][nt][2], o[mt][nt][3],
                            af[mt][0], af[mt][1], af[mt][2], af[mt][3], b0, b1);
            }
        }
    }

    // epilogue: divide by l, write fp16 pairs to g_ctxh
    float inv[4];
#pragma unroll
    for (int sl = 0; sl < 4; sl++) inv[sl] = 1.f / l[sl];
#pragma unroll
    for (int mt = 0; mt < 2; mt++) {
        int rrg0 = q0 + r0 + mt * 16;
        uint32_t* dst0 = g_ctxh + (size_t)(b * SS + rrg0) * (DD / 2) + h * 64;
        uint32_t* dst1 = g_ctxh + (size_t)(b * SS + rrg0 + 8) * (DD / 2) + h * 64;
#pragma unroll
        for (int nt = 0; nt < 8; nt++) {
            int pc = hf * 32 + nt * 4 + tig;   // pair index within head
            dst0[pc] = pack_h2(o[mt][nt][0] * inv[2*mt],   o[mt][nt][1] * inv[2*mt]);
            dst1[pc] = pack_h2(o[mt][nt][2] * inv[2*mt+1], o[mt][nt][3] * inv[2*mt+1]);
        }
    }
}

// ---------------- launch ----------------
extern "C" void kernel_launch(void* const* d_in, const int* in_sizes, int n_in,
                              void* d_out, int out_size) {
    const float* x    = (const float*)d_in[0];
    const float* Wqkv = (const float*)d_in[1];
    const float* bqkv = (const float*)d_in[2];
    const float* Wo   = (const float*)d_in[3];
    const float* bo   = (const float*)d_in[4];
    float* out = (float*)d_out;

    void *qkvPtr, *xhPtr, *wqkvhPtr, *wohPtr, *ctxhPtr;
    cudaGetSymbolAddress(&qkvPtr, g_qkv);
    cudaGetSymbolAddress(&xhPtr, g_xh);
    cudaGetSymbolAddress(&wqkvhPtr, g_wqkvh);
    cudaGetSymbolAddress(&wohPtr, g_woh);
    cudaGetSymbolAddress(&ctxhPtr, g_ctxh);

    cudaFuncSetAttribute(attn_mma_kernel,
                         cudaFuncAttributeMaxDynamicSharedMemorySize,
                         AH_SMEM_BYTES);
    cudaFuncSetAttribute(gemm_h_kernel,
                         cudaFuncAttributeMaxDynamicSharedMemorySize,
                         GH_SMEM_BYTES);

    // 0) convert x -> fp16; transpose+convert weights -> fp16 [N][K]
    {
        int n4x = (BB * SS * DD) / 4;
        x2h_kernel<<<(n4x + 255) / 256, 256>>>(x, (uint32_t*)xhPtr, n4x);
        wT2h_kernel<<<dim3(ND3 / 32, DD / 32), dim3(32, 8)>>>(
            Wqkv, (__half*)wqkvhPtr, DD, ND3);
        wT2h_kernel<<<dim3(DD / 32, DD / 32), dim3(32, 8)>>>(
            Wo, (__half*)wohPtr, DD, DD);
    }

    // 1) RoPE tables
    rope_table_kernel<<<(SS * 64 + 255) / 256, 256>>>();

    // 2) QKV GEMM (fp16 m16n8k16, cp.async 3-stage) -> g_qkv fp32
    gemm_h_kernel<<<dim3(ND3 / 128, (BB * SS) / 256), 256, GH_SMEM_BYTES>>>(
        (const uint32_t*)xhPtr, (const uint32_t*)wqkvhPtr, bqkv, (float*)qkvPtr,
        BB * SS, ND3, DD);

    // 3a) RoPE + split -> g_qh/g_kh fp16
    rope_split_kernel<<<(BB * HH * SS * 64) / 256, 256>>>();
    // 3b) V transpose -> g_vT fp16 [B,H,DH,S]
    vT_kernel<<<dim3(SS / 32, DHH / 32, BB * HH), dim3(32, 8)>>>();

    // 4) flash attention (fp16 m16n8k16) -> g_ctxh
    attn_mma_kernel<<<dim3(SS / 128, BB * HH), 256, AH_SMEM_BYTES>>>();

    // 5) output projection (fp16 m16n8k16) -> out fp32
    gemm_h_kernel<<<dim3(DD / 128, (BB * SS) / 256), 256, GH_SMEM_BYTES>>>(
        (const uint32_t*)ctxhPtr, (const uint32_t*)wohPtr, bo, out, BB * SS, DD, DD);
}

// round 14
// speedup vs baseline: 2.2536x; 1.0692x over previous
#include <cuda_runtime.h>
#include <cuda_fp16.h>
#include <math.h>
#include <stdint.h>

#define BB 2
#define SS 2048
#define DD 2048
#define HH 16
#define DHH 128
#define ND3 (3*DD)

// ---------------- scratch (static device globals; no allocation) ----------------
__device__ float    g_qkv[(size_t)BB*SS*ND3];          // [B,S,3D] fp32
__device__ uint32_t g_qh [(size_t)BB*HH*SS*DHH/2];     // [B,H,S,DH] fp16 pairs, scaled
__device__ uint32_t g_kh [(size_t)BB*HH*SS*DHH/2];     // fp16 pairs
__device__ uint32_t g_vT [(size_t)BB*HH*DHH*SS/2];     // [B,H,DH,S] fp16 pairs (transposed)
__device__ uint32_t g_ctxh[(size_t)BB*SS*DD/2];        // [B,S,H*DH] fp16 pairs
__device__ uint32_t g_xh [(size_t)BB*SS*DD/2];         // x fp16 pairs [M][K/2]
__device__ uint32_t g_wqkvh[(size_t)ND3*DD/2];         // Wqkv^T fp16 [6144][1024]
__device__ uint32_t g_woh  [(size_t)DD*DD/2];          // Wo^T fp16 [2048][1024]
__device__ float g_cos[SS*64];
__device__ float g_sin[SS*64];
__device__ float g_invf_f[64];

__device__ __forceinline__ uint32_t pack_h2(float lo, float hi) {
    __half2 h = __floats2half2_rn(lo, hi);
    return *(uint32_t*)&h;
}

__device__ __forceinline__ uint32_t smem_u32(const void* p) {
    uint32_t a;
    asm("{ .reg .u64 t; cvta.to.shared.u64 t, %1; cvt.u32.u64 %0, t; }" : "=r"(a) : "l"(p));
    return a;
}

__device__ __forceinline__ void cp16(uint32_t dst, const void* src) {
    asm volatile("cp.async.cg.shared.global [%0], [%1], 16;" :: "r"(dst), "l"(src));
}
#define CP_COMMIT() asm volatile("cp.async.commit_group;" ::: "memory")
#define CP_WAIT2()  asm volatile("cp.async.wait_group 2;" ::: "memory")

#define MMA_F16(c0,c1,c2,c3,a0,a1,a2,a3,b0,b1)                           \
    asm volatile(                                                        \
        "mma.sync.aligned.m16n8k16.row.col.f32.f16.f16.f32 "             \
        "{%0,%1,%2,%3}, {%4,%5,%6,%7}, {%8,%9}, {%0,%1,%2,%3};"          \
        : "+f"(c0), "+f"(c1), "+f"(c2), "+f"(c3)                         \
        : "r"(a0), "r"(a1), "r"(a2), "r"(a3), "r"(b0), "r"(b1))

// ---------------- pre-pass: fp32 -> fp16 (x) ----------------
__global__ void x2h_kernel(const float* __restrict__ in,
                           uint32_t* __restrict__ out, int n4) {
    int i = blockIdx.x * blockDim.x + threadIdx.x;
    if (i >= n4) return;
    float4 v = ((const float4*)in)[i];
    uint2 t;
    t.x = pack_h2(v.x, v.y);
    t.y = pack_h2(v.z, v.w);
    ((uint2*)out)[i] = t;
}

// ---------------- pre-pass: transpose + convert W [K,N] -> [N,K] fp16 ----------------
__global__ void wT2h_kernel(const float* __restrict__ in,
                            __half* __restrict__ out, int K, int N) {
    __shared__ float t[32][33];
    int n0 = blockIdx.x * 32, k0 = blockIdx.y * 32;
    int tx = threadIdx.x, ty = threadIdx.y;
#pragma unroll
    for (int i = 0; i < 32; i += 8)
        t[ty + i][tx] = in[(size_t)(k0 + ty + i) * N + n0 + tx];
    __syncthreads();
#pragma unroll
    for (int i = 0; i < 32; i += 8)
        out[(size_t)(n0 + ty + i) * K + k0 + tx] = __float2half_rn(t[tx][ty + i]);
}

// ---------------- pre-pass: V slice of qkv -> g_vT [B,H,DH,S] fp16 ----------------
__global__ void vT_kernel() {
    __shared__ float t[32][33];
    int bh = blockIdx.z;
    int b = bh >> 4, h = bh & 15;
    int d0 = blockIdx.y * 32;
    int s0 = blockIdx.x * 32;
    int tx = threadIdx.x, ty = threadIdx.y;
    const float* src = g_qkv + (size_t)b * SS * ND3 + 2 * DD + h * DHH;
#pragma unroll
    for (int i = 0; i < 32; i += 8)
        t[ty + i][tx] = src[(size_t)(s0 + ty + i) * ND3 + d0 + tx];
    __syncthreads();
    __half* dst = (__half*)g_vT + (size_t)bh * DHH * SS;
#pragma unroll
    for (int i = 0; i < 32; i += 8)
        dst[(size_t)(d0 + ty + i) * SS + s0 + tx] = __float2half_rn(t[tx][ty + i]);
}

// ==================== fp16 mma GEMM: 4-stage cp.async, 1 barrier/chunk ====================
#define GH_ASTR 20
#define GH_BSTR 20
#define GH_STG  (256*GH_ASTR + 128*GH_BSTR)   // 7680 u32
#define GH_SMEM_BYTES (4 * GH_STG * 4)        // 122880

__global__ void __launch_bounds__(256) gemm_h_kernel(
    const uint32_t* __restrict__ A, const uint32_t* __restrict__ Bt,
    const float* __restrict__ bias, float* __restrict__ C,
    int M, int N, int K)
{
    extern __shared__ uint32_t gsm[];
    uint32_t sbase = smem_u32(gsm);

    int tid  = threadIdx.x;
    int lane = tid & 31;
    int w    = tid >> 5;
    int wr   = w >> 1;       // 0..3
    int wc   = w & 1;        // 0..1
    int grp  = lane >> 2;
    int tig  = lane & 3;
    int m0 = blockIdx.y * 256;
    int n0 = blockIdx.x * 128;
    const int K2 = K >> 1;

    const int lrow = tid >> 2;          // 0..63
    const int lc4  = (tid & 3) * 4;     // 0,4,8,12
    const uint32_t* Abase = A + (size_t)(m0 + lrow) * K2 + lc4;
    const uint32_t* Bbase = Bt + (size_t)(n0 + lrow) * K2 + lc4;

    float acc[4][8][4];
#pragma unroll
    for (int mt = 0; mt < 4; mt++)
#pragma unroll
        for (int nt = 0; nt < 8; nt++)
#pragma unroll
            for (int i = 0; i < 4; i++) acc[mt][nt][i] = 0.f;

    const int nCh = K / 32;

    // prologue: chunks 0,1,2 -> stages 0,1,2
#pragma unroll
    for (int st = 0; st < 3; st++) {
        uint32_t sA = sbase + st * GH_STG * 4;
        uint32_t sB = sA + 256 * GH_ASTR * 4;
#pragma unroll
        for (int i = 0; i < 4; i++)
            cp16(sA + (((lrow + i * 64) * GH_ASTR + lc4) << 2),
                 Abase + (size_t)i * 64 * K2 + st * 16);
#pragma unroll
        for (int i = 0; i < 2; i++)
            cp16(sB + (((lrow + i * 64) * GH_BSTR + lc4) << 2),
                 Bbase + (size_t)i * 64 * K2 + st * 16);
        CP_COMMIT();
    }

    for (int kc = 0; kc < nCh; kc++) {
        int stage = kc & 3;
        CP_WAIT2();
        __syncthreads();
        uint32_t* As = gsm + stage * GH_STG;
        uint32_t* Bs = As + 256 * GH_ASTR;

#pragma unroll
        for (int kk = 0; kk < 2; kk++) {
            int kb = kk * 8 + tig;
            uint32_t af[4][4], bf[8][2];
#pragma unroll
            for (int mt = 0; mt < 4; mt++) {
                int r = wr * 64 + mt * 16 + grp;
                af[mt][0] = As[r * GH_ASTR + kb];
                af[mt][1] = As[(r + 8) * GH_ASTR + kb];
                af[mt][2] = As[r * GH_ASTR + kb + 4];
                af[mt][3] = As[(r + 8) * GH_ASTR + kb + 4];
            }
#pragma unroll
            for (int nt = 0; nt < 8; nt++) {
                int cn = wc * 64 + nt * 8 + grp;
                bf[nt][0] = Bs[cn * GH_BSTR + kb];
                bf[nt][1] = Bs[cn * GH_BSTR + kb + 4];
            }
#pragma unroll
            for (int mt = 0; mt < 4; mt++)
#pragma unroll
                for (int nt = 0; nt < 8; nt++)
                    MMA_F16(acc[mt][nt][0], acc[mt][nt][1], acc[mt][nt][2], acc[mt][nt][3],
                            af[mt][0], af[mt][1], af[mt][2], af[mt][3],
                            bf[nt][0], bf[nt][1]);
        }

        int kn = kc + 3;
        if (kn < nCh) {
            int wst = kn & 3;   // never equals any stage being read in the window
            uint32_t sA = sbase + wst * GH_STG * 4;
            uint32_t sB = sA + 256 * GH_ASTR * 4;
#pragma unroll
            for (int i = 0; i < 4; i++)
                cp16(sA + (((lrow + i * 64) * GH_ASTR + lc4) << 2),
                     Abase + (size_t)i * 64 * K2 + kn * 16);
#pragma unroll
            for (int i = 0; i < 2; i++)
                cp16(sB + (((lrow + i * 64) * GH_BSTR + lc4) << 2),
                     Bbase + (size_t)i * 64 * K2 + kn * 16);
        }
        CP_COMMIT();
    }

#pragma unroll
    for (int mt = 0; mt < 4; mt++) {
        int r0 = m0 + wr * 64 + mt * 16 + grp;
#pragma unroll
        for (int nt = 0; nt < 8; nt++) {
            int cn = n0 + wc * 64 + nt * 8 + tig * 2;
            float b0 = bias[cn], b1 = bias[cn + 1];
            float2 v0 = make_float2(acc[mt][nt][0] + b0, acc[mt][nt][1] + b1);
            float2 v1 = make_float2(acc[mt][nt][2] + b0, acc[mt][nt][3] + b1);
            *(float2*)(C + (size_t)r0 * N + cn) = v0;
            *(float2*)(C + (size_t)(r0 + 8) * N + cn) = v1;
        }
    }
}

// ---------------- RoPE tables (fp32, mirrors reference einsum+cos) ----------------
__global__ void invf_kernel() {
    int j = threadIdx.x;
    if (j < 64)
        g_invf_f[j] = (float)pow(10000.0, -(double)j / 64.0);
}

__global__ void rope_table_kernel() {
    int idx = blockIdx.x * blockDim.x + threadIdx.x;
    if (idx >= SS * 64) return;
    int t = idx >> 6;
    int j = idx & 63;
    float th = (float)t * g_invf_f[j];
    g_cos[idx] = cosf(th);
    g_sin[idx] = sinf(th);
}

// ---------------- RoPE + split, emit fp16 pairs ----------------
__global__ void rope_split_kernel() {
    int idx = blockIdx.x * blockDim.x + threadIdx.x;
    if (idx >= BB * HH * SS * 64) return;
    int j = idx & 63;
    int s = (idx >> 6) & (SS - 1);
    int h = (idx >> 17) & (HH - 1);
    int b = idx >> 21;

    const float* qrow = g_qkv + (size_t)(b * SS + s) * ND3 + h * DHH;
    const float* krow = qrow + DD;
    size_t o = ((size_t)(b * HH + h) * SS + s) * 64;

    const float qscale = 0.088388347648318447f;
    const float* ctab = g_cos + s * 64;
    const float* stab = g_sin + s * 64;

    float q0, q1, k0, k1;
    if (j < 32) {
        int d0 = 2 * j, d1 = 2 * j + 1;
        float c0 = ctab[d0], s0 = stab[d0], c1 = ctab[d1], s1 = stab[d1];
        q0 = qrow[d0] * c0 + qrow[2 * d0 + 1] * s0;
        q1 = qrow[d1] * c1 + qrow[2 * d1 + 1] * s1;
        k0 = krow[d0] * c0 + krow[2 * d0 + 1] * s0;
        k1 = krow[d1] * c1 + krow[2 * d1 + 1] * s1;
    } else {
        int d0 = 2 * j, d1 = 2 * j + 1;
        int e0 = d0 - 64, e1 = d1 - 64;
        float c0 = ctab[e0], s0 = stab[e0], c1 = ctab[e1], s1 = stab[e1];
        q0 = qrow[d0] * c0 - qrow[2 * e0] * s0;
        q1 = qrow[d1] * c1 - qrow[2 * e1] * s1;
        k0 = krow[d0] * c0 - krow[2 * e0] * s0;
        k1 = krow[d1] * c1 - krow[2 * e1] * s1;
    }
    g_qh[o + j] = pack_h2(q0 * qscale, q1 * qscale);
    g_kh[o + j] = pack_h2(k0, k1);
}

// ==================== flash attention fp16, double-buffered K/V ====================
#define AH_QSTR 68
#define AH_KSTR 68
#define AH_VSTR 36
#define AH_PSTR 36
#define AH_KV_STG (64*AH_KSTR + 128*AH_VSTR)   // 8960 u32 per stage
#define AH_RED  (128*AH_QSTR + 2*AH_KV_STG + 128*AH_PSTR)
#define AH_SMEM_U32 (AH_RED + 512)
#define AH_SMEM_BYTES (AH_SMEM_U32 * 4)        // ~129KB

__global__ void __launch_bounds__(256, 1) attn_mma_kernel() {
    extern __shared__ uint32_t sm4[];
    uint32_t* Qs   = sm4;                        // [128][68]
    uint32_t* KV0  = Qs + 128 * AH_QSTR;         // stage0: K [64][68], VT [128][36]
    uint32_t* KV1  = KV0 + AH_KV_STG;            // stage1
    uint32_t* Ps   = KV1 + AH_KV_STG;            // [128][36]
    float* redmax  = (float*)(sm4 + AH_RED);     // [2][128]
    float* redsum  = redmax + 256;               // [2][128]

    int tid  = threadIdx.x;
    int lane = tid & 31;
    int w    = tid >> 5;
    int g    = w & 3;
    int hf   = w >> 2;
    int grp  = lane >> 2;
    int tig  = lane & 3;

    int bh = blockIdx.y;
    int b = bh >> 4, h = bh & 15;
    int q0 = blockIdx.x * 128;

    const uint32_t* Qg = g_qh + (size_t)bh * SS * 64;
    const uint32_t* Kg = g_kh + (size_t)bh * SS * 64;
    const uint32_t* Vg = g_vT + (size_t)bh * DHH * (SS / 2);

    // load Q tile
#pragma unroll
    for (int i = 0; i < 8; i++) {
        int flat = tid + i * 256;
        int r = flat >> 4, c = (flat & 15) * 4;
        uint4 q4 = *(const uint4*)(Qg + (size_t)(q0 + r) * 64 + c);
        *(uint4*)&Qs[r * AH_QSTR + c] = q4;
    }

    int krr[4], krc[4], vrr[4], vrc[4];
#pragma unroll
    for (int i = 0; i < 4; i++) {
        int flat = tid + i * 256;
        krr[i] = flat >> 4;  krc[i] = (flat & 15) * 4;
        vrr[i] = flat >> 3;  vrc[i] = (flat & 7) * 4;
    }
    uint4 kpf[4], vpf[4];
#pragma unroll
    for (int i = 0; i < 4; i++) {
        kpf[i] = *(const uint4*)(Kg + (size_t)krr[i] * 64 + krc[i]);
        vpf[i] = *(const uint4*)(Vg + (size_t)vrr[i] * (SS / 2) + vrc[i]);
    }
    // STS tile0 -> stage0; prefetch tile1
    {
        uint32_t* Ks  = KV0;
        uint32_t* VsT = KV0 + 64 * AH_KSTR;
#pragma unroll
        for (int i = 0; i < 4; i++) {
            *(uint4*)&Ks[krr[i] * AH_KSTR + krc[i]] = kpf[i];
            *(uint4*)&VsT[vrr[i] * AH_VSTR + vrc[i]] = vpf[i];
        }
        const uint32_t* Kn = Kg + (size_t)64 * 64;
        const uint32_t* Vn = Vg + 32;
#pragma unroll
        for (int i = 0; i < 4; i++) {
            kpf[i] = *(const uint4*)(Kn + (size_t)krr[i] * 64 + krc[i]);
            vpf[i] = *(const uint4*)(Vn + (size_t)vrr[i] * (SS / 2) + vrc[i]);
        }
    }
    __syncthreads();

    int r0 = g * 32 + grp;
    float o[2][8][4];
#pragma unroll
    for (int mt = 0; mt < 2; mt++)
#pragma unroll
        for (int nt = 0; nt < 8; nt++)
#pragma unroll
            for (int i = 0; i < 4; i++) o[mt][nt][i] = 0.f;
    float m[4] = {-1e30f, -1e30f, -1e30f, -1e30f};
    float l[4] = {0.f, 0.f, 0.f, 0.f};

    const int NKT = SS / 64;
    for (int kt = 0; kt < NKT; kt++) {
        uint32_t* stg = (kt & 1) ? KV1 : KV0;
        uint32_t* Ks  = stg;
        uint32_t* VsT = stg + 64 * AH_KSTR;

        // STS tile kt+1 into other stage; then issue LDG kt+2
        if (kt + 1 < NKT) {
            uint32_t* nstg = (kt & 1) ? KV0 : KV1;
            uint32_t* nKs  = nstg;
            uint32_t* nVsT = nstg + 64 * AH_KSTR;
#pragma unroll
            for (int i = 0; i < 4; i++) {
                *(uint4*)&nKs[krr[i] * AH_KSTR + krc[i]] = kpf[i];
                *(uint4*)&nVsT[vrr[i] * AH_VSTR + vrc[i]] = vpf[i];
            }
            if (kt + 2 < NKT) {
                const uint32_t* Kn = Kg + (size_t)((kt + 2) * 64) * 64;
                const uint32_t* Vn = Vg + (kt + 2) * 32;
#pragma unroll
                for (int i = 0; i < 4; i++) {
                    kpf[i] = *(const uint4*)(Kn + (size_t)krr[i] * 64 + krc[i]);
                    vpf[i] = *(const uint4*)(Vn + (size_t)vrr[i] * (SS / 2) + vrc[i]);
                }
            }
        }

        // S = Q K^T
        float s[2][4][4];
#pragma unroll
        for (int mt = 0; mt < 2; mt++)
#pragma unroll
            for (int nt = 0; nt < 4; nt++)
#pragma unroll
                for (int i = 0; i < 4; i++) s[mt][nt][i] = 0.f;

#pragma unroll
        for (int ks = 0; ks < 8; ks++) {
            int kb = ks * 8 + tig;
            uint32_t af[2][4];
#pragma unroll
            for (int mt = 0; mt < 2; mt++) {
                int rr = r0 + mt * 16;
                af[mt][0] = Qs[rr * AH_QSTR + kb];
                af[mt][1] = Qs[(rr + 8) * AH_QSTR + kb];
                af[mt][2] = Qs[rr * AH_QSTR + kb + 4];
                af[mt][3] = Qs[(rr + 8) * AH_QSTR + kb + 4];
            }
#pragma unroll
            for (int nt = 0; nt < 4; nt++) {
                int kr = hf * 32 + nt * 8 + grp;
                uint32_t b0 = Ks[kr * AH_KSTR + kb];
                uint32_t b1 = Ks[kr * AH_KSTR + kb + 4];
#pragma unroll
                for (int mt = 0; mt < 2; mt++)
                    MMA_F16(s[mt][nt][0], s[mt][nt][1], s[mt][nt][2], s[mt][nt][3],
                            af[mt][0], af[mt][1], af[mt][2], af[mt][3], b0, b1);
            }
        }

        float mx[4] = {-1e30f, -1e30f, -1e30f, -1e30f};
#pragma unroll
        for (int mt = 0; mt < 2; mt++)
#pragma unroll
            for (int nt = 0; nt < 4; nt++) {
                mx[2*mt]   = fmaxf(mx[2*mt],   fmaxf(s[mt][nt][0], s[mt][nt][1]));
                mx[2*mt+1] = fmaxf(mx[2*mt+1], fmaxf(s[mt][nt][2], s[mt][nt][3]));
            }
#pragma unroll
        for (int off = 1; off <= 2; off <<= 1)
#pragma unroll
            for (int sl = 0; sl < 4; sl++)
                mx[sl] = fmaxf(mx[sl], __shfl_xor_sync(0xffffffffu, mx[sl], off));
        if (tig == 0) {
#pragma unroll
            for (int sl = 0; sl < 4; sl++)
                redmax[hf * 128 + r0 + sl * 8] = mx[sl];
        }
        __syncthreads();
        float nm[4], sc[4];
#pragma unroll
        for (int sl = 0; sl < 4; sl++) {
            int rr = r0 + sl * 8;
            nm[sl] = fmaxf(m[sl], fmaxf(redmax[rr], redmax[128 + rr]));
            sc[sl] = __expf(m[sl] - nm[sl]);
        }

        float ps[4] = {0.f, 0.f, 0.f, 0.f};
#pragma unroll
        for (int mt = 0; mt < 2; mt++)
#pragma unroll
            for (int nt = 0; nt < 4; nt++) {
                float p0 = __expf(s[mt][nt][0] - nm[2*mt]);
                float p1 = __expf(s[mt][nt][1] - nm[2*mt]);
                float p2 = __expf(s[mt][nt][2] - nm[2*mt+1]);
                float p3 = __expf(s[mt][nt][3] - nm[2*mt+1]);
                ps[2*mt]   += p0 + p1;
                ps[2*mt+1] += p2 + p3;
                int pc = hf * 16 + nt * 4 + tig;
                int rr = r0 + mt * 16;
                Ps[rr * AH_PSTR + pc]       = pack_h2(p0, p1);
                Ps[(rr + 8) * AH_PSTR + pc] = pack_h2(p2, p3);
            }
#pragma unroll
        for (int off = 1; off <= 2; off <<= 1)
#pragma unroll
            for (int sl = 0; sl < 4; sl++)
                ps[sl] += __shfl_xor_sync(0xffffffffu, ps[sl], off);
        if (tig == 0) {
#pragma unroll
            for (int sl = 0; sl < 4; sl++)
                redsum[hf * 128 + r0 + sl * 8] = ps[sl];
        }
        __syncthreads();
#pragma unroll
        for (int sl = 0; sl < 4; sl++) {
            int rr = r0 + sl * 8;
            l[sl] = l[sl] * sc[sl] + redsum[rr] + redsum[128 + rr];
            m[sl] = nm[sl];
        }
#pragma unroll
        for (int mt = 0; mt < 2; mt++)
#pragma unroll
            for (int nt = 0; nt < 8; nt++) {
                o[mt][nt][0] *= sc[2*mt]; o[mt][nt][1] *= sc[2*mt];
                o[mt][nt][2] *= sc[2*mt+1]; o[mt][nt][3] *= sc[2*mt+1];
            }

        // O += P V
#pragma unroll
        for (int ksv = 0; ksv < 4; ksv++) {
            int kb = ksv * 8 + tig;
            uint32_t af[2][4];
#pragma unroll
            for (int mt = 0; mt < 2; mt++) {
                int rr = r0 + mt * 16;
                af[mt][0] = Ps[rr * AH_PSTR + kb];
                af[mt][1] = Ps[(rr + 8) * AH_PSTR + kb];
                af[mt][2] = Ps[rr * AH_PSTR + kb + 4];
                af[mt][3] = Ps[(rr + 8) * AH_PSTR + kb + 4];
            }
#pragma unroll
            for (int nt = 0; nt < 8; nt++) {
                int vc = hf * 64 + nt * 8 + grp;
                uint32_t b0 = VsT[vc * AH_VSTR + kb];
                uint32_t b1 = VsT[vc * AH_VSTR + kb + 4];
#pragma unroll
                for (int mt = 0; mt < 2; mt++)
                    MMA_F16(o[mt][nt][0], o[mt][nt][1], o[mt][nt][2], o[mt][nt][3],
                            af[mt][0], af[mt][1], af[mt][2], af[mt][3], b0, b1);
            }
        }
        __syncthreads();   // STS(kt+1) visible; stage kt&1 free for overwrite at kt+2
    }

    float inv[4];
#pragma unroll
    for (int sl = 0; sl < 4; sl++) inv[sl] = 1.f / l[sl];
#pragma unroll
    for (int mt = 0; mt < 2; mt++) {
        int rrg0 = q0 + r0 + mt * 16;
        uint32_t* dst0 = g_ctxh + (size_t)(b * SS + rrg0) * (DD / 2) + h * 64;
        uint32_t* dst1 = g_ctxh + (size_t)(b * SS + rrg0 + 8) * (DD / 2) + h * 64;
#pragma unroll
        for (int nt = 0; nt < 8; nt++) {
            int pc = hf * 32 + nt * 4 + tig;
            dst0[pc] = pack_h2(o[mt][nt][0] * inv[2*mt],   o[mt][nt][1] * inv[2*mt]);
            dst1[pc] = pack_h2(o[mt][nt][2] * inv[2*mt+1], o[mt][nt][3] * inv[2*mt+1]);
        }
    }
}

// ---------------- launch ----------------
extern "C" void kernel_launch(void* const* d_in, const int* in_sizes, int n_in,
                              void* d_out, int out_size) {
    const float* x    = (const float*)d_in[0];
    const float* Wqkv = (const float*)d_in[1];
    const float* bqkv = (const float*)d_in[2];
    const float* Wo   = (const float*)d_in[3];
    const float* bo   = (const float*)d_in[4];
    float* out = (float*)d_out;

    void *qkvPtr, *xhPtr, *wqkvhPtr, *wohPtr, *ctxhPtr;
    cudaGetSymbolAddress(&qkvPtr, g_qkv);
    cudaGetSymbolAddress(&xhPtr, g_xh);
    cudaGetSymbolAddress(&wqkvhPtr, g_wqkvh);
    cudaGetSymbolAddress(&wohPtr, g_woh);
    cudaGetSymbolAddress(&ctxhPtr, g_ctxh);

    cudaFuncSetAttribute(attn_mma_kernel,
                         cudaFuncAttributeMaxDynamicSharedMemorySize,
                         AH_SMEM_BYTES);
    cudaFuncSetAttribute(gemm_h_kernel,
                         cudaFuncAttributeMaxDynamicSharedMemorySize,
                         GH_SMEM_BYTES);

    // 0) convert x -> fp16; transpose+convert weights -> fp16 [N][K]
    {
        int n4x = (BB * SS * DD) / 4;
        x2h_kernel<<<(n4x + 255) / 256, 256>>>(x, (uint32_t*)xhPtr, n4x);
        wT2h_kernel<<<dim3(ND3 / 32, DD / 32), dim3(32, 8)>>>(
            Wqkv, (__half*)wqkvhPtr, DD, ND3);
        wT2h_kernel<<<dim3(DD / 32, DD / 32), dim3(32, 8)>>>(
            Wo, (__half*)wohPtr, DD, DD);
    }

    // 1) RoPE tables (fp32, reference-faithful)
    invf_kernel<<<1, 64>>>();
    rope_table_kernel<<<(SS * 64 + 255) / 256, 256>>>();

    // 2) QKV GEMM (fp16, 4-stage cp.async) -> g_qkv fp32
    gemm_h_kernel<<<dim3(ND3 / 128, (BB * SS) / 256), 256, GH_SMEM_BYTES>>>(
        (const uint32_t*)xhPtr, (const uint32_t*)wqkvhPtr, bqkv, (float*)qkvPtr,
        BB * SS, ND3, DD);

    // 3a) RoPE + split -> g_qh/g_kh fp16
    rope_split_kernel<<<(BB * HH * SS * 64) / 256, 256>>>();
    // 3b) V transpose -> g_vT fp16 [B,H,DH,S]
    vT_kernel<<<dim3(SS / 32, DHH / 32, BB * HH), dim3(32, 8)>>>();

    // 4) flash attention (fp16, double-buffered) -> g_ctxh
    attn_mma_kernel<<<dim3(SS / 128, BB * HH), 256, AH_SMEM_BYTES>>>();

    // 5) output projection (fp16, 4-stage cp.async) -> out fp32
    gemm_h_kernel<<<dim3(DD / 128, (BB * SS) / 256), 256, GH_SMEM_BYTES>>>(
        (const uint32_t*)ctxhPtr, (const uint32_t*)wohPtr, bo, out, BB * SS, DD, DD);
}

// round 15
// speedup vs baseline: 2.3136x; 1.0266x over previous
#include <cuda_runtime.h>
#include <cuda_fp16.h>
#include <math.h>
#include <stdint.h>

#define BB 2
#define SS 2048
#define DD 2048
#define HH 16
#define DHH 128
#define ND3 (3*DD)

// ---------------- scratch (static device globals; no allocation) ----------------
__device__ float    g_qkv[(size_t)BB*SS*ND3];          // [B,S,3D] fp32
__device__ uint32_t g_qh [(size_t)BB*HH*SS*DHH/2];     // [B,H,S,DH] fp16 pairs, scaled
__device__ uint32_t g_kh [(size_t)BB*HH*SS*DHH/2];     // fp16 pairs
__device__ uint32_t g_vT [(size_t)BB*HH*DHH*SS/2];     // [B,H,DH,S] fp16 pairs (transposed)
__device__ uint32_t g_ctxh[(size_t)BB*SS*DD/2];        // [B,S,H*DH] fp16 pairs
__device__ uint32_t g_xh [(size_t)BB*SS*DD/2];         // x fp16 pairs [M][K/2]
__device__ uint32_t g_wqkvh[(size_t)ND3*DD/2];         // Wqkv^T fp16 [6144][1024]
__device__ uint32_t g_woh  [(size_t)DD*DD/2];          // Wo^T fp16 [2048][1024]
__device__ float g_cos[SS*64];
__device__ float g_sin[SS*64];

__device__ __forceinline__ uint32_t pack_h2(float lo, float hi) {
    __half2 h = __floats2half2_rn(lo, hi);
    return *(uint32_t*)&h;
}

__device__ __forceinline__ uint32_t smem_u32(const void* p) {
    uint32_t a;
    asm("{ .reg .u64 t; cvta.to.shared.u64 t, %1; cvt.u32.u64 %0, t; }" : "=r"(a) : "l"(p));
    return a;
}

__device__ __forceinline__ void cp16(uint32_t dst, const void* src) {
    asm volatile("cp.async.cg.shared.global [%0], [%1], 16;" :: "r"(dst), "l"(src));
}
#define CP_COMMIT() asm volatile("cp.async.commit_group;" ::: "memory")
#define CP_WAIT2()  asm volatile("cp.async.wait_group 2;" ::: "memory")

#define MMA_F16(c0,c1,c2,c3,a0,a1,a2,a3,b0,b1)                           \
    asm volatile(                                                        \
        "mma.sync.aligned.m16n8k16.row.col.f32.f16.f16.f32 "             \
        "{%0,%1,%2,%3}, {%4,%5,%6,%7}, {%8,%9}, {%0,%1,%2,%3};"          \
        : "+f"(c0), "+f"(c1), "+f"(c2), "+f"(c3)                         \
        : "r"(a0), "r"(a1), "r"(a2), "r"(a3), "r"(b0), "r"(b1))

// ---------------- pre-pass: fp32 -> fp16 (x) ----------------
__global__ void x2h_kernel(const float* __restrict__ in,
                           uint32_t* __restrict__ out, int n4) {
    int i = blockIdx.x * blockDim.x + threadIdx.x;
    if (i >= n4) return;
    float4 v = ((const float4*)in)[i];
    uint2 t;
    t.x = pack_h2(v.x, v.y);
    t.y = pack_h2(v.z, v.w);
    ((uint2*)out)[i] = t;
}

// ---------------- pre-pass: transpose + convert W [K,N] -> [N,K] fp16 ----------------
__global__ void wT2h_kernel(const float* __restrict__ in,
                            __half* __restrict__ out, int K, int N) {
    __shared__ float t[32][33];
    int n0 = blockIdx.x * 32, k0 = blockIdx.y * 32;
    int tx = threadIdx.x, ty = threadIdx.y;
#pragma unroll
    for (int i = 0; i < 32; i += 8)
        t[ty + i][tx] = in[(size_t)(k0 + ty + i) * N + n0 + tx];
    __syncthreads();
#pragma unroll
    for (int i = 0; i < 32; i += 8)
        out[(size_t)(n0 + ty + i) * K + k0 + tx] = __float2half_rn(t[tx][ty + i]);
}

// ---------------- pre-pass: V slice of qkv -> g_vT [B,H,DH,S] fp16 ----------------
__global__ void vT_kernel() {
    __shared__ float t[32][33];
    int bh = blockIdx.z;
    int b = bh >> 4, h = bh & 15;
    int d0 = blockIdx.y * 32;
    int s0 = blockIdx.x * 32;
    int tx = threadIdx.x, ty = threadIdx.y;
    const float* src = g_qkv + (size_t)b * SS * ND3 + 2 * DD + h * DHH;
#pragma unroll
    for (int i = 0; i < 32; i += 8)
        t[ty + i][tx] = src[(size_t)(s0 + ty + i) * ND3 + d0 + tx];
    __syncthreads();
    __half* dst = (__half*)g_vT + (size_t)bh * DHH * SS;
#pragma unroll
    for (int i = 0; i < 32; i += 8)
        dst[(size_t)(d0 + ty + i) * SS + s0 + tx] = __float2half_rn(t[tx][ty + i]);
}

// ==================== fp16 mma GEMM: 4-stage cp.async (R13, known-good) ====================
#define GH_ASTR 20
#define GH_BSTR 20
#define GH_STG  (256*GH_ASTR + 128*GH_BSTR)   // 7680 u32
#define GH_SMEM_BYTES (4 * GH_STG * 4)        // 122880

__global__ void __launch_bounds__(256) gemm_h_kernel(
    const uint32_t* __restrict__ A, const uint32_t* __restrict__ Bt,
    const float* __restrict__ bias, float* __restrict__ C,
    int M, int N, int K)
{
    extern __shared__ uint32_t gsm[];
    uint32_t sbase = smem_u32(gsm);

    int tid  = threadIdx.x;
    int lane = tid & 31;
    int w    = tid >> 5;
    int wr   = w >> 1;
    int wc   = w & 1;
    int grp  = lane >> 2;
    int tig  = lane & 3;
    int m0 = blockIdx.y * 256;
    int n0 = blockIdx.x * 128;
    const int K2 = K >> 1;

    const int lrow = tid >> 2;
    const int lc4  = (tid & 3) * 4;
    const uint32_t* Abase = A + (size_t)(m0 + lrow) * K2 + lc4;
    const uint32_t* Bbase = Bt + (size_t)(n0 + lrow) * K2 + lc4;

    float acc[4][8][4];
#pragma unroll
    for (int mt = 0; mt < 4; mt++)
#pragma unroll
        for (int nt = 0; nt < 8; nt++)
#pragma unroll
            for (int i = 0; i < 4; i++) acc[mt][nt][i] = 0.f;

    const int nCh = K / 32;

#pragma unroll
    for (int st = 0; st < 3; st++) {
        uint32_t sA = sbase + st * GH_STG * 4;
        uint32_t sB = sA + 256 * GH_ASTR * 4;
#pragma unroll
        for (int i = 0; i < 4; i++)
            cp16(sA + (((lrow + i * 64) * GH_ASTR + lc4) << 2),
                 Abase + (size_t)i * 64 * K2 + st * 16);
#pragma unroll
        for (int i = 0; i < 2; i++)
            cp16(sB + (((lrow + i * 64) * GH_BSTR + lc4) << 2),
                 Bbase + (size_t)i * 64 * K2 + st * 16);
        CP_COMMIT();
    }

    for (int kc = 0; kc < nCh; kc++) {
        int stage = kc & 3;
        CP_WAIT2();
        __syncthreads();
        uint32_t* As = gsm + stage * GH_STG;
        uint32_t* Bs = As + 256 * GH_ASTR;

#pragma unroll
        for (int kk = 0; kk < 2; kk++) {
            int kb = kk * 8 + tig;
            uint32_t af[4][4], bf[8][2];
#pragma unroll
            for (int mt = 0; mt < 4; mt++) {
                int r = wr * 64 + mt * 16 + grp;
                af[mt][0] = As[r * GH_ASTR + kb];
                af[mt][1] = As[(r + 8) * GH_ASTR + kb];
                af[mt][2] = As[r * GH_ASTR + kb + 4];
                af[mt][3] = As[(r + 8) * GH_ASTR + kb + 4];
            }
#pragma unroll
            for (int nt = 0; nt < 8; nt++) {
                int cn = wc * 64 + nt * 8 + grp;
                bf[nt][0] = Bs[cn * GH_BSTR + kb];
                bf[nt][1] = Bs[cn * GH_BSTR + kb + 4];
            }
#pragma unroll
            for (int mt = 0; mt < 4; mt++)
#pragma unroll
                for (int nt = 0; nt < 8; nt++)
                    MMA_F16(acc[mt][nt][0], acc[mt][nt][1], acc[mt][nt][2], acc[mt][nt][3],
                            af[mt][0], af[mt][1], af[mt][2], af[mt][3],
                            bf[nt][0], bf[nt][1]);
        }

        int kn = kc + 3;
        if (kn < nCh) {
            int wst = kn & 3;
            uint32_t sA = sbase + wst * GH_STG * 4;
            uint32_t sB = sA + 256 * GH_ASTR * 4;
#pragma unroll
            for (int i = 0; i < 4; i++)
                cp16(sA + (((lrow + i * 64) * GH_ASTR + lc4) << 2),
                     Abase + (size_t)i * 64 * K2 + kn * 16);
#pragma unroll
            for (int i = 0; i < 2; i++)
                cp16(sB + (((lrow + i * 64) * GH_BSTR + lc4) << 2),
                     Bbase + (size_t)i * 64 * K2 + kn * 16);
        }
        CP_COMMIT();
    }

#pragma unroll
    for (int mt = 0; mt < 4; mt++) {
        int r0 = m0 + wr * 64 + mt * 16 + grp;
#pragma unroll
        for (int nt = 0; nt < 8; nt++) {
            int cn = n0 + wc * 64 + nt * 8 + tig * 2;
            float b0 = bias[cn], b1 = bias[cn + 1];
            float2 v0 = make_float2(acc[mt][nt][0] + b0, acc[mt][nt][1] + b1);
            float2 v1 = make_float2(acc[mt][nt][2] + b0, acc[mt][nt][3] + b1);
            *(float2*)(C + (size_t)r0 * N + cn) = v0;
            *(float2*)(C + (size_t)(r0 + 8) * N + cn) = v1;
        }
    }
}

// ---------------- RoPE tables (per-block invf in smem, fp32 trig) ----------------
__global__ void rope_table_kernel() {
    __shared__ float invf[64];
    if (threadIdx.x < 64)
        invf[threadIdx.x] = (float)pow(10000.0, -(double)threadIdx.x / 64.0);
    __syncthreads();
    int idx = blockIdx.x * blockDim.x + threadIdx.x;
    if (idx >= SS * 64) return;
    int t = idx >> 6;
    int j = idx & 63;
    float th = (float)t * invf[j];
    g_cos[idx] = cosf(th);
    g_sin[idx] = sinf(th);
}

// ---------------- RoPE + split, emit fp16 pairs ----------------
__global__ void rope_split_kernel() {
    int idx = blockIdx.x * blockDim.x + threadIdx.x;
    if (idx >= BB * HH * SS * 64) return;
    int j = idx & 63;
    int s = (idx >> 6) & (SS - 1);
    int h = (idx >> 17) & (HH - 1);
    int b = idx >> 21;

    const float* qrow = g_qkv + (size_t)(b * SS + s) * ND3 + h * DHH;
    const float* krow = qrow + DD;
    size_t o = ((size_t)(b * HH + h) * SS + s) * 64;

    const float qscale = 0.088388347648318447f;
    const float* ctab = g_cos + s * 64;
    const float* stab = g_sin + s * 64;

    float q0, q1, k0, k1;
    if (j < 32) {
        int d0 = 2 * j, d1 = 2 * j + 1;
        float c0 = ctab[d0], s0 = stab[d0], c1 = ctab[d1], s1 = stab[d1];
        q0 = qrow[d0] * c0 + qrow[2 * d0 + 1] * s0;
        q1 = qrow[d1] * c1 + qrow[2 * d1 + 1] * s1;
        k0 = krow[d0] * c0 + krow[2 * d0 + 1] * s0;
        k1 = krow[d1] * c1 + krow[2 * d1 + 1] * s1;
    } else {
        int d0 = 2 * j, d1 = 2 * j + 1;
        int e0 = d0 - 64, e1 = d1 - 64;
        float c0 = ctab[e0], s0 = stab[e0], c1 = ctab[e1], s1 = stab[e1];
        q0 = qrow[d0] * c0 - qrow[2 * e0] * s0;
        q1 = qrow[d1] * c1 - qrow[2 * e1] * s1;
        k0 = krow[d0] * c0 - krow[2 * e0] * s0;
        k1 = krow[d1] * c1 - krow[2 * e1] * s1;
    }
    g_qh[o + j] = pack_h2(q0 * qscale, q1 * qscale);
    g_kh[o + j] = pack_h2(k0, k1);
}

// ==================== flash attention fp16, BN=128 keys/step ====================
// BM=128 q-rows, BN=128 keys, 256 threads = 8 warps (4 row-groups x 2 halves).
// QK warp tile 32x64 keys; PV warp tile 32 rows x 64 cols over 128 keys.
// All tiles stride 68 u32 (pairs): 68 mod 32 = 4 -> conflict-free fragments.
#define AH_STR 68
#define AH_RED  (4 * 128 * AH_STR)
#define AH_SMEM_U32 (AH_RED + 512)
#define AH_SMEM_BYTES (AH_SMEM_U32 * 4)   // ~141KB

__global__ void __launch_bounds__(256, 1) attn_mma_kernel() {
    extern __shared__ uint32_t sm4[];
    uint32_t* Qs  = sm4;                     // [128 rows][68]  d-pairs
    uint32_t* Ks  = Qs + 128 * AH_STR;       // [128 keys][68]  d-pairs
    uint32_t* VsT = Ks + 128 * AH_STR;       // [128 d][68]     key-pairs
    uint32_t* Ps  = VsT + 128 * AH_STR;      // [128 rows][68]  key-pairs
    float* redmax = (float*)(sm4 + AH_RED);  // [2][128]
    float* redsum = redmax + 256;            // [2][128]

    int tid  = threadIdx.x;
    int lane = tid & 31;
    int w    = tid >> 5;
    int g    = w & 3;           // row group
    int hf   = w >> 2;          // key half (QK) / out-col half (PV)
    int grp  = lane >> 2;
    int tig  = lane & 3;

    int bh = blockIdx.y;
    int b = bh >> 4, h = bh & 15;
    int q0 = blockIdx.x * 128;

    const uint32_t* Qg = g_qh + (size_t)bh * SS * 64;
    const uint32_t* Kg = g_kh + (size_t)bh * SS * 64;
    const uint32_t* Vg = g_vT + (size_t)bh * DHH * (SS / 2);

    // load Q tile: 128 rows x 64 pairs
#pragma unroll
    for (int i = 0; i < 8; i++) {
        int flat = tid + i * 256;
        int r = flat >> 4, c = (flat & 15) * 4;
        uint4 q4 = *(const uint4*)(Qg + (size_t)(q0 + r) * 64 + c);
        *(uint4*)&Qs[r * AH_STR + c] = q4;
    }

    // per-thread K/V load slots: K [128 keys][64 pairs], VT [128 d][64 pairs]
    int lr[8], lc[8];
#pragma unroll
    for (int i = 0; i < 8; i++) {
        int flat = tid + i * 256;
        lr[i] = flat >> 4;
        lc[i] = (flat & 15) * 4;
    }
    uint4 kpf[8], vpf[8];
#pragma unroll
    for (int i = 0; i < 8; i++) {
        kpf[i] = *(const uint4*)(Kg + (size_t)lr[i] * 64 + lc[i]);
        vpf[i] = *(const uint4*)(Vg + (size_t)lr[i] * (SS / 2) + lc[i]);
    }

    int r0 = g * 32 + grp;
    float o[2][8][4];
#pragma unroll
    for (int mt = 0; mt < 2; mt++)
#pragma unroll
        for (int nt = 0; nt < 8; nt++)
#pragma unroll
            for (int i = 0; i < 4; i++) o[mt][nt][i] = 0.f;
    float m[4] = {-1e30f, -1e30f, -1e30f, -1e30f};
    float l[4] = {0.f, 0.f, 0.f, 0.f};

    const int NKT = SS / 128;
    for (int kt = 0; kt < NKT; kt++) {
        __syncthreads();   // prev PV done reading Ks/VsT/Ps
#pragma unroll
        for (int i = 0; i < 8; i++) {
            *(uint4*)&Ks[lr[i] * AH_STR + lc[i]] = kpf[i];
            *(uint4*)&VsT[lr[i] * AH_STR + lc[i]] = vpf[i];
        }
        __syncthreads();

        // S = Q K^T : warp tile 32 rows x 64 keys, K=128 d -> 8 k16 steps
        float s[2][8][4];
#pragma unroll
        for (int mt = 0; mt < 2; mt++)
#pragma unroll
            for (int nt = 0; nt < 8; nt++)
#pragma unroll
                for (int i = 0; i < 4; i++) s[mt][nt][i] = 0.f;

#pragma unroll
        for (int ks = 0; ks < 8; ks++) {
            int kb = ks * 8 + tig;
            uint32_t af[2][4];
#pragma unroll
            for (int mt = 0; mt < 2; mt++) {
                int rr = r0 + mt * 16;
                af[mt][0] = Qs[rr * AH_STR + kb];
                af[mt][1] = Qs[(rr + 8) * AH_STR + kb];
                af[mt][2] = Qs[rr * AH_STR + kb + 4];
                af[mt][3] = Qs[(rr + 8) * AH_STR + kb + 4];
            }
#pragma unroll
            for (int nt = 0; nt < 8; nt++) {
                int kr = hf * 64 + nt * 8 + grp;
                uint32_t b0 = Ks[kr * AH_STR + kb];
                uint32_t b1 = Ks[kr * AH_STR + kb + 4];
#pragma unroll
                for (int mt = 0; mt < 2; mt++)
                    MMA_F16(s[mt][nt][0], s[mt][nt][1], s[mt][nt][2], s[mt][nt][3],
                            af[mt][0], af[mt][1], af[mt][2], af[mt][3], b0, b1);
            }
        }

        // partial max over this warp's 64 keys (per row-slot)
        float mx[4] = {-1e30f, -1e30f, -1e30f, -1e30f};
#pragma unroll
        for (int mt = 0; mt < 2; mt++)
#pragma unroll
            for (int nt = 0; nt < 8; nt++) {
                mx[2*mt]   = fmaxf(mx[2*mt],   fmaxf(s[mt][nt][0], s[mt][nt][1]));
                mx[2*mt+1] = fmaxf(mx[2*mt+1], fmaxf(s[mt][nt][2], s[mt][nt][3]));
            }
#pragma unroll
        for (int off = 1; off <= 2; off <<= 1)
#pragma unroll
            for (int sl = 0; sl < 4; sl++)
                mx[sl] = fmaxf(mx[sl], __shfl_xor_sync(0xffffffffu, mx[sl], off));
        if (tig == 0) {
#pragma unroll
            for (int sl = 0; sl < 4; sl++)
                redmax[hf * 128 + r0 + sl * 8] = mx[sl];
        }
        __syncthreads();
        float nm[4], sc[4];
#pragma unroll
        for (int sl = 0; sl < 4; sl++) {
            int rr = r0 + sl * 8;
            nm[sl] = fmaxf(m[sl], fmaxf(redmax[rr], redmax[128 + rr]));
            sc[sl] = __expf(m[sl] - nm[sl]);
        }

        // exp + P store + partial sums
        float ps[4] = {0.f, 0.f, 0.f, 0.f};
#pragma unroll
        for (int mt = 0; mt < 2; mt++)
#pragma unroll
            for (int nt = 0; nt < 8; nt++) {
                float p0 = __expf(s[mt][nt][0] - nm[2*mt]);
                float p1 = __expf(s[mt][nt][1] - nm[2*mt]);
                float p2 = __expf(s[mt][nt][2] - nm[2*mt+1]);
                float p3 = __expf(s[mt][nt][3] - nm[2*mt+1]);
                ps[2*mt]   += p0 + p1;
                ps[2*mt+1] += p2 + p3;
                int pc = hf * 32 + nt * 4 + tig;   // key-pair index
                int rr = r0 + mt * 16;
                Ps[rr * AH_STR + pc]       = pack_h2(p0, p1);
                Ps[(rr + 8) * AH_STR + pc] = pack_h2(p2, p3);
            }
#pragma unroll
        for (int off = 1; off <= 2; off <<= 1)
#pragma unroll
            for (int sl = 0; sl < 4; sl++)
                ps[sl] += __shfl_xor_sync(0xffffffffu, ps[sl], off);
        if (tig == 0) {
#pragma unroll
            for (int sl = 0; sl < 4; sl++)
                redsum[hf * 128 + r0 + sl * 8] = ps[sl];
        }
        __syncthreads();   // P complete (both halves), sums ready

        // issue gmem prefetch for kt+1 (overlaps PV below; s regs now dead)
        if (kt + 1 < NKT) {
            const uint32_t* Kn = Kg + (size_t)((kt + 1) * 128) * 64;
            const uint32_t* Vn = Vg + (kt + 1) * 64;
#pragma unroll
            for (int i = 0; i < 8; i++) {
                kpf[i] = *(const uint4*)(Kn + (size_t)lr[i] * 64 + lc[i]);
                vpf[i] = *(const uint4*)(Vn + (size_t)lr[i] * (SS / 2) + lc[i]);
            }
        }

#pragma unroll
        for (int sl = 0; sl < 4; sl++) {
            int rr = r0 + sl * 8;
            l[sl] = l[sl] * sc[sl] + redsum[rr] + redsum[128 + rr];
            m[sl] = nm[sl];
        }
#pragma unroll
        for (int mt = 0; mt < 2; mt++)
#pragma unroll
            for (int nt = 0; nt < 8; nt++) {
                o[mt][nt][0] *= sc[2*mt]; o[mt][nt][1] *= sc[2*mt];
                o[mt][nt][2] *= sc[2*mt+1]; o[mt][nt][3] *= sc[2*mt+1];
            }

        // O += P V : warp 32 rows x 64 out cols, 128 keys -> 8 k16 steps
#pragma unroll
        for (int ksv = 0; ksv < 8; ksv++) {
            int kb = ksv * 8 + tig;
            uint32_t af[2][4];
#pragma unroll
            for (int mt = 0; mt < 2; mt++) {
                int rr = r0 + mt * 16;
                af[mt][0] = Ps[rr * AH_STR + kb];
                af[mt][1] = Ps[(rr + 8) * AH_STR + kb];
                af[mt][2] = Ps[rr * AH_STR + kb + 4];
                af[mt][3] = Ps[(rr + 8) * AH_STR + kb + 4];
            }
#pragma unroll
            for (int nt = 0; nt < 8; nt++) {
                int vc = hf * 64 + nt * 8 + grp;
                uint32_t b0 = VsT[vc * AH_STR + kb];
                uint32_t b1 = VsT[vc * AH_STR + kb + 4];
#pragma unroll
                for (int mt = 0; mt < 2; mt++)
                    MMA_F16(o[mt][nt][0], o[mt][nt][1], o[mt][nt][2], o[mt][nt][3],
                            af[mt][0], af[mt][1], af[mt][2], af[mt][3], b0, b1);
            }
        }
    }

    // epilogue
    float inv[4];
#pragma unroll
    for (int sl = 0; sl < 4; sl++) inv[sl] = 1.f / l[sl];
#pragma unroll
    for (int mt = 0; mt < 2; mt++) {
        int rrg0 = q0 + r0 + mt * 16;
        uint32_t* dst0 = g_ctxh + (size_t)(b * SS + rrg0) * (DD / 2) + h * 64;
        uint32_t* dst1 = g_ctxh + (size_t)(b * SS + rrg0 + 8) * (DD / 2) + h * 64;
#pragma unroll
        for (int nt = 0; nt < 8; nt++) {
            int pc = hf * 32 + nt * 4 + tig;
            dst0[pc] = pack_h2(o[mt][nt][0] * inv[2*mt],   o[mt][nt][1] * inv[2*mt]);
            dst1[pc] = pack_h2(o[mt][nt][2] * inv[2*mt+1], o[mt][nt][3] * inv[2*mt+1]);
        }
    }
}

// ---------------- launch ----------------
extern "C" void kernel_launch(void* const* d_in, const int* in_sizes, int n_in,
                              void* d_out, int out_size) {
    const float* x    = (const float*)d_in[0];
    const float* Wqkv = (const float*)d_in[1];
    const float* bqkv = (const float*)d_in[2];
    const float* Wo   = (const float*)d_in[3];
    const float* bo   = (const float*)d_in[4];
    float* out = (float*)d_out;

    void *qkvPtr, *xhPtr, *wqkvhPtr, *wohPtr, *ctxhPtr;
    cudaGetSymbolAddress(&qkvPtr, g_qkv);
    cudaGetSymbolAddress(&xhPtr, g_xh);
    cudaGetSymbolAddress(&wqkvhPtr, g_wqkvh);
    cudaGetSymbolAddress(&wohPtr, g_woh);
    cudaGetSymbolAddress(&ctxhPtr, g_ctxh);

    cudaFuncSetAttribute(attn_mma_kernel,
                         cudaFuncAttributeMaxDynamicSharedMemorySize,
                         AH_SMEM_BYTES);
    cudaFuncSetAttribute(gemm_h_kernel,
                         cudaFuncAttributeMaxDynamicSharedMemorySize,
                         GH_SMEM_BYTES);

    // 0) convert x -> fp16; transpose+convert weights -> fp16 [N][K]
    {
        int n4x = (BB * SS * DD) / 4;
        x2h_kernel<<<(n4x + 255) / 256, 256>>>(x, (uint32_t*)xhPtr, n4x);
        wT2h_kernel<<<dim3(ND3 / 32, DD / 32), dim3(32, 8)>>>(
            Wqkv, (__half*)wqkvhPtr, DD, ND3);
        wT2h_kernel<<<dim3(DD / 32, DD / 32), dim3(32, 8)>>>(
            Wo, (__half*)wohPtr, DD, DD);
    }

    // 1) RoPE tables
    rope_table_kernel<<<(SS * 64 + 255) / 256, 256>>>();

    // 2) QKV GEMM (fp16, 4-stage cp.async) -> g_qkv fp32
    gemm_h_kernel<<<dim3(ND3 / 128, (BB * SS) / 256), 256, GH_SMEM_BYTES>>>(
        (const uint32_t*)xhPtr, (const uint32_t*)wqkvhPtr, bqkv, (float*)qkvPtr,
        BB * SS, ND3, DD);

    // 3a) RoPE + split -> g_qh/g_kh fp16
    rope_split_kernel<<<(BB * HH * SS * 64) / 256, 256>>>();
    // 3b) V transpose -> g_vT fp16 [B,H,DH,S]
    vT_kernel<<<dim3(SS / 32, DHH / 32, BB * HH), dim3(32, 8)>>>();

    // 4) flash attention (fp16, BN=128) -> g_ctxh
    attn_mma_kernel<<<dim3(SS / 128, BB * HH), 256, AH_SMEM_BYTES>>>();

    // 5) output projection (fp16, 4-stage cp.async) -> out fp32
    gemm_h_kernel<<<dim3(DD / 128, (BB * SS) / 256), 256, GH_SMEM_BYTES>>>(
        (const uint32_t*)ctxhPtr, (const uint32_t*)wohPtr, bo, out, BB * SS, DD, DD);
}

// round 16
// speedup vs baseline: 2.3234x; 1.0042x over previous
#include <cuda_runtime.h>
#include <cuda_fp16.h>
#include <math.h>
#include <stdint.h>

#define BB 2
#define SS 2048
#define DD 2048
#define HH 16
#define DHH 128
#define ND3 (3*DD)

// ---------------- scratch (static device globals; no allocation) ----------------
__device__ float    g_qkv[(size_t)BB*SS*ND3];          // [B,S,3D] fp32
__device__ uint32_t g_qh [(size_t)BB*HH*SS*DHH/2];     // [B,H,S,DH] fp16 pairs, scaled
__device__ uint32_t g_kh [(size_t)BB*HH*SS*DHH/2];     // fp16 pairs
__device__ uint32_t g_vT [(size_t)BB*HH*DHH*SS/2];     // [B,H,DH,S] fp16 pairs (transposed)
__device__ uint32_t g_ctxh[(size_t)BB*SS*DD/2];        // [B,S,H*DH] fp16 pairs
__device__ uint32_t g_xh [(size_t)BB*SS*DD/2];         // x fp16 pairs [M][K/2]
__device__ uint32_t g_wqkvh[(size_t)ND3*DD/2];         // Wqkv^T fp16 [6144][1024]
__device__ uint32_t g_woh  [(size_t)DD*DD/2];          // Wo^T fp16 [2048][1024]
__device__ float g_cos[SS*64];
__device__ float g_sin[SS*64];

__device__ __forceinline__ uint32_t pack_h2(float lo, float hi) {
    __half2 h = __floats2half2_rn(lo, hi);
    return *(uint32_t*)&h;
}

__device__ __forceinline__ uint32_t smem_u32(const void* p) {
    uint32_t a;
    asm("{ .reg .u64 t; cvta.to.shared.u64 t, %1; cvt.u32.u64 %0, t; }" : "=r"(a) : "l"(p));
    return a;
}

__device__ __forceinline__ void cp16(uint32_t dst, const void* src) {
    asm volatile("cp.async.cg.shared.global [%0], [%1], 16;" :: "r"(dst), "l"(src));
}
#define CP_COMMIT() asm volatile("cp.async.commit_group;" ::: "memory")
#define CP_WAIT2()  asm volatile("cp.async.wait_group 2;" ::: "memory")

#define MMA_F16(c0,c1,c2,c3,a0,a1,a2,a3,b0,b1)                           \
    asm volatile(                                                        \
        "mma.sync.aligned.m16n8k16.row.col.f32.f16.f16.f32 "             \
        "{%0,%1,%2,%3}, {%4,%5,%6,%7}, {%8,%9}, {%0,%1,%2,%3};"          \
        : "+f"(c0), "+f"(c1), "+f"(c2), "+f"(c3)                         \
        : "r"(a0), "r"(a1), "r"(a2), "r"(a3), "r"(b0), "r"(b1))

// ==================== fused prepass 1: x2h | Wqkv^T->h | Wo^T->h | rope tables ====================
// grid sections by blockIdx.x; every section bit-identical to its standalone kernel.
#define P1_NB_X   8192        // x2h: 2,097,152 float4 / 256
#define P1_NB_WQ  12288       // wT2h Wqkv: (6144/32) x (2048/32)
#define P1_NB_WO  4096        // wT2h Wo:   (2048/32) x (2048/32)
#define P1_NB_RT  512         // rope_table: 2048*64 / 256
#define P1_GRID   (P1_NB_X + P1_NB_WQ + P1_NB_WO + P1_NB_RT)

__device__ __forceinline__ void wT2h_body(const float* __restrict__ in,
                                          __half* __restrict__ out,
                                          int K, int N, int bx, int by,
                                          float (*t)[33], int tx, int ty) {
    int n0 = bx * 32, k0 = by * 32;
#pragma unroll
    for (int i = 0; i < 32; i += 8)
        t[ty + i][tx] = in[(size_t)(k0 + ty + i) * N + n0 + tx];
    __syncthreads();
#pragma unroll
    for (int i = 0; i < 32; i += 8)
        out[(size_t)(n0 + ty + i) * K + k0 + tx] = __float2half_rn(t[tx][ty + i]);
}

__global__ void __launch_bounds__(256) prep1_kernel(
    const float* __restrict__ x, const float* __restrict__ Wqkv,
    const float* __restrict__ Wo)
{
    __shared__ float t[32][33];
    int blk = blockIdx.x;
    int tid = threadIdx.x;
    int tx = tid & 31, ty = tid >> 5;

    if (blk < P1_NB_X) {
        // x -> fp16 pairs
        int i = blk * 256 + tid;
        float4 v = ((const float4*)x)[i];
        uint2 o;
        o.x = pack_h2(v.x, v.y);
        o.y = pack_h2(v.z, v.w);
        ((uint2*)g_xh)[i] = o;
        return;
    }
    blk -= P1_NB_X;
    if (blk < P1_NB_WQ) {
        wT2h_body(Wqkv, (__half*)g_wqkvh, DD, ND3, blk % (ND3 / 32), blk / (ND3 / 32),
                  t, tx, ty);
        return;
    }
    blk -= P1_NB_WQ;
    if (blk < P1_NB_WO) {
        wT2h_body(Wo, (__half*)g_woh, DD, DD, blk % (DD / 32), blk / (DD / 32),
                  t, tx, ty);
        return;
    }
    blk -= P1_NB_WO;
    {
        // rope tables
        float* invf = &t[0][0];
        if (tid < 64)
            invf[tid] = (float)pow(10000.0, -(double)tid / 64.0);
        __syncthreads();
        int idx = blk * 256 + tid;
        int tt = idx >> 6;
        int j = idx & 63;
        float th = (float)tt * invf[j];
        g_cos[idx] = cosf(th);
        g_sin[idx] = sinf(th);
    }
}

// ==================== fused prepass 2: rope_split | vT ====================
#define P2_NB_RS  16384       // rope_split: BB*HH*SS*64 / 256
#define P2_NB_VT  8192        // vT: (SS/32) * (DHH/32) * (BB*HH)
#define P2_GRID   (P2_NB_RS + P2_NB_VT)

__global__ void __launch_bounds__(256) prep2_kernel() {
    __shared__ float t[32][33];
    int blk = blockIdx.x;
    int tid = threadIdx.x;

    if (blk < P2_NB_RS) {
        int idx = blk * 256 + tid;
        int j = idx & 63;
        int s = (idx >> 6) & (SS - 1);
        int h = (idx >> 17) & (HH - 1);
        int b = idx >> 21;

        const float* qrow = g_qkv + (size_t)(b * SS + s) * ND3 + h * DHH;
        const float* krow = qrow + DD;
        size_t o = ((size_t)(b * HH + h) * SS + s) * 64;

        const float qscale = 0.088388347648318447f;
        const float* ctab = g_cos + s * 64;
        const float* stab = g_sin + s * 64;

        float q0, q1, k0, k1;
        if (j < 32) {
            int d0 = 2 * j, d1 = 2 * j + 1;
            float c0 = ctab[d0], s0 = stab[d0], c1 = ctab[d1], s1 = stab[d1];
            q0 = qrow[d0] * c0 + qrow[2 * d0 + 1] * s0;
            q1 = qrow[d1] * c1 + qrow[2 * d1 + 1] * s1;
            k0 = krow[d0] * c0 + krow[2 * d0 + 1] * s0;
            k1 = krow[d1] * c1 + krow[2 * d1 + 1] * s1;
        } else {
            int d0 = 2 * j, d1 = 2 * j + 1;
            int e0 = d0 - 64, e1 = d1 - 64;
            float c0 = ctab[e0], s0 = stab[e0], c1 = ctab[e1], s1 = stab[e1];
            q0 = qrow[d0] * c0 - qrow[2 * e0] * s0;
            q1 = qrow[d1] * c1 - qrow[2 * e1] * s1;
            k0 = krow[d0] * c0 - krow[2 * e0] * s0;
            k1 = krow[d1] * c1 - krow[2 * e1] * s1;
        }
        g_qh[o + j] = pack_h2(q0 * qscale, q1 * qscale);
        g_kh[o + j] = pack_h2(k0, k1);
        return;
    }
    blk -= P2_NB_RS;
    {
        // V transpose: blk -> (sx 0..63, dy 0..3, bh 0..31)
        int sx = blk & 63;
        int dy = (blk >> 6) & 3;
        int bh = blk >> 8;
        int b = bh >> 4, h = bh & 15;
        int d0 = dy * 32;
        int s0 = sx * 32;
        int tx = tid & 31, ty = tid >> 5;
        const float* src = g_qkv + (size_t)b * SS * ND3 + 2 * DD + h * DHH;
#pragma unroll
        for (int i = 0; i < 32; i += 8)
            t[ty + i][tx] = src[(size_t)(s0 + ty + i) * ND3 + d0 + tx];
        __syncthreads();
        __half* dst = (__half*)g_vT + (size_t)bh * DHH * SS;
#pragma unroll
        for (int i = 0; i < 32; i += 8)
            dst[(size_t)(d0 + ty + i) * SS + s0 + tx] = __float2half_rn(t[tx][ty + i]);
    }
}

// ==================== fp16 mma GEMM: 4-stage cp.async (R13/R14, known-good) ====================
#define GH_ASTR 20
#define GH_BSTR 20
#define GH_STG  (256*GH_ASTR + 128*GH_BSTR)   // 7680 u32
#define GH_SMEM_BYTES (4 * GH_STG * 4)        // 122880

__global__ void __launch_bounds__(256) gemm_h_kernel(
    const uint32_t* __restrict__ A, const uint32_t* __restrict__ Bt,
    const float* __restrict__ bias, float* __restrict__ C,
    int M, int N, int K)
{
    extern __shared__ uint32_t gsm[];
    uint32_t sbase = smem_u32(gsm);

    int tid  = threadIdx.x;
    int lane = tid & 31;
    int w    = tid >> 5;
    int wr   = w >> 1;
    int wc   = w & 1;
    int grp  = lane >> 2;
    int tig  = lane & 3;
    int m0 = blockIdx.y * 256;
    int n0 = blockIdx.x * 128;
    const int K2 = K >> 1;

    const int lrow = tid >> 2;
    const int lc4  = (tid & 3) * 4;
    const uint32_t* Abase = A + (size_t)(m0 + lrow) * K2 + lc4;
    const uint32_t* Bbase = Bt + (size_t)(n0 + lrow) * K2 + lc4;

    float acc[4][8][4];
#pragma unroll
    for (int mt = 0; mt < 4; mt++)
#pragma unroll
        for (int nt = 0; nt < 8; nt++)
#pragma unroll
            for (int i = 0; i < 4; i++) acc[mt][nt][i] = 0.f;

    const int nCh = K / 32;

#pragma unroll
    for (int st = 0; st < 3; st++) {
        uint32_t sA = sbase + st * GH_STG * 4;
        uint32_t sB = sA + 256 * GH_ASTR * 4;
#pragma unroll
        for (int i = 0; i < 4; i++)
            cp16(sA + (((lrow + i * 64) * GH_ASTR + lc4) << 2),
                 Abase + (size_t)i * 64 * K2 + st * 16);
#pragma unroll
        for (int i = 0; i < 2; i++)
            cp16(sB + (((lrow + i * 64) * GH_BSTR + lc4) << 2),
                 Bbase + (size_t)i * 64 * K2 + st * 16);
        CP_COMMIT();
    }

    for (int kc = 0; kc < nCh; kc++) {
        int stage = kc & 3;
        CP_WAIT2();
        __syncthreads();
        uint32_t* As = gsm + stage * GH_STG;
        uint32_t* Bs = As + 256 * GH_ASTR;

#pragma unroll
        for (int kk = 0; kk < 2; kk++) {
            int kb = kk * 8 + tig;
            uint32_t af[4][4], bf[8][2];
#pragma unroll
            for (int mt = 0; mt < 4; mt++) {
                int r = wr * 64 + mt * 16 + grp;
                af[mt][0] = As[r * GH_ASTR + kb];
                af[mt][1] = As[(r + 8) * GH_ASTR + kb];
                af[mt][2] = As[r * GH_ASTR + kb + 4];
                af[mt][3] = As[(r + 8) * GH_ASTR + kb + 4];
            }
#pragma unroll
            for (int nt = 0; nt < 8; nt++) {
                int cn = wc * 64 + nt * 8 + grp;
                bf[nt][0] = Bs[cn * GH_BSTR + kb];
                bf[nt][1] = Bs[cn * GH_BSTR + kb + 4];
            }
#pragma unroll
            for (int mt = 0; mt < 4; mt++)
#pragma unroll
                for (int nt = 0; nt < 8; nt++)
                    MMA_F16(acc[mt][nt][0], acc[mt][nt][1], acc[mt][nt][2], acc[mt][nt][3],
                            af[mt][0], af[mt][1], af[mt][2], af[mt][3],
                            bf[nt][0], bf[nt][1]);
        }

        int kn = kc + 3;
        if (kn < nCh) {
            int wst = kn & 3;
            uint32_t sA = sbase + wst * GH_STG * 4;
            uint32_t sB = sA + 256 * GH_ASTR * 4;
#pragma unroll
            for (int i = 0; i < 4; i++)
                cp16(sA + (((lrow + i * 64) * GH_ASTR + lc4) << 2),
                     Abase + (size_t)i * 64 * K2 + kn * 16);
#pragma unroll
            for (int i = 0; i < 2; i++)
                cp16(sB + (((lrow + i * 64) * GH_BSTR + lc4) << 2),
                     Bbase + (size_t)i * 64 * K2 + kn * 16);
        }
        CP_COMMIT();
    }

#pragma unroll
    for (int mt = 0; mt < 4; mt++) {
        int r0 = m0 + wr * 64 + mt * 16 + grp;
#pragma unroll
        for (int nt = 0; nt < 8; nt++) {
            int cn = n0 + wc * 64 + nt * 8 + tig * 2;
            float b0 = bias[cn], b1 = bias[cn + 1];
            float2 v0 = make_float2(acc[mt][nt][0] + b0, acc[mt][nt][1] + b1);
            float2 v1 = make_float2(acc[mt][nt][2] + b0, acc[mt][nt][3] + b1);
            *(float2*)(C + (size_t)r0 * N + cn) = v0;
            *(float2*)(C + (size_t)(r0 + 8) * N + cn) = v1;
        }
    }
}

// ==================== flash attention fp16, BN=128 (R14, known-good) ====================
#define AH_STR 68
#define AH_RED  (4 * 128 * AH_STR)
#define AH_SMEM_U32 (AH_RED + 512)
#define AH_SMEM_BYTES (AH_SMEM_U32 * 4)   // ~141KB

__global__ void __launch_bounds__(256, 1) attn_mma_kernel() {
    extern __shared__ uint32_t sm4[];
    uint32_t* Qs  = sm4;
    uint32_t* Ks  = Qs + 128 * AH_STR;
    uint32_t* VsT = Ks + 128 * AH_STR;
    uint32_t* Ps  = VsT + 128 * AH_STR;
    float* redmax = (float*)(sm4 + AH_RED);
    float* redsum = redmax + 256;

    int tid  = threadIdx.x;
    int lane = tid & 31;
    int w    = tid >> 5;
    int g    = w & 3;
    int hf   = w >> 2;
    int grp  = lane >> 2;
    int tig  = lane & 3;

    int bh = blockIdx.y;
    int b = bh >> 4, h = bh & 15;
    int q0 = blockIdx.x * 128;

    const uint32_t* Qg = g_qh + (size_t)bh * SS * 64;
    const uint32_t* Kg = g_kh + (size_t)bh * SS * 64;
    const uint32_t* Vg = g_vT + (size_t)bh * DHH * (SS / 2);

#pragma unroll
    for (int i = 0; i < 8; i++) {
        int flat = tid + i * 256;
        int r = flat >> 4, c = (flat & 15) * 4;
        uint4 q4 = *(const uint4*)(Qg + (size_t)(q0 + r) * 64 + c);
        *(uint4*)&Qs[r * AH_STR + c] = q4;
    }

    int lr[8], lc[8];
#pragma unroll
    for (int i = 0; i < 8; i++) {
        int flat = tid + i * 256;
        lr[i] = flat >> 4;
        lc[i] = (flat & 15) * 4;
    }
    uint4 kpf[8], vpf[8];
#pragma unroll
    for (int i = 0; i < 8; i++) {
        kpf[i] = *(const uint4*)(Kg + (size_t)lr[i] * 64 + lc[i]);
        vpf[i] = *(const uint4*)(Vg + (size_t)lr[i] * (SS / 2) + lc[i]);
    }

    int r0 = g * 32 + grp;
    float o[2][8][4];
#pragma unroll
    for (int mt = 0; mt < 2; mt++)
#pragma unroll
        for (int nt = 0; nt < 8; nt++)
#pragma unroll
            for (int i = 0; i < 4; i++) o[mt][nt][i] = 0.f;
    float m[4] = {-1e30f, -1e30f, -1e30f, -1e30f};
    float l[4] = {0.f, 0.f, 0.f, 0.f};

    const int NKT = SS / 128;
    for (int kt = 0; kt < NKT; kt++) {
        __syncthreads();
#pragma unroll
        for (int i = 0; i < 8; i++) {
            *(uint4*)&Ks[lr[i] * AH_STR + lc[i]] = kpf[i];
            *(uint4*)&VsT[lr[i] * AH_STR + lc[i]] = vpf[i];
        }
        __syncthreads();

        float s[2][8][4];
#pragma unroll
        for (int mt = 0; mt < 2; mt++)
#pragma unroll
            for (int nt = 0; nt < 8; nt++)
#pragma unroll
                for (int i = 0; i < 4; i++) s[mt][nt][i] = 0.f;

#pragma unroll
        for (int ks = 0; ks < 8; ks++) {
            int kb = ks * 8 + tig;
            uint32_t af[2][4];
#pragma unroll
            for (int mt = 0; mt < 2; mt++) {
                int rr = r0 + mt * 16;
                af[mt][0] = Qs[rr * AH_STR + kb];
                af[mt][1] = Qs[(rr + 8) * AH_STR + kb];
                af[mt][2] = Qs[rr * AH_STR + kb + 4];
                af[mt][3] = Qs[(rr + 8) * AH_STR + kb + 4];
            }
#pragma unroll
            for (int nt = 0; nt < 8; nt++) {
                int kr = hf * 64 + nt * 8 + grp;
                uint32_t b0 = Ks[kr * AH_STR + kb];
                uint32_t b1 = Ks[kr * AH_STR + kb + 4];
#pragma unroll
                for (int mt = 0; mt < 2; mt++)
                    MMA_F16(s[mt][nt][0], s[mt][nt][1], s[mt][nt][2], s[mt][nt][3],
                            af[mt][0], af[mt][1], af[mt][2], af[mt][3], b0, b1);
            }
        }

        float mx[4] = {-1e30f, -1e30f, -1e30f, -1e30f};
#pragma unroll
        for (int mt = 0; mt < 2; mt++)
#pragma unroll
            for (int nt = 0; nt < 8; nt++) {
                mx[2*mt]   = fmaxf(mx[2*mt],   fmaxf(s[mt][nt][0], s[mt][nt][1]));
                mx[2*mt+1] = fmaxf(mx[2*mt+1], fmaxf(s[mt][nt][2], s[mt][nt][3]));
            }
#pragma unroll
        for (int off = 1; off <= 2; off <<= 1)
#pragma unroll
            for (int sl = 0; sl < 4; sl++)
                mx[sl] = fmaxf(mx[sl], __shfl_xor_sync(0xffffffffu, mx[sl], off));
        if (tig == 0) {
#pragma unroll
            for (int sl = 0; sl < 4; sl++)
                redmax[hf * 128 + r0 + sl * 8] = mx[sl];
        }
        __syncthreads();
        float nm[4], sc[4];
#pragma unroll
        for (int sl = 0; sl < 4; sl++) {
            int rr = r0 + sl * 8;
            nm[sl] = fmaxf(m[sl], fmaxf(redmax[rr], redmax[128 + rr]));
            sc[sl] = __expf(m[sl] - nm[sl]);
        }

        float ps[4] = {0.f, 0.f, 0.f, 0.f};
#pragma unroll
        for (int mt = 0; mt < 2; mt++)
#pragma unroll
            for (int nt = 0; nt < 8; nt++) {
                float p0 = __expf(s[mt][nt][0] - nm[2*mt]);
                float p1 = __expf(s[mt][nt][1] - nm[2*mt]);
                float p2 = __expf(s[mt][nt][2] - nm[2*mt+1]);
                float p3 = __expf(s[mt][nt][3] - nm[2*mt+1]);
                ps[2*mt]   += p0 + p1;
                ps[2*mt+1] += p2 + p3;
                int pc = hf * 32 + nt * 4 + tig;
                int rr = r0 + mt * 16;
                Ps[rr * AH_STR + pc]       = pack_h2(p0, p1);
                Ps[(rr + 8) * AH_STR + pc] = pack_h2(p2, p3);
            }
#pragma unroll
        for (int off = 1; off <= 2; off <<= 1)
#pragma unroll
            for (int sl = 0; sl < 4; sl++)
                ps[sl] += __shfl_xor_sync(0xffffffffu, ps[sl], off);
        if (tig == 0) {
#pragma unroll
            for (int sl = 0; sl < 4; sl++)
                redsum[hf * 128 + r0 + sl * 8] = ps[sl];
        }
        __syncthreads();

        if (kt + 1 < NKT) {
            const uint32_t* Kn = Kg + (size_t)((kt + 1) * 128) * 64;
            const uint32_t* Vn = Vg + (kt + 1) * 64;
#pragma unroll
            for (int i = 0; i < 8; i++) {
                kpf[i] = *(const uint4*)(Kn + (size_t)lr[i] * 64 + lc[i]);
                vpf[i] = *(const uint4*)(Vn + (size_t)lr[i] * (SS / 2) + lc[i]);
            }
        }

#pragma unroll
        for (int sl = 0; sl < 4; sl++) {
            int rr = r0 + sl * 8;
            l[sl] = l[sl] * sc[sl] + redsum[rr] + redsum[128 + rr];
            m[sl] = nm[sl];
        }
#pragma unroll
        for (int mt = 0; mt < 2; mt++)
#pragma unroll
            for (int nt = 0; nt < 8; nt++) {
                o[mt][nt][0] *= sc[2*mt]; o[mt][nt][1] *= sc[2*mt];
                o[mt][nt][2] *= sc[2*mt+1]; o[mt][nt][3] *= sc[2*mt+1];
            }

#pragma unroll
        for (int ksv = 0; ksv < 8; ksv++) {
            int kb = ksv * 8 + tig;
            uint32_t af[2][4];
#pragma unroll
            for (int mt = 0; mt < 2; mt++) {
                int rr = r0 + mt * 16;
                af[mt][0] = Ps[rr * AH_STR + kb];
                af[mt][1] = Ps[(rr + 8) * AH_STR + kb];
                af[mt][2] = Ps[rr * AH_STR + kb + 4];
                af[mt][3] = Ps[(rr + 8) * AH_STR + kb + 4];
            }
#pragma unroll
            for (int nt = 0; nt < 8; nt++) {
                int vc = hf * 64 + nt * 8 + grp;
                uint32_t b0 = VsT[vc * AH_STR + kb];
                uint32_t b1 = VsT[vc * AH_STR + kb + 4];
#pragma unroll
                for (int mt = 0; mt < 2; mt++)
                    MMA_F16(o[mt][nt][0], o[mt][nt][1], o[mt][nt][2], o[mt][nt][3],
                            af[mt][0], af[mt][1], af[mt][2], af[mt][3], b0, b1);
            }
        }
    }

    float inv[4];
#pragma unroll
    for (int sl = 0; sl < 4; sl++) inv[sl] = 1.f / l[sl];
#pragma unroll
    for (int mt = 0; mt < 2; mt++) {
        int rrg0 = q0 + r0 + mt * 16;
        uint32_t* dst0 = g_ctxh + (size_t)(b * SS + rrg0) * (DD / 2) + h * 64;
        uint32_t* dst1 = g_ctxh + (size_t)(b * SS + rrg0 + 8) * (DD / 2) + h * 64;
#pragma unroll
        for (int nt = 0; nt < 8; nt++) {
            int pc = hf * 32 + nt * 4 + tig;
            dst0[pc] = pack_h2(o[mt][nt][0] * inv[2*mt],   o[mt][nt][1] * inv[2*mt]);
            dst1[pc] = pack_h2(o[mt][nt][2] * inv[2*mt+1], o[mt][nt][3] * inv[2*mt+1]);
        }
    }
}

// ---------------- launch ----------------
extern "C" void kernel_launch(void* const* d_in, const int* in_sizes, int n_in,
                              void* d_out, int out_size) {
    const float* x    = (const float*)d_in[0];
    const float* Wqkv = (const float*)d_in[1];
    const float* bqkv = (const float*)d_in[2];
    const float* Wo   = (const float*)d_in[3];
    const float* bo   = (const float*)d_in[4];
    float* out = (float*)d_out;

    void *qkvPtr, *xhPtr, *wqkvhPtr, *wohPtr, *ctxhPtr;
    cudaGetSymbolAddress(&qkvPtr, g_qkv);
    cudaGetSymbolAddress(&xhPtr, g_xh);
    cudaGetSymbolAddress(&wqkvhPtr, g_wqkvh);
    cudaGetSymbolAddress(&wohPtr, g_woh);
    cudaGetSymbolAddress(&ctxhPtr, g_ctxh);

    cudaFuncSetAttribute(attn_mma_kernel,
                         cudaFuncAttributeMaxDynamicSharedMemorySize,
                         AH_SMEM_BYTES);
    cudaFuncSetAttribute(gemm_h_kernel,
                         cudaFuncAttributeMaxDynamicSharedMemorySize,
                         GH_SMEM_BYTES);

    // 1) fused prepass: x->fp16 | Wqkv^T fp16 | Wo^T fp16 | rope tables
    prep1_kernel<<<P1_GRID, 256>>>(x, Wqkv, Wo);

    // 2) QKV GEMM (fp16, 4-stage cp.async) -> g_qkv fp32
    gemm_h_kernel<<<dim3(ND3 / 128, (BB * SS) / 256), 256, GH_SMEM_BYTES>>>(
        (const uint32_t*)xhPtr, (const uint32_t*)wqkvhPtr, bqkv, (float*)qkvPtr,
        BB * SS, ND3, DD);

    // 3) fused prepass: RoPE+split fp16 | V transpose fp16
    prep2_kernel<<<P2_GRID, 256>>>();

    // 4) flash attention (fp16, BN=128) -> g_ctxh
    attn_mma_kernel<<<dim3(SS / 128, BB * HH), 256, AH_SMEM_BYTES>>>();

    // 5) output projection (fp16, 4-stage cp.async) -> out fp32
    gemm_h_kernel<<<dim3(DD / 128, (BB * SS) / 256), 256, GH_SMEM_BYTES>>>(
        (const uint32_t*)ctxhPtr, (const uint32_t*)wohPtr, bo, out, BB * SS, DD, DD);
}

// round 17
// speedup vs baseline: 2.4113x; 1.0378x over previous
#include <cuda_runtime.h>
#include <cuda_fp16.h>
#include <math.h>
#include <stdint.h>

#define BB 2
#define SS 2048
#define DD 2048
#define HH 16
#define DHH 128
#define ND3 (3*DD)

// ---------------- scratch (static device globals; no allocation) ----------------
__device__ float    g_qkv[(size_t)BB*SS*ND3];          // [B,S,3D] fp32 (only q,k cols written)
__device__ uint32_t g_vh [(size_t)BB*SS*DD/2];         // v GEMM output, fp16 pairs [B*S][1024]
__device__ uint32_t g_qh [(size_t)BB*HH*SS*DHH/2];     // [B,H,S,DH] fp16 pairs, scaled
__device__ uint32_t g_kh [(size_t)BB*HH*SS*DHH/2];     // fp16 pairs
__device__ uint32_t g_vT [(size_t)BB*HH*DHH*SS/2];     // [B,H,DH,S] fp16 pairs (transposed)
__device__ uint32_t g_ctxh[(size_t)BB*SS*DD/2];        // [B,S,H*DH] fp16 pairs
__device__ uint32_t g_xh [(size_t)BB*SS*DD/2];         // x fp16 pairs [M][K/2]
__device__ uint32_t g_wqkvh[(size_t)ND3*DD/2];         // Wqkv^T fp16 [6144][1024]
__device__ uint32_t g_woh  [(size_t)DD*DD/2];          // Wo^T fp16 [2048][1024]
__device__ float g_cos[SS*64];
__device__ float g_sin[SS*64];

__device__ __forceinline__ uint32_t pack_h2(float lo, float hi) {
    __half2 h = __floats2half2_rn(lo, hi);
    return *(uint32_t*)&h;
}

__device__ __forceinline__ uint32_t smem_u32(const void* p) {
    uint32_t a;
    asm("{ .reg .u64 t; cvta.to.shared.u64 t, %1; cvt.u32.u64 %0, t; }" : "=r"(a) : "l"(p));
    return a;
}

__device__ __forceinline__ void cp16(uint32_t dst, const void* src) {
    asm volatile("cp.async.cg.shared.global [%0], [%1], 16;" :: "r"(dst), "l"(src));
}
#define CP_COMMIT() asm volatile("cp.async.commit_group;" ::: "memory")
#define CP_WAIT2()  asm volatile("cp.async.wait_group 2;" ::: "memory")

#define MMA_F16(c0,c1,c2,c3,a0,a1,a2,a3,b0,b1)                           \
    asm volatile(                                                        \
        "mma.sync.aligned.m16n8k16.row.col.f32.f16.f16.f32 "             \
        "{%0,%1,%2,%3}, {%4,%5,%6,%7}, {%8,%9}, {%0,%1,%2,%3};"          \
        : "+f"(c0), "+f"(c1), "+f"(c2), "+f"(c3)                         \
        : "r"(a0), "r"(a1), "r"(a2), "r"(a3), "r"(b0), "r"(b1))

// ==================== fused prepass 1: x2h | Wqkv^T->h | Wo^T->h | rope tables ====================
// wT2h tiles: 64 K-rows x 32 N-cols -> packed u32 stores along K.
#define P1_NB_X   8192        // x2h: 2,097,152 float4 / 256
#define P1_NB_WQ  6144        // (2048/64) x (6144/32)
#define P1_NB_WO  2048        // (2048/64) x (2048/32)
#define P1_NB_RT  512         // rope_table: 2048*64 / 256
#define P1_GRID   (P1_NB_X + P1_NB_WQ + P1_NB_WO + P1_NB_RT)

__device__ __forceinline__ void wT2h_body(const float* __restrict__ in,
                                          uint32_t* __restrict__ out,
                                          int K, int N, int bk, int bn,
                                          float (*t)[33], int tid) {
    int k0 = bk * 64, n0 = bn * 32;
#pragma unroll
    for (int i = 0; i < 8; i++) {
        int flat = tid + i * 256;
        int kl = flat >> 5, nl = flat & 31;
        t[kl][nl] = in[(size_t)(k0 + kl) * N + n0 + nl];
    }
    __syncthreads();
    int K2 = K >> 1;
#pragma unroll
    for (int i = 0; i < 4; i++) {
        int flat = tid + i * 256;
        int nl = flat >> 5, kp = flat & 31;
        out[(size_t)(n0 + nl) * K2 + (k0 >> 1) + kp] =
            pack_h2(t[2 * kp][nl], t[2 * kp + 1][nl]);
    }
}

__global__ void __launch_bounds__(256) prep1_kernel(
    const float* __restrict__ x, const float* __restrict__ Wqkv,
    const float* __restrict__ Wo)
{
    __shared__ float t[64][33];
    int blk = blockIdx.x;
    int tid = threadIdx.x;

    if (blk < P1_NB_X) {
        int i = blk * 256 + tid;
        float4 v = ((const float4*)x)[i];
        uint2 o;
        o.x = pack_h2(v.x, v.y);
        o.y = pack_h2(v.z, v.w);
        ((uint2*)g_xh)[i] = o;
        return;
    }
    blk -= P1_NB_X;
    if (blk < P1_NB_WQ) {
        wT2h_body(Wqkv, g_wqkvh, DD, ND3, blk / 192, blk % 192, t, tid);
        return;
    }
    blk -= P1_NB_WQ;
    if (blk < P1_NB_WO) {
        wT2h_body(Wo, g_woh, DD, DD, blk / 64, blk % 64, t, tid);
        return;
    }
    blk -= P1_NB_WO;
    {
        float* invf = &t[0][0];
        if (tid < 64)
            invf[tid] = (float)pow(10000.0, -(double)tid / 64.0);
        __syncthreads();
        int idx = blk * 256 + tid;
        int tt = idx >> 6;
        int j = idx & 63;
        float th = (float)tt * invf[j];
        g_cos[idx] = cosf(th);
        g_sin[idx] = sinf(th);
    }
}

// ==================== fused prepass 2: rope_split | vT (fp16 in, packed u32 out) ====================
#define P2_NB_RS  16384       // rope_split: BB*HH*SS*64 / 256
#define P2_NB_VT  4096        // vT: (DHH/32) x (SS/64) x (BB*HH)
#define P2_GRID   (P2_NB_RS + P2_NB_VT)

__global__ void __launch_bounds__(256) prep2_kernel() {
    __shared__ __half th[32][66];   // padded: banks 33*dp mod 32 all distinct
    int blk = blockIdx.x;
    int tid = threadIdx.x;

    if (blk < P2_NB_RS) {
        int idx = blk * 256 + tid;
        int j = idx & 63;
        int s = (idx >> 6) & (SS - 1);
        int h = (idx >> 17) & (HH - 1);
        int b = idx >> 21;

        const float* qrow = g_qkv + (size_t)(b * SS + s) * ND3 + h * DHH;
        const float* krow = qrow + DD;
        size_t o = ((size_t)(b * HH + h) * SS + s) * 64;

        const float qscale = 0.088388347648318447f;
        const float* ctab = g_cos + s * 64;
        const float* stab = g_sin + s * 64;

        float q0, q1, k0, k1;
        if (j < 32) {
            int d0 = 2 * j, d1 = 2 * j + 1;
            float c0 = ctab[d0], s0 = stab[d0], c1 = ctab[d1], s1 = stab[d1];
            q0 = qrow[d0] * c0 + qrow[2 * d0 + 1] * s0;
            q1 = qrow[d1] * c1 + qrow[2 * d1 + 1] * s1;
            k0 = krow[d0] * c0 + krow[2 * d0 + 1] * s0;
            k1 = krow[d1] * c1 + krow[2 * d1 + 1] * s1;
        } else {
            int d0 = 2 * j, d1 = 2 * j + 1;
            int e0 = d0 - 64, e1 = d1 - 64;
            float c0 = ctab[e0], s0 = stab[e0], c1 = ctab[e1], s1 = stab[e1];
            q0 = qrow[d0] * c0 - qrow[2 * e0] * s0;
            q1 = qrow[d1] * c1 - qrow[2 * e1] * s1;
            k0 = krow[d0] * c0 - krow[2 * e0] * s0;
            k1 = krow[d1] * c1 - krow[2 * e1] * s1;
        }
        g_qh[o + j] = pack_h2(q0 * qscale, q1 * qscale);
        g_kh[o + j] = pack_h2(k0, k1);
        return;
    }
    blk -= P2_NB_RS;
    {
        // vT: block = 32 d x 64 s, fp16 pairs in (d-pairs) -> fp16 pairs out (s-pairs)
        int sx = blk & 31;
        int dy = (blk >> 5) & 3;
        int bh = blk >> 7;
        int b = bh >> 4, h = bh & 15;
        int s0 = sx * 64;
        int d0 = dy * 32;
        int dp0 = dy * 16;

#pragma unroll
        for (int i = 0; i < 4; i++) {
            int flat = tid + i * 256;
            int s = flat >> 4, dp = flat & 15;
            uint32_t val = g_vh[(size_t)(b * SS + s0 + s) * 1024 + h * 64 + dp0 + dp];
            __half2 h2 = *(__half2*)&val;
            th[2 * dp][s]     = h2.x;
            th[2 * dp + 1][s] = h2.y;
        }
        __syncthreads();
#pragma unroll
        for (int i = 0; i < 4; i++) {
            int flat = tid + i * 256;
            int d = flat >> 5, sp = flat & 31;
            uint32_t o = *(const uint32_t*)&th[d][2 * sp];
            g_vT[(size_t)bh * (DHH * (SS / 2)) + (size_t)(d0 + d) * (SS / 2)
                 + (s0 >> 1) + sp] = o;
        }
    }
}

// ==================== fp16 mma GEMM: 4-stage cp.async; v-region writes fp16 ====================
#define GH_ASTR 20
#define GH_BSTR 20
#define GH_STG  (256*GH_ASTR + 128*GH_BSTR)   // 7680 u32
#define GH_SMEM_BYTES (4 * GH_STG * 4)        // 122880

__global__ void __launch_bounds__(256) gemm_h_kernel(
    const uint32_t* __restrict__ A, const uint32_t* __restrict__ Bt,
    const float* __restrict__ bias, float* __restrict__ C,
    uint32_t* __restrict__ Vh, int vsplit,
    int M, int N, int K)
{
    extern __shared__ uint32_t gsm[];
    uint32_t sbase = smem_u32(gsm);

    int tid  = threadIdx.x;
    int lane = tid & 31;
    int w    = tid >> 5;
    int wr   = w >> 1;
    int wc   = w & 1;
    int grp  = lane >> 2;
    int tig  = lane & 3;
    int m0 = blockIdx.y * 256;
    int n0 = blockIdx.x * 128;
    const int K2 = K >> 1;

    const int lrow = tid >> 2;
    const int lc4  = (tid & 3) * 4;
    const uint32_t* Abase = A + (size_t)(m0 + lrow) * K2 + lc4;
    const uint32_t* Bbase = Bt + (size_t)(n0 + lrow) * K2 + lc4;

    float acc[4][8][4];
#pragma unroll
    for (int mt = 0; mt < 4; mt++)
#pragma unroll
        for (int nt = 0; nt < 8; nt++)
#pragma unroll
            for (int i = 0; i < 4; i++) acc[mt][nt][i] = 0.f;

    const int nCh = K / 32;

#pragma unroll
    for (int st = 0; st < 3; st++) {
        uint32_t sA = sbase + st * GH_STG * 4;
        uint32_t sB = sA + 256 * GH_ASTR * 4;
#pragma unroll
        for (int i = 0; i < 4; i++)
            cp16(sA + (((lrow + i * 64) * GH_ASTR + lc4) << 2),
                 Abase + (size_t)i * 64 * K2 + st * 16);
#pragma unroll
        for (int i = 0; i < 2; i++)
            cp16(sB + (((lrow + i * 64) * GH_BSTR + lc4) << 2),
                 Bbase + (size_t)i * 64 * K2 + st * 16);
        CP_COMMIT();
    }

    for (int kc = 0; kc < nCh; kc++) {
        int stage = kc & 3;
        CP_WAIT2();
        __syncthreads();
        uint32_t* As = gsm + stage * GH_STG;
        uint32_t* Bs = As + 256 * GH_ASTR;

#pragma unroll
        for (int kk = 0; kk < 2; kk++) {
            int kb = kk * 8 + tig;
            uint32_t af[4][4], bf[8][2];
#pragma unroll
            for (int mt = 0; mt < 4; mt++) {
                int r = wr * 64 + mt * 16 + grp;
                af[mt][0] = As[r * GH_ASTR + kb];
                af[mt][1] = As[(r + 8) * GH_ASTR + kb];
                af[mt][2] = As[r * GH_ASTR + kb + 4];
                af[mt][3] = As[(r + 8) * GH_ASTR + kb + 4];
            }
#pragma unroll
            for (int nt = 0; nt < 8; nt++) {
                int cn = wc * 64 + nt * 8 + grp;
                bf[nt][0] = Bs[cn * GH_BSTR + kb];
                bf[nt][1] = Bs[cn * GH_BSTR + kb + 4];
            }
#pragma unroll
            for (int mt = 0; mt < 4; mt++)
#pragma unroll
                for (int nt = 0; nt < 8; nt++)
                    MMA_F16(acc[mt][nt][0], acc[mt][nt][1], acc[mt][nt][2], acc[mt][nt][3],
                            af[mt][0], af[mt][1], af[mt][2], af[mt][3],
                            bf[nt][0], bf[nt][1]);
        }

        int kn = kc + 3;
        if (kn < nCh) {
            int wst = kn & 3;
            uint32_t sA = sbase + wst * GH_STG * 4;
            uint32_t sB = sA + 256 * GH_ASTR * 4;
#pragma unroll
            for (int i = 0; i < 4; i++)
                cp16(sA + (((lrow + i * 64) * GH_ASTR + lc4) << 2),
                     Abase + (size_t)i * 64 * K2 + kn * 16);
#pragma unroll
            for (int i = 0; i < 2; i++)
                cp16(sB + (((lrow + i * 64) * GH_BSTR + lc4) << 2),
                     Bbase + (size_t)i * 64 * K2 + kn * 16);
        }
        CP_COMMIT();
    }

    if (n0 >= vsplit) {
        // v region: write fp16 pairs directly (bit-identical to fp32 store + later cvt)
#pragma unroll
        for (int mt = 0; mt < 4; mt++) {
            int r0 = m0 + wr * 64 + mt * 16 + grp;
#pragma unroll
            for (int nt = 0; nt < 8; nt++) {
                int cn = n0 + wc * 64 + nt * 8 + tig * 2;
                float b0 = bias[cn], b1 = bias[cn + 1];
                int vp = (cn - 4096) >> 1;
                Vh[(size_t)r0 * 1024 + vp] =
                    pack_h2(acc[mt][nt][0] + b0, acc[mt][nt][1] + b1);
                Vh[(size_t)(r0 + 8) * 1024 + vp] =
                    pack_h2(acc[mt][nt][2] + b0, acc[mt][nt][3] + b1);
            }
        }
    } else {
#pragma unroll
        for (int mt = 0; mt < 4; mt++) {
            int r0 = m0 + wr * 64 + mt * 16 + grp;
#pragma unroll
            for (int nt = 0; nt < 8; nt++) {
                int cn = n0 + wc * 64 + nt * 8 + tig * 2;
                float b0 = bias[cn], b1 = bias[cn + 1];
                float2 v0 = make_float2(acc[mt][nt][0] + b0, acc[mt][nt][1] + b1);
                float2 v1 = make_float2(acc[mt][nt][2] + b0, acc[mt][nt][3] + b1);
                *(float2*)(C + (size_t)r0 * N + cn) = v0;
                *(float2*)(C + (size_t)(r0 + 8) * N + cn) = v1;
            }
        }
    }
}

// ==================== flash attention fp16, BN=128 (R14/R15, known-good) ====================
#define AH_STR 68
#define AH_RED  (4 * 128 * AH_STR)
#define AH_SMEM_U32 (AH_RED + 512)
#define AH_SMEM_BYTES (AH_SMEM_U32 * 4)   // ~141KB

__global__ void __launch_bounds__(256, 1) attn_mma_kernel() {
    extern __shared__ uint32_t sm4[];
    uint32_t* Qs  = sm4;
    uint32_t* Ks  = Qs + 128 * AH_STR;
    uint32_t* VsT = Ks + 128 * AH_STR;
    uint32_t* Ps  = VsT + 128 * AH_STR;
    float* redmax = (float*)(sm4 + AH_RED);
    float* redsum = redmax + 256;

    int tid  = threadIdx.x;
    int lane = tid & 31;
    int w    = tid >> 5;
    int g    = w & 3;
    int hf   = w >> 2;
    int grp  = lane >> 2;
    int tig  = lane & 3;

    int bh = blockIdx.y;
    int b = bh >> 4, h = bh & 15;
    int q0 = blockIdx.x * 128;

    const uint32_t* Qg = g_qh + (size_t)bh * SS * 64;
    const uint32_t* Kg = g_kh + (size_t)bh * SS * 64;
    const uint32_t* Vg = g_vT + (size_t)bh * DHH * (SS / 2);

#pragma unroll
    for (int i = 0; i < 8; i++) {
        int flat = tid + i * 256;
        int r = flat >> 4, c = (flat & 15) * 4;
        uint4 q4 = *(const uint4*)(Qg + (size_t)(q0 + r) * 64 + c);
        *(uint4*)&Qs[r * AH_STR + c] = q4;
    }

    int lr[8], lc[8];
#pragma unroll
    for (int i = 0; i < 8; i++) {
        int flat = tid + i * 256;
        lr[i] = flat >> 4;
        lc[i] = (flat & 15) * 4;
    }
    uint4 kpf[8], vpf[8];
#pragma unroll
    for (int i = 0; i < 8; i++) {
        kpf[i] = *(const uint4*)(Kg + (size_t)lr[i] * 64 + lc[i]);
        vpf[i] = *(const uint4*)(Vg + (size_t)lr[i] * (SS / 2) + lc[i]);
    }

    int r0 = g * 32 + grp;
    float o[2][8][4];
#pragma unroll
    for (int mt = 0; mt < 2; mt++)
#pragma unroll
        for (int nt = 0; nt < 8; nt++)
#pragma unroll
            for (int i = 0; i < 4; i++) o[mt][nt][i] = 0.f;
    float m[4] = {-1e30f, -1e30f, -1e30f, -1e30f};
    float l[4] = {0.f, 0.f, 0.f, 0.f};

    const int NKT = SS / 128;
    for (int kt = 0; kt < NKT; kt++) {
        __syncthreads();
#pragma unroll
        for (int i = 0; i < 8; i++) {
            *(uint4*)&Ks[lr[i] * AH_STR + lc[i]] = kpf[i];
            *(uint4*)&VsT[lr[i] * AH_STR + lc[i]] = vpf[i];
        }
        __syncthreads();

        float s[2][8][4];
#pragma unroll
        for (int mt = 0; mt < 2; mt++)
#pragma unroll
            for (int nt = 0; nt < 8; nt++)
#pragma unroll
                for (int i = 0; i < 4; i++) s[mt][nt][i] = 0.f;

#pragma unroll
        for (int ks = 0; ks < 8; ks++) {
            int kb = ks * 8 + tig;
            uint32_t af[2][4];
#pragma unroll
            for (int mt = 0; mt < 2; mt++) {
                int rr = r0 + mt * 16;
                af[mt][0] = Qs[rr * AH_STR + kb];
                af[mt][1] = Qs[(rr + 8) * AH_STR + kb];
                af[mt][2] = Qs[rr * AH_STR + kb + 4];
                af[mt][3] = Qs[(rr + 8) * AH_STR + kb + 4];
            }
#pragma unroll
            for (int nt = 0; nt < 8; nt++) {
                int kr = hf * 64 + nt * 8 + grp;
                uint32_t b0 = Ks[kr * AH_STR + kb];
                uint32_t b1 = Ks[kr * AH_STR + kb + 4];
#pragma unroll
                for (int mt = 0; mt < 2; mt++)
                    MMA_F16(s[mt][nt][0], s[mt][nt][1], s[mt][nt][2], s[mt][nt][3],
                            af[mt][0], af[mt][1], af[mt][2], af[mt][3], b0, b1);
            }
        }

        float mx[4] = {-1e30f, -1e30f, -1e30f, -1e30f};
#pragma unroll
        for (int mt = 0; mt < 2; mt++)
#pragma unroll
            for (int nt = 0; nt < 8; nt++) {
                mx[2*mt]   = fmaxf(mx[2*mt],   fmaxf(s[mt][nt][0], s[mt][nt][1]));
                mx[2*mt+1] = fmaxf(mx[2*mt+1], fmaxf(s[mt][nt][2], s[mt][nt][3]));
            }
#pragma unroll
        for (int off = 1; off <= 2; off <<= 1)
#pragma unroll
            for (int sl = 0; sl < 4; sl++)
                mx[sl] = fmaxf(mx[sl], __shfl_xor_sync(0xffffffffu, mx[sl], off));
        if (tig == 0) {
#pragma unroll
            for (int sl = 0; sl < 4; sl++)
                redmax[hf * 128 + r0 + sl * 8] = mx[sl];
        }
        __syncthreads();
        float nm[4], sc[4];
#pragma unroll
        for (int sl = 0; sl < 4; sl++) {
            int rr = r0 + sl * 8;
            nm[sl] = fmaxf(m[sl], fmaxf(redmax[rr], redmax[128 + rr]));
            sc[sl] = __expf(m[sl] - nm[sl]);
        }

        float ps[4] = {0.f, 0.f, 0.f, 0.f};
#pragma unroll
        for (int mt = 0; mt < 2; mt++)
#pragma unroll
            for (int nt = 0; nt < 8; nt++) {
                float p0 = __expf(s[mt][nt][0] - nm[2*mt]);
                float p1 = __expf(s[mt][nt][1] - nm[2*mt]);
                float p2 = __expf(s[mt][nt][2] - nm[2*mt+1]);
                float p3 = __expf(s[mt][nt][3] - nm[2*mt+1]);
                ps[2*mt]   += p0 + p1;
                ps[2*mt+1] += p2 + p3;
                int pc = hf * 32 + nt * 4 + tig;
                int rr = r0 + mt * 16;
                Ps[rr * AH_STR + pc]       = pack_h2(p0, p1);
                Ps[(rr + 8) * AH_STR + pc] = pack_h2(p2, p3);
            }
#pragma unroll
        for (int off = 1; off <= 2; off <<= 1)
#pragma unroll
            for (int sl = 0; sl < 4; sl++)
                ps[sl] += __shfl_xor_sync(0xffffffffu, ps[sl], off);
        if (tig == 0) {
#pragma unroll
            for (int sl = 0; sl < 4; sl++)
                redsum[hf * 128 + r0 + sl * 8] = ps[sl];
        }
        __syncthreads();

        if (kt + 1 < NKT) {
            const uint32_t* Kn = Kg + (size_t)((kt + 1) * 128) * 64;
            const uint32_t* Vn = Vg + (kt + 1) * 64;
#pragma unroll
            for (int i = 0; i < 8; i++) {
                kpf[i] = *(const uint4*)(Kn + (size_t)lr[i] * 64 + lc[i]);
                vpf[i] = *(const uint4*)(Vn + (size_t)lr[i] * (SS / 2) + lc[i]);
            }
        }

#pragma unroll
        for (int sl = 0; sl < 4; sl++) {
            int rr = r0 + sl * 8;
            l[sl] = l[sl] * sc[sl] + redsum[rr] + redsum[128 + rr];
            m[sl] = nm[sl];
        }
#pragma unroll
        for (int mt = 0; mt < 2; mt++)
#pragma unroll
            for (int nt = 0; nt < 8; nt++) {
                o[mt][nt][0] *= sc[2*mt]; o[mt][nt][1] *= sc[2*mt];
                o[mt][nt][2] *= sc[2*mt+1]; o[mt][nt][3] *= sc[2*mt+1];
            }

#pragma unroll
        for (int ksv = 0; ksv < 8; ksv++) {
            int kb = ksv * 8 + tig;
            uint32_t af[2][4];
#pragma unroll
            for (int mt = 0; mt < 2; mt++) {
                int rr = r0 + mt * 16;
                af[mt][0] = Ps[rr * AH_STR + kb];
                af[mt][1] = Ps[(rr + 8) * AH_STR + kb];
                af[mt][2] = Ps[rr * AH_STR + kb + 4];
                af[mt][3] = Ps[(rr + 8) * AH_STR + kb + 4];
            }
#pragma unroll
            for (int nt = 0; nt < 8; nt++) {
                int vc = hf * 64 + nt * 8 + grp;
                uint32_t b0 = VsT[vc * AH_STR + kb];
                uint32_t b1 = VsT[vc * AH_STR + kb + 4];
#pragma unroll
                for (int mt = 0; mt < 2; mt++)
                    MMA_F16(o[mt][nt][0], o[mt][nt][1], o[mt][nt][2], o[mt][nt][3],
                            af[mt][0], af[mt][1], af[mt][2], af[mt][3], b0, b1);
            }
        }
    }

    float inv[4];
#pragma unroll
    for (int sl = 0; sl < 4; sl++) inv[sl] = 1.f / l[sl];
#pragma unroll
    for (int mt = 0; mt < 2; mt++) {
        int rrg0 = q0 + r0 + mt * 16;
        uint32_t* dst0 = g_ctxh + (size_t)(b * SS + rrg0) * (DD / 2) + h * 64;
        uint32_t* dst1 = g_ctxh + (size_t)(b * SS + rrg0 + 8) * (DD / 2) + h * 64;
#pragma unroll
        for (int nt = 0; nt < 8; nt++) {
            int pc = hf * 32 + nt * 4 + tig;
            dst0[pc] = pack_h2(o[mt][nt][0] * inv[2*mt],   o[mt][nt][1] * inv[2*mt]);
            dst1[pc] = pack_h2(o[mt][nt][2] * inv[2*mt+1], o[mt][nt][3] * inv[2*mt+1]);
        }
    }
}

// ---------------- launch ----------------
extern "C" void kernel_launch(void* const* d_in, const int* in_sizes, int n_in,
                              void* d_out, int out_size) {
    const float* x    = (const float*)d_in[0];
    const float* Wqkv = (const float*)d_in[1];
    const float* bqkv = (const float*)d_in[2];
    const float* Wo   = (const float*)d_in[3];
    const float* bo   = (const float*)d_in[4];
    float* out = (float*)d_out;

    void *qkvPtr, *vhPtr, *xhPtr, *wqkvhPtr, *wohPtr, *ctxhPtr;
    cudaGetSymbolAddress(&qkvPtr, g_qkv);
    cudaGetSymbolAddress(&vhPtr, g_vh);
    cudaGetSymbolAddress(&xhPtr, g_xh);
    cudaGetSymbolAddress(&wqkvhPtr, g_wqkvh);
    cudaGetSymbolAddress(&wohPtr, g_woh);
    cudaGetSymbolAddress(&ctxhPtr, g_ctxh);

    cudaFuncSetAttribute(attn_mma_kernel,
                         cudaFuncAttributeMaxDynamicSharedMemorySize,
                         AH_SMEM_BYTES);
    cudaFuncSetAttribute(gemm_h_kernel,
                         cudaFuncAttributeMaxDynamicSharedMemorySize,
                         GH_SMEM_BYTES);

    // 1) fused prepass: x->fp16 | Wqkv^T fp16 | Wo^T fp16 | rope tables
    prep1_kernel<<<P1_GRID, 256>>>(x, Wqkv, Wo);

    // 2) QKV GEMM -> q,k fp32 in g_qkv; v fp16 pairs in g_vh
    gemm_h_kernel<<<dim3(ND3 / 128, (BB * SS) / 256), 256, GH_SMEM_BYTES>>>(
        (const uint32_t*)xhPtr, (const uint32_t*)wqkvhPtr, bqkv, (float*)qkvPtr,
        (uint32_t*)vhPtr, 4096, BB * SS, ND3, DD);

    // 3) fused prepass: RoPE+split fp16 | V transpose (fp16 in/out)
    prep2_kernel<<<P2_GRID, 256>>>();

    // 4) flash attention (fp16, BN=128) -> g_ctxh
    attn_mma_kernel<<<dim3(SS / 128, BB * HH), 256, AH_SMEM_BYTES>>>();

    // 5) output projection -> out fp32 (vsplit disabled)
    gemm_h_kernel<<<dim3(DD / 128, (BB * SS) / 256), 256, GH_SMEM_BYTES>>>(
        (const uint32_t*)ctxhPtr, (const uint32_t*)wohPtr, bo, out,
        (uint32_t*)vhPtr, 1 << 30, BB * SS, DD, DD);
}